// round 1
// baseline (speedup 1.0000x reference)
#include <cuda_runtime.h>
#include <math.h>
#include <stdint.h>

// ---------------- problem constants ----------------
#define Dm    1024
#define Tlen  2048
#define Bb    4
#define Hh    16
#define DK    64
#define Ll    2
#define Vv    8192
#define NROW  (Bb*Tlen)          // 8192 token rows

// ---------------- scratch (device globals; no allocation allowed) ----------
__device__ float g_x  [NROW*Dm];        // 32 MB  residual stream
__device__ float g_h  [NROW*Dm];        // 32 MB  LN output / final LN
__device__ float g_h2 [NROW*Dm];        // 32 MB  conv output
__device__ float g_qkv[NROW*3*Dm];      // 96 MB
__device__ float g_y  [NROW*Dm];        // 32 MB  scan output
__device__ float g_ret [Ll*Hh*DK*DK];   // retention
__device__ float g_gate[Ll*Hh*DK*DK];   // gate

// ---------------- embedding gather ----------------
__global__ void embed_kernel(const int* __restrict__ ids,
                             const float* __restrict__ W,
                             float* __restrict__ x) {
    int row = blockIdx.x;
    int id  = ids[row];
    const float4* src = (const float4*)(W + (size_t)id * Dm);
    float4* dst = (float4*)(x + (size_t)row * Dm);
    for (int i = threadIdx.x; i < Dm/4; i += blockDim.x) dst[i] = src[i];
}

// ---------------- block reduce helper (blockDim == 256) ----------------
__device__ __forceinline__ float blockReduceSum(float v, float* sh) {
    #pragma unroll
    for (int o = 16; o; o >>= 1) v += __shfl_xor_sync(0xffffffffu, v, o);
    if ((threadIdx.x & 31) == 0) sh[threadIdx.x >> 5] = v;
    __syncthreads();
    float tot = 0.f;
    #pragma unroll
    for (int i = 0; i < 8; i++) tot += sh[i];
    __syncthreads();
    return tot;
}

// ---------------- layernorm over Dm (one block per row, 256 threads) ------
__global__ void __launch_bounds__(256) ln_kernel(const float* __restrict__ x,
                                                 const float* __restrict__ g,
                                                 const float* __restrict__ b,
                                                 float* __restrict__ out) {
    __shared__ float sh[8];
    int row = blockIdx.x;
    const float* xr = x + (size_t)row * Dm;
    int i0 = threadIdx.x * 4;
    float4 xv = *(const float4*)(xr + i0);
    float s = xv.x + xv.y + xv.z + xv.w;
    float mean = blockReduceSum(s, sh) * (1.f / Dm);
    float d0 = xv.x - mean, d1 = xv.y - mean, d2 = xv.z - mean, d3 = xv.w - mean;
    float sq = d0*d0 + d1*d1 + d2*d2 + d3*d3;
    float var = blockReduceSum(sq, sh) * (1.f / Dm);
    float rstd = rsqrtf(var + 1e-5f);
    float4 gv = *(const float4*)(g + i0);
    float4 bv = *(const float4*)(b + i0);
    float4 ov;
    ov.x = d0 * rstd * gv.x + bv.x;
    ov.y = d1 * rstd * gv.y + bv.y;
    ov.z = d2 * rstd * gv.z + bv.z;
    ov.w = d3 * rstd * gv.w + bv.w;
    *(float4*)(out + (size_t)row * Dm + i0) = ov;
}

// ---------------- causal depthwise conv (width 3, left pad 2) + add -------
// out[t,d] = h[t,d] + w0[d]*h[t-2,d] + w1[d]*h[t-1,d] + w2[d]*h[t,d] + cb[d]
__global__ void __launch_bounds__(256) conv_kernel(const float* __restrict__ h,
                                                   const float* __restrict__ cw,
                                                   const float* __restrict__ cb,
                                                   float* __restrict__ out) {
    int row = blockIdx.x;
    int t = row % Tlen;
    const float* h0 = h + (size_t)row * Dm;
    int i = threadIdx.x * 4;
    float4 cur = *(const float4*)(h0 + i);
    float4 w0 = *(const float4*)(cw + 0*Dm + i);
    float4 w1 = *(const float4*)(cw + 1*Dm + i);
    float4 w2 = *(const float4*)(cw + 2*Dm + i);
    float4 bb = *(const float4*)(cb + i);
    float4 z = make_float4(0.f, 0.f, 0.f, 0.f);
    float4 p1 = (t >= 1) ? *(const float4*)(h0 - Dm + i) : z;
    float4 p2 = (t >= 2) ? *(const float4*)(h0 - 2*Dm + i) : z;
    float4 o;
    o.x = cur.x + w0.x*p2.x + w1.x*p1.x + w2.x*cur.x + bb.x;
    o.y = cur.y + w0.y*p2.y + w1.y*p1.y + w2.y*cur.y + bb.y;
    o.z = cur.z + w0.z*p2.z + w1.z*p1.z + w2.z*cur.z + bb.z;
    o.w = cur.w + w0.w*p2.w + w1.w*p1.w + w2.w*cur.w + bb.w;
    *(float4*)(out + (size_t)row * Dm + i) = o;
}

// ---------------- per-head k layernorm (in place inside qkv) --------------
// block = 512 threads = 16 warps, warp w = head w, one block per token row
__global__ void __launch_bounds__(512) kln_kernel(float* __restrict__ qkv,
                                                  const float* __restrict__ g,
                                                  const float* __restrict__ b) {
    int row = blockIdx.x;
    int wid = threadIdx.x >> 5, lane = threadIdx.x & 31;
    float* k = qkv + (size_t)row * (3*Dm) + Dm + wid * DK;
    float x0 = k[lane], x1 = k[lane + 32];
    float s = x0 + x1;
    #pragma unroll
    for (int o = 16; o; o >>= 1) s += __shfl_xor_sync(0xffffffffu, s, o);
    float mean = s * (1.f / DK);
    float d0 = x0 - mean, d1 = x1 - mean;
    float q = d0*d0 + d1*d1;
    #pragma unroll
    for (int o = 16; o; o >>= 1) q += __shfl_xor_sync(0xffffffffu, q, o);
    float rstd = rsqrtf(q * (1.f / DK) + 1e-5f);
    k[lane]      = d0 * rstd * g[lane]      + b[lane];
    k[lane + 32] = d1 * rstd * g[lane + 32] + b[lane + 32];
}

// ---------------- static physics: retention & gate (time invariant) -------
__global__ void physics_kernel(const float* __restrict__ W_LTM,
                               const float* __restrict__ V_T0,
                               const float* __restrict__ V_gs,
                               const float* __restrict__ beta_tau,
                               const float* __restrict__ beta_gm,
                               const float* __restrict__ C_ch,
                               const float* __restrict__ gma,
                               const float* __restrict__ alpha,
                               const float* __restrict__ icth,
                               float* __restrict__ ret,
                               float* __restrict__ gate) {
    int idx = blockIdx.x * blockDim.x + threadIdx.x;
    if (idx >= Ll*Hh*DK*DK) return;
    int lh = idx / (DK*DK);
    int l  = lh / Hh;
    float veff = (V_gs[lh] - V_T0[lh]) + W_LTM[idx];
    float sp   = (veff > 20.f) ? veff : log1pf(expf(veff));
    float g_ch = beta_tau[lh] * sp;
    float r    = expf(-g_ch / C_ch[lh]);          // 1 - lam
    float G    = beta_gm[lh] * sp * (1.f / (1.f + expf(-veff)));
    float sgn  = tanhf(alpha[l] * (g_ch - icth[l]));
    ret[idx]  = r;
    gate[idx] = gma[lh] * sgn * G;
}

// ---------------- sequential recurrence ----------------
// grid = B*H blocks, 256 threads. thread i: row v = i>>2, k-slice = (i&3)*16.
// F, retention, gate, W_LTM rows live in registers. q/k/v double-buffered in
// shared (one __syncthreads per step). y[v] reduced over 4 lanes via shfl.
__global__ void __launch_bounds__(256, 1) scan_kernel(const float* __restrict__ qkv,
                                                      const float* __restrict__ ret,
                                                      const float* __restrict__ gate,
                                                      const float* __restrict__ W,
                                                      float* __restrict__ y) {
    int bh = blockIdx.x;
    int b = bh / Hh, h = bh % Hh;
    int tid = threadIdx.x;
    int v = tid >> 2, part = tid & 3, koff = part * 16;

    float r[16], g[16], w[16], f[16];
    {
        int base = (h*DK + v)*DK + koff;
        #pragma unroll
        for (int j = 0; j < 16; j++) {
            r[j] = ret[base + j];
            g[j] = gate[base + j];
            w[j] = W[base + j];
            f[j] = 0.f;
        }
    }

    __shared__ float sbuf[2][192];   // [q(64) | k(64) | v(64)]
    size_t rowbase = (size_t)b * Tlen * (3*Dm) + h * DK;
    float* yout = y + (size_t)b * Tlen * Dm + h * DK + v;

    for (int t = 0; t < Tlen; t++) {
        int p = t & 1;
        if (tid < 192) {
            int which = tid >> 6, lane = tid & 63;
            sbuf[p][tid] = qkv[rowbase + (size_t)t * (3*Dm) + which * Dm + lane];
        }
        __syncthreads();
        float vt = sbuf[p][128 + v];
        const float4* k4 = (const float4*)&sbuf[p][64 + koff];
        const float4* q4 = (const float4*)&sbuf[p][koff];
        float yacc = 0.f;
        #pragma unroll
        for (int j4 = 0; j4 < 4; j4++) {
            float4 kk = k4[j4];
            float4 qq = q4[j4];
            int j = j4 * 4;
            f[j+0] = r[j+0]*f[j+0] + (g[j+0]*vt)*kk.x;
            f[j+1] = r[j+1]*f[j+1] + (g[j+1]*vt)*kk.y;
            f[j+2] = r[j+2]*f[j+2] + (g[j+2]*vt)*kk.z;
            f[j+3] = r[j+3]*f[j+3] + (g[j+3]*vt)*kk.w;
            yacc = fmaf(w[j+0] + f[j+0], qq.x, yacc);
            yacc = fmaf(w[j+1] + f[j+1], qq.y, yacc);
            yacc = fmaf(w[j+2] + f[j+2], qq.z, yacc);
            yacc = fmaf(w[j+3] + f[j+3], qq.w, yacc);
        }
        yacc += __shfl_xor_sync(0xffffffffu, yacc, 1);
        yacc += __shfl_xor_sync(0xffffffffu, yacc, 2);
        if (part == 0) yout[(size_t)t * Dm] = yacc;
    }
}

// ---------------- SGEMM: C[m,n] = sum_k A[m,k]*B[n,k] (+ Res[m,n]) --------
// A: (M,K) row-major; B: (N,K) row-major (weights). 128x128 tile, BK=16,
// 256 threads, 8x8 per thread.
#define BM 128
#define BN 128
#define BK 16
__global__ void __launch_bounds__(256) sgemm_nt(int M, int N, int K,
                                                const float* __restrict__ A,
                                                const float* __restrict__ B,
                                                const float* __restrict__ Res,
                                                float* __restrict__ C) {
    __shared__ float As[BK][BM];
    __shared__ float Bs[BK][BN];
    int tid = threadIdx.x;
    int m0 = blockIdx.y * BM, n0 = blockIdx.x * BN;
    int tm = tid >> 4, tn = tid & 15;

    float acc[8][8] = {};

    for (int k0 = 0; k0 < K; k0 += BK) {
        #pragma unroll
        for (int s = 0; s < 2; s++) {
            int vecid = tid + s * 256;          // 512 float4 per 128x16 tile
            int row = vecid >> 2;
            int c4  = (vecid & 3) << 2;
            float4 a = *(const float4*)(A + (size_t)(m0 + row) * K + k0 + c4);
            As[c4+0][row] = a.x; As[c4+1][row] = a.y;
            As[c4+2][row] = a.z; As[c4+3][row] = a.w;
            float4 bq = *(const float4*)(B + (size_t)(n0 + row) * K + k0 + c4);
            Bs[c4+0][row] = bq.x; Bs[c4+1][row] = bq.y;
            Bs[c4+2][row] = bq.z; Bs[c4+3][row] = bq.w;
        }
        __syncthreads();
        #pragma unroll
        for (int kk = 0; kk < BK; kk++) {
            float am[8], bn[8];
            *(float4*)&am[0] = *(const float4*)&As[kk][tm*8];
            *(float4*)&am[4] = *(const float4*)&As[kk][tm*8 + 4];
            *(float4*)&bn[0] = *(const float4*)&Bs[kk][tn*8];
            *(float4*)&bn[4] = *(const float4*)&Bs[kk][tn*8 + 4];
            #pragma unroll
            for (int i = 0; i < 8; i++)
                #pragma unroll
                for (int j = 0; j < 8; j++)
                    acc[i][j] = fmaf(am[i], bn[j], acc[i][j]);
        }
        __syncthreads();
    }

    #pragma unroll
    for (int i = 0; i < 8; i++) {
        size_t off = (size_t)(m0 + tm*8 + i) * N + n0 + tn*8;
        float4 o0 = make_float4(acc[i][0], acc[i][1], acc[i][2], acc[i][3]);
        float4 o1 = make_float4(acc[i][4], acc[i][5], acc[i][6], acc[i][7]);
        if (Res) {
            float4 r0 = *(const float4*)(Res + off);
            float4 r1 = *(const float4*)(Res + off + 4);
            o0.x += r0.x; o0.y += r0.y; o0.z += r0.z; o0.w += r0.w;
            o1.x += r1.x; o1.y += r1.y; o1.z += r1.z; o1.w += r1.w;
        }
        *(float4*)(C + off)     = o0;
        *(float4*)(C + off + 4) = o1;
    }
}

// ---------------- launch ----------------
extern "C" void kernel_launch(void* const* d_in, const int* in_sizes, int n_in,
                              void* d_out, int out_size) {
    const int*   ids      = (const int*)  d_in[0];
    // d_in[1] = state_quant_bits = 16 -> no quantization path
    const float* embedW   = (const float*)d_in[2];
    const float* conv_w   = (const float*)d_in[3];
    const float* conv_b   = (const float*)d_in[4];
    const float* Wqkv     = (const float*)d_in[5];
    const float* Wo       = (const float*)d_in[6];
    const float* W_LTM    = (const float*)d_in[7];
    const float* V_T0     = (const float*)d_in[8];
    const float* V_gs     = (const float*)d_in[9];
    const float* beta_tau = (const float*)d_in[10];
    const float* beta_gm  = (const float*)d_in[11];
    const float* C_ch     = (const float*)d_in[12];
    const float* gma      = (const float*)d_in[13];
    const float* alpha    = (const float*)d_in[14];
    const float* icth     = (const float*)d_in[15];
    const float* ln1_g    = (const float*)d_in[16];
    const float* ln1_b    = (const float*)d_in[17];
    const float* lnk_g    = (const float*)d_in[18];
    const float* lnk_b    = (const float*)d_in[19];
    const float* lnf_g    = (const float*)d_in[20];
    const float* lnf_b    = (const float*)d_in[21];
    const float* headW    = (const float*)d_in[22];
    float* out = (float*)d_out;

    float *x, *h, *h2, *qkv, *y, *ret, *gate;
    cudaGetSymbolAddress((void**)&x,    g_x);
    cudaGetSymbolAddress((void**)&h,    g_h);
    cudaGetSymbolAddress((void**)&h2,   g_h2);
    cudaGetSymbolAddress((void**)&qkv,  g_qkv);
    cudaGetSymbolAddress((void**)&y,    g_y);
    cudaGetSymbolAddress((void**)&ret,  g_ret);
    cudaGetSymbolAddress((void**)&gate, g_gate);

    embed_kernel<<<NROW, 256>>>(ids, embedW, x);
    {
        int n = Ll*Hh*DK*DK;
        physics_kernel<<<(n + 255)/256, 256>>>(W_LTM, V_T0, V_gs, beta_tau, beta_gm,
                                               C_ch, gma, alpha, icth, ret, gate);
    }

    for (int l = 0; l < Ll; l++) {
        ln_kernel<<<NROW, 256>>>(x, ln1_g + l*Dm, ln1_b + l*Dm, h);
        conv_kernel<<<NROW, 256>>>(h, conv_w + l*3*Dm, conv_b + l*Dm, h2);

        dim3 gq((3*Dm)/BN, NROW/BM);
        sgemm_nt<<<gq, 256>>>(NROW, 3*Dm, Dm, h2, Wqkv + (size_t)l*3*Dm*Dm, nullptr, qkv);

        kln_kernel<<<NROW, 512>>>(qkv, lnk_g + l*DK, lnk_b + l*DK);

        scan_kernel<<<Bb*Hh, 256>>>(qkv,
                                    ret  + (size_t)l*Hh*DK*DK,
                                    gate + (size_t)l*Hh*DK*DK,
                                    W_LTM + (size_t)l*Hh*DK*DK,
                                    y);

        dim3 go(Dm/BN, NROW/BM);
        sgemm_nt<<<go, 256>>>(NROW, Dm, Dm, y, Wo + (size_t)l*Dm*Dm, x, x);
    }

    ln_kernel<<<NROW, 256>>>(x, lnf_g, lnf_b, h);
    dim3 gh(Vv/BN, NROW/BM);
    sgemm_nt<<<gh, 256>>>(NROW, Vv, Dm, h, headW, nullptr, out);
}

// round 2
// speedup vs baseline: 2.1215x; 2.1215x over previous
#include <cuda_runtime.h>
#include <math.h>
#include <stdint.h>

// ---------------- problem constants ----------------
#define Dm    1024
#define Tlen  2048
#define Bb    4
#define Hh    16
#define DK    64
#define Ll    2
#define Vv    8192
#define NROW  (Bb*Tlen)          // 8192 token rows

// ---------------- scratch (device globals; no allocation allowed) ----------
__device__ float g_x  [NROW*Dm];        // 32 MB  residual stream
__device__ float g_h  [NROW*Dm];        // 32 MB  LN output / final LN
__device__ float g_h2 [NROW*Dm];        // 32 MB  conv output
__device__ float g_qkv[NROW*3*Dm];      // 96 MB
__device__ float g_y  [NROW*Dm];        // 32 MB  scan output
__device__ float g_ret [Ll*Hh*DK*DK];   // retention
__device__ float g_gate[Ll*Hh*DK*DK];   // gate

// ---------------- embedding gather ----------------
__global__ void embed_kernel(const int* __restrict__ ids,
                             const float* __restrict__ W,
                             float* __restrict__ x) {
    int row = blockIdx.x;
    int id  = ids[row];
    const float4* src = (const float4*)(W + (size_t)id * Dm);
    float4* dst = (float4*)(x + (size_t)row * Dm);
    for (int i = threadIdx.x; i < Dm/4; i += blockDim.x) dst[i] = src[i];
}

// ---------------- block reduce helper (blockDim == 256) ----------------
__device__ __forceinline__ float blockReduceSum(float v, float* sh) {
    #pragma unroll
    for (int o = 16; o; o >>= 1) v += __shfl_xor_sync(0xffffffffu, v, o);
    if ((threadIdx.x & 31) == 0) sh[threadIdx.x >> 5] = v;
    __syncthreads();
    float tot = 0.f;
    #pragma unroll
    for (int i = 0; i < 8; i++) tot += sh[i];
    __syncthreads();
    return tot;
}

// ---------------- layernorm over Dm (one block per row, 256 threads) ------
__global__ void __launch_bounds__(256) ln_kernel(const float* __restrict__ x,
                                                 const float* __restrict__ g,
                                                 const float* __restrict__ b,
                                                 float* __restrict__ out) {
    __shared__ float sh[8];
    int row = blockIdx.x;
    const float* xr = x + (size_t)row * Dm;
    int i0 = threadIdx.x * 4;
    float4 xv = *(const float4*)(xr + i0);
    float s = xv.x + xv.y + xv.z + xv.w;
    float mean = blockReduceSum(s, sh) * (1.f / Dm);
    float d0 = xv.x - mean, d1 = xv.y - mean, d2 = xv.z - mean, d3 = xv.w - mean;
    float sq = d0*d0 + d1*d1 + d2*d2 + d3*d3;
    float var = blockReduceSum(sq, sh) * (1.f / Dm);
    float rstd = rsqrtf(var + 1e-5f);
    float4 gv = *(const float4*)(g + i0);
    float4 bv = *(const float4*)(b + i0);
    float4 ov;
    ov.x = d0 * rstd * gv.x + bv.x;
    ov.y = d1 * rstd * gv.y + bv.y;
    ov.z = d2 * rstd * gv.z + bv.z;
    ov.w = d3 * rstd * gv.w + bv.w;
    *(float4*)(out + (size_t)row * Dm + i0) = ov;
}

// ---------------- causal depthwise conv (width 3, left pad 2) + add -------
__global__ void __launch_bounds__(256) conv_kernel(const float* __restrict__ h,
                                                   const float* __restrict__ cw,
                                                   const float* __restrict__ cb,
                                                   float* __restrict__ out) {
    int row = blockIdx.x;
    int t = row % Tlen;
    const float* h0 = h + (size_t)row * Dm;
    int i = threadIdx.x * 4;
    float4 cur = *(const float4*)(h0 + i);
    float4 w0 = *(const float4*)(cw + 0*Dm + i);
    float4 w1 = *(const float4*)(cw + 1*Dm + i);
    float4 w2 = *(const float4*)(cw + 2*Dm + i);
    float4 bb = *(const float4*)(cb + i);
    float4 z = make_float4(0.f, 0.f, 0.f, 0.f);
    float4 p1 = (t >= 1) ? *(const float4*)(h0 - Dm + i) : z;
    float4 p2 = (t >= 2) ? *(const float4*)(h0 - 2*Dm + i) : z;
    float4 o;
    o.x = cur.x + w0.x*p2.x + w1.x*p1.x + w2.x*cur.x + bb.x;
    o.y = cur.y + w0.y*p2.y + w1.y*p1.y + w2.y*cur.y + bb.y;
    o.z = cur.z + w0.z*p2.z + w1.z*p1.z + w2.z*cur.z + bb.z;
    o.w = cur.w + w0.w*p2.w + w1.w*p1.w + w2.w*cur.w + bb.w;
    *(float4*)(out + (size_t)row * Dm + i) = o;
}

// ---------------- per-head k layernorm (in place inside qkv) --------------
__global__ void __launch_bounds__(512) kln_kernel(float* __restrict__ qkv,
                                                  const float* __restrict__ g,
                                                  const float* __restrict__ b) {
    int row = blockIdx.x;
    int wid = threadIdx.x >> 5, lane = threadIdx.x & 31;
    float* k = qkv + (size_t)row * (3*Dm) + Dm + wid * DK;
    float x0 = k[lane], x1 = k[lane + 32];
    float s = x0 + x1;
    #pragma unroll
    for (int o = 16; o; o >>= 1) s += __shfl_xor_sync(0xffffffffu, s, o);
    float mean = s * (1.f / DK);
    float d0 = x0 - mean, d1 = x1 - mean;
    float q = d0*d0 + d1*d1;
    #pragma unroll
    for (int o = 16; o; o >>= 1) q += __shfl_xor_sync(0xffffffffu, q, o);
    float rstd = rsqrtf(q * (1.f / DK) + 1e-5f);
    k[lane]      = d0 * rstd * g[lane]      + b[lane];
    k[lane + 32] = d1 * rstd * g[lane + 32] + b[lane + 32];
}

// ---------------- static physics: retention & gate (time invariant) -------
__global__ void physics_kernel(const float* __restrict__ W_LTM,
                               const float* __restrict__ V_T0,
                               const float* __restrict__ V_gs,
                               const float* __restrict__ beta_tau,
                               const float* __restrict__ beta_gm,
                               const float* __restrict__ C_ch,
                               const float* __restrict__ gma,
                               const float* __restrict__ alpha,
                               const float* __restrict__ icth,
                               float* __restrict__ ret,
                               float* __restrict__ gate) {
    int idx = blockIdx.x * blockDim.x + threadIdx.x;
    if (idx >= Ll*Hh*DK*DK) return;
    int lh = idx / (DK*DK);
    int l  = lh / Hh;
    float veff = (V_gs[lh] - V_T0[lh]) + W_LTM[idx];
    float sp   = (veff > 20.f) ? veff : log1pf(expf(veff));
    float g_ch = beta_tau[lh] * sp;
    float r    = expf(-g_ch / C_ch[lh]);          // 1 - lam
    float G    = beta_gm[lh] * sp * (1.f / (1.f + expf(-veff)));
    float sgn  = tanhf(alpha[l] * (g_ch - icth[l]));
    ret[idx]  = r;
    gate[idx] = gma[lh] * sgn * G;
}

// ---------------- sequential recurrence (register-prefetch pipelined) -----
// grid = B*H blocks, 256 threads. thread i: row v = i>>2, k-slice = (i&3)*16.
__global__ void __launch_bounds__(256, 1) scan_kernel(const float* __restrict__ qkv,
                                                      const float* __restrict__ ret,
                                                      const float* __restrict__ gate,
                                                      const float* __restrict__ W,
                                                      float* __restrict__ y) {
    int bh = blockIdx.x;
    int b = bh / Hh, h = bh % Hh;
    int tid = threadIdx.x;
    int v = tid >> 2, part = tid & 3, koff = part * 16;

    float r[16], g[16], w[16], f[16];
    {
        int base = (h*DK + v)*DK + koff;
        #pragma unroll
        for (int j = 0; j < 16; j++) {
            r[j] = ret[base + j];
            g[j] = gate[base + j];
            w[j] = W[base + j];
            f[j] = 0.f;
        }
    }

    __shared__ float sbuf[2][192];   // [q(64) | k(64) | v(64)]
    bool loader = tid < 192;
    int which = tid >> 6, lane = tid & 63;
    size_t rowbase = (size_t)b * Tlen * (3*Dm) + h * DK;
    const float* src = qkv + rowbase + which * Dm + lane;
    float pre = loader ? src[0] : 0.f;
    float* yout = y + (size_t)b * Tlen * Dm + h * DK + v;

    for (int t = 0; t < Tlen; t++) {
        int p = t & 1;
        if (loader) sbuf[p][tid] = pre;
        __syncthreads();
        if (loader && (t + 1 < Tlen))
            pre = src[(size_t)(t + 1) * (3*Dm)];      // hidden behind compute
        float vt = sbuf[p][128 + v];
        const float4* k4 = (const float4*)&sbuf[p][64 + koff];
        const float4* q4 = (const float4*)&sbuf[p][koff];
        float yacc = 0.f;
        #pragma unroll
        for (int j4 = 0; j4 < 4; j4++) {
            float4 kk = k4[j4];
            float4 qq = q4[j4];
            int j = j4 * 4;
            f[j+0] = r[j+0]*f[j+0] + (g[j+0]*vt)*kk.x;
            f[j+1] = r[j+1]*f[j+1] + (g[j+1]*vt)*kk.y;
            f[j+2] = r[j+2]*f[j+2] + (g[j+2]*vt)*kk.z;
            f[j+3] = r[j+3]*f[j+3] + (g[j+3]*vt)*kk.w;
            yacc = fmaf(w[j+0] + f[j+0], qq.x, yacc);
            yacc = fmaf(w[j+1] + f[j+1], qq.y, yacc);
            yacc = fmaf(w[j+2] + f[j+2], qq.z, yacc);
            yacc = fmaf(w[j+3] + f[j+3], qq.w, yacc);
        }
        yacc += __shfl_xor_sync(0xffffffffu, yacc, 1);
        yacc += __shfl_xor_sync(0xffffffffu, yacc, 2);
        if (part == 0) yout[(size_t)t * Dm] = yacc;
    }
}

// ---------------- tf32 tensor-core GEMM: C = A * B^T (+Res) ---------------
// A: (M,K) row-major fp32; B: (N,K) row-major fp32 (weights).
// Block 128x128, BK=16, 8 warps each 64x32, mma.sync m16n8k8 tf32.
#define BMt 128
#define BNt 128
#define BKt 16
#define ASTR 20      // padded smem stride (conflict-free for frag reads)

__device__ __forceinline__ float to_tf32(float x) {
    asm("cvt.rna.tf32.f32 %0, %0;" : "+f"(x));
    return x;
}

__device__ __forceinline__ void mma_tf32(float c[4],
                                         uint32_t a0, uint32_t a1, uint32_t a2, uint32_t a3,
                                         uint32_t b0, uint32_t b1) {
    asm volatile(
        "mma.sync.aligned.m16n8k8.row.col.f32.tf32.tf32.f32 "
        "{%0,%1,%2,%3}, {%4,%5,%6,%7}, {%8,%9}, {%0,%1,%2,%3};\n"
        : "+f"(c[0]), "+f"(c[1]), "+f"(c[2]), "+f"(c[3])
        : "r"(a0), "r"(a1), "r"(a2), "r"(a3), "r"(b0), "r"(b1));
}

__global__ void __launch_bounds__(256) mma_nt(int M, int N, int K,
                                              const float* __restrict__ A,
                                              const float* __restrict__ B,
                                              const float* __restrict__ Res,
                                              float* __restrict__ C) {
    __shared__ float As[2][BMt*ASTR];
    __shared__ float Bs[2][BNt*ASTR];
    int tid = threadIdx.x;
    int wid = tid >> 5, lane = tid & 31;
    int wm = (wid >> 2) * 64;        // 0 or 64
    int wn = (wid & 3) * 32;         // 0,32,64,96
    int m0 = blockIdx.y * BMt, n0 = blockIdx.x * BNt;
    int lg = lane >> 2;              // 0..7
    int lq = lane & 3;               // 0..3

    float acc[4][4][4];
    #pragma unroll
    for (int i = 0; i < 4; i++)
        #pragma unroll
        for (int j = 0; j < 4; j++)
            #pragma unroll
            for (int q = 0; q < 4; q++) acc[i][j][q] = 0.f;

    // loader mapping: v = tid + s*256; row = v>>2 (0..127), c4 = (v&3)*4
    int r0 = tid >> 2, c4 = (tid & 3) << 2;

    float4 pa[2], pb[2];
    {
        const float* Ab = A + (size_t)(m0 + r0) * K + c4;
        const float* Bbp = B + (size_t)(n0 + r0) * K + c4;
        pa[0] = *(const float4*)Ab;
        pb[0] = *(const float4*)Bbp;
        pa[1] = *(const float4*)(Ab + (size_t)64 * K);
        pb[1] = *(const float4*)(Bbp + (size_t)64 * K);
    }

    int nTiles = K / BKt;
    for (int kt = 0; kt < nTiles; kt++) {
        int p = kt & 1;
        // store prefetched tile into smem buffer p (tf32-rounded)
        #pragma unroll
        for (int s = 0; s < 2; s++) {
            float4 a = pa[s], bq = pb[s];
            a.x = to_tf32(a.x); a.y = to_tf32(a.y); a.z = to_tf32(a.z); a.w = to_tf32(a.w);
            bq.x = to_tf32(bq.x); bq.y = to_tf32(bq.y); bq.z = to_tf32(bq.z); bq.w = to_tf32(bq.w);
            *(float4*)&As[p][(r0 + s*64)*ASTR + c4] = a;
            *(float4*)&Bs[p][(r0 + s*64)*ASTR + c4] = bq;
        }
        __syncthreads();

        // prefetch next tile (hidden behind the mma work)
        if (kt + 1 < nTiles) {
            int k0 = (kt + 1) * BKt;
            const float* Ab = A + (size_t)(m0 + r0) * K + k0 + c4;
            const float* Bbp = B + (size_t)(n0 + r0) * K + k0 + c4;
            pa[0] = *(const float4*)Ab;
            pb[0] = *(const float4*)Bbp;
            pa[1] = *(const float4*)(Ab + (size_t)64 * K);
            pb[1] = *(const float4*)(Bbp + (size_t)64 * K);
        }

        const uint32_t* Au = (const uint32_t*)As[p];
        const uint32_t* Bu = (const uint32_t*)Bs[p];
        #pragma unroll
        for (int q = 0; q < 2; q++) {
            int kb = q * 8;
            uint32_t af[4][4], bf[4][2];
            #pragma unroll
            for (int i = 0; i < 4; i++) {
                int R = wm + i*16 + lg;
                af[i][0] = Au[R*ASTR + kb + lq];
                af[i][1] = Au[(R+8)*ASTR + kb + lq];
                af[i][2] = Au[R*ASTR + kb + lq + 4];
                af[i][3] = Au[(R+8)*ASTR + kb + lq + 4];
            }
            #pragma unroll
            for (int j = 0; j < 4; j++) {
                int Nr = wn + j*8 + lg;
                bf[j][0] = Bu[Nr*ASTR + kb + lq];
                bf[j][1] = Bu[Nr*ASTR + kb + lq + 4];
            }
            #pragma unroll
            for (int i = 0; i < 4; i++)
                #pragma unroll
                for (int j = 0; j < 4; j++)
                    mma_tf32(acc[i][j], af[i][0], af[i][1], af[i][2], af[i][3],
                             bf[j][0], bf[j][1]);
        }
        __syncthreads();
    }

    // epilogue: c0 (row,col),(row,col+1); c2,c3 at row+8
    #pragma unroll
    for (int i = 0; i < 4; i++) {
        int row = m0 + wm + i*16 + lg;
        #pragma unroll
        for (int j = 0; j < 4; j++) {
            int col = n0 + wn + j*8 + 2*lq;
            size_t o0 = (size_t)row * N + col;
            size_t o1 = (size_t)(row + 8) * N + col;
            float2 v0 = make_float2(acc[i][j][0], acc[i][j][1]);
            float2 v1 = make_float2(acc[i][j][2], acc[i][j][3]);
            if (Res) {
                float2 q0 = *(const float2*)(Res + o0);
                float2 q1 = *(const float2*)(Res + o1);
                v0.x += q0.x; v0.y += q0.y;
                v1.x += q1.x; v1.y += q1.y;
            }
            *(float2*)(C + o0) = v0;
            *(float2*)(C + o1) = v1;
        }
    }
}

// ---------------- launch ----------------
extern "C" void kernel_launch(void* const* d_in, const int* in_sizes, int n_in,
                              void* d_out, int out_size) {
    const int*   ids      = (const int*)  d_in[0];
    // d_in[1] = state_quant_bits = 16 -> no quantization path
    const float* embedW   = (const float*)d_in[2];
    const float* conv_w   = (const float*)d_in[3];
    const float* conv_b   = (const float*)d_in[4];
    const float* Wqkv     = (const float*)d_in[5];
    const float* Wo       = (const float*)d_in[6];
    const float* W_LTM    = (const float*)d_in[7];
    const float* V_T0     = (const float*)d_in[8];
    const float* V_gs     = (const float*)d_in[9];
    const float* beta_tau = (const float*)d_in[10];
    const float* beta_gm  = (const float*)d_in[11];
    const float* C_ch     = (const float*)d_in[12];
    const float* gma      = (const float*)d_in[13];
    const float* alpha    = (const float*)d_in[14];
    const float* icth     = (const float*)d_in[15];
    const float* ln1_g    = (const float*)d_in[16];
    const float* ln1_b    = (const float*)d_in[17];
    const float* lnk_g    = (const float*)d_in[18];
    const float* lnk_b    = (const float*)d_in[19];
    const float* lnf_g    = (const float*)d_in[20];
    const float* lnf_b    = (const float*)d_in[21];
    const float* headW    = (const float*)d_in[22];
    float* out = (float*)d_out;

    float *x, *h, *h2, *qkv, *y, *ret, *gate;
    cudaGetSymbolAddress((void**)&x,    g_x);
    cudaGetSymbolAddress((void**)&h,    g_h);
    cudaGetSymbolAddress((void**)&h2,   g_h2);
    cudaGetSymbolAddress((void**)&qkv,  g_qkv);
    cudaGetSymbolAddress((void**)&y,    g_y);
    cudaGetSymbolAddress((void**)&ret,  g_ret);
    cudaGetSymbolAddress((void**)&gate, g_gate);

    embed_kernel<<<NROW, 256>>>(ids, embedW, x);
    {
        int n = Ll*Hh*DK*DK;
        physics_kernel<<<(n + 255)/256, 256>>>(W_LTM, V_T0, V_gs, beta_tau, beta_gm,
                                               C_ch, gma, alpha, icth, ret, gate);
    }

    for (int l = 0; l < Ll; l++) {
        ln_kernel<<<NROW, 256>>>(x, ln1_g + l*Dm, ln1_b + l*Dm, h);
        conv_kernel<<<NROW, 256>>>(h, conv_w + l*3*Dm, conv_b + l*Dm, h2);

        dim3 gq((3*Dm)/BNt, NROW/BMt);
        mma_nt<<<gq, 256>>>(NROW, 3*Dm, Dm, h2, Wqkv + (size_t)l*3*Dm*Dm, nullptr, qkv);

        kln_kernel<<<NROW, 512>>>(qkv, lnk_g + l*DK, lnk_b + l*DK);

        scan_kernel<<<Bb*Hh, 256>>>(qkv,
                                    ret  + (size_t)l*Hh*DK*DK,
                                    gate + (size_t)l*Hh*DK*DK,
                                    W_LTM + (size_t)l*Hh*DK*DK,
                                    y);

        dim3 go(Dm/BNt, NROW/BMt);
        mma_nt<<<go, 256>>>(NROW, Dm, Dm, y, Wo + (size_t)l*Dm*Dm, x, x);
    }

    ln_kernel<<<NROW, 256>>>(x, lnf_g, lnf_b, h);
    dim3 gh(Vv/BNt, NROW/BMt);
    mma_nt<<<gh, 256>>>(NROW, Vv, Dm, h, headW, nullptr, out);
}

// round 5
// speedup vs baseline: 2.4146x; 1.1382x over previous
#include <cuda_runtime.h>
#include <math.h>
#include <stdint.h>

// ---------------- problem constants ----------------
#define Dm    1024
#define Tlen  2048
#define Bb    4
#define Hh    16
#define DK    64
#define Ll    2
#define Vv    8192
#define NROW  (Bb*Tlen)          // 8192 token rows

// ---------------- scratch (device globals; no allocation allowed) ----------
__device__ float g_x  [NROW*Dm];
__device__ float g_h  [NROW*Dm];
__device__ float g_h2 [NROW*Dm];
__device__ float g_qkv[NROW*3*Dm];
__device__ float g_y  [NROW*Dm];
__device__ float g_ret [Ll*Hh*DK*DK];
__device__ float g_gate[Ll*Hh*DK*DK];
// pre-rounded (tf32) weights
__device__ float g_wq [Ll*3*Dm*Dm];     // 24 MB
__device__ float g_wo [Ll*Dm*Dm];       // 8 MB
__device__ float g_wh [Vv*Dm];          // 32 MB

__device__ __forceinline__ float to_tf32(float x) {
    asm("cvt.rna.tf32.f32 %0, %0;" : "+f"(x));
    return x;
}

// ---------------- weight pre-round (tf32) ----------------
__global__ void __launch_bounds__(256) round_kernel(const float* __restrict__ s,
                                                    float* __restrict__ d) {
    int i = (blockIdx.x * blockDim.x + threadIdx.x) * 4;
    float4 v = *(const float4*)(s + i);
    v.x = to_tf32(v.x); v.y = to_tf32(v.y);
    v.z = to_tf32(v.z); v.w = to_tf32(v.w);
    *(float4*)(d + i) = v;
}

// ---------------- embedding gather ----------------
__global__ void embed_kernel(const int* __restrict__ ids,
                             const float* __restrict__ W,
                             float* __restrict__ x) {
    int row = blockIdx.x;
    int id  = ids[row];
    const float4* src = (const float4*)(W + (size_t)id * Dm);
    float4* dst = (float4*)(x + (size_t)row * Dm);
    for (int i = threadIdx.x; i < Dm/4; i += blockDim.x) dst[i] = src[i];
}

// ---------------- block reduce helper (blockDim == 256) ----------------
__device__ __forceinline__ float blockReduceSum(float v, float* sh) {
    #pragma unroll
    for (int o = 16; o; o >>= 1) v += __shfl_xor_sync(0xffffffffu, v, o);
    if ((threadIdx.x & 31) == 0) sh[threadIdx.x >> 5] = v;
    __syncthreads();
    float tot = 0.f;
    #pragma unroll
    for (int i = 0; i < 8; i++) tot += sh[i];
    __syncthreads();
    return tot;
}

// ---------------- layernorm over Dm (rnd: tf32-round the output) ----------
__global__ void __launch_bounds__(256) ln_kernel(const float* __restrict__ x,
                                                 const float* __restrict__ g,
                                                 const float* __restrict__ b,
                                                 float* __restrict__ out,
                                                 int rnd) {
    __shared__ float sh[8];
    int row = blockIdx.x;
    const float* xr = x + (size_t)row * Dm;
    int i0 = threadIdx.x * 4;
    float4 xv = *(const float4*)(xr + i0);
    float s = xv.x + xv.y + xv.z + xv.w;
    float mean = blockReduceSum(s, sh) * (1.f / Dm);
    float d0 = xv.x - mean, d1 = xv.y - mean, d2 = xv.z - mean, d3 = xv.w - mean;
    float sq = d0*d0 + d1*d1 + d2*d2 + d3*d3;
    float var = blockReduceSum(sq, sh) * (1.f / Dm);
    float rstd = rsqrtf(var + 1e-5f);
    float4 gv = *(const float4*)(g + i0);
    float4 bv = *(const float4*)(b + i0);
    float4 ov;
    ov.x = d0 * rstd * gv.x + bv.x;
    ov.y = d1 * rstd * gv.y + bv.y;
    ov.z = d2 * rstd * gv.z + bv.z;
    ov.w = d3 * rstd * gv.w + bv.w;
    if (rnd) {
        ov.x = to_tf32(ov.x); ov.y = to_tf32(ov.y);
        ov.z = to_tf32(ov.z); ov.w = to_tf32(ov.w);
    }
    *(float4*)(out + (size_t)row * Dm + i0) = ov;
}

// ---------------- causal depthwise conv (output tf32-rounded) -------------
__global__ void __launch_bounds__(256) conv_kernel(const float* __restrict__ h,
                                                   const float* __restrict__ cw,
                                                   const float* __restrict__ cb,
                                                   float* __restrict__ out) {
    int row = blockIdx.x;
    int t = row % Tlen;
    const float* h0 = h + (size_t)row * Dm;
    int i = threadIdx.x * 4;
    float4 cur = *(const float4*)(h0 + i);
    float4 w0 = *(const float4*)(cw + 0*Dm + i);
    float4 w1 = *(const float4*)(cw + 1*Dm + i);
    float4 w2 = *(const float4*)(cw + 2*Dm + i);
    float4 bb = *(const float4*)(cb + i);
    float4 z = make_float4(0.f, 0.f, 0.f, 0.f);
    float4 p1 = (t >= 1) ? *(const float4*)(h0 - Dm + i) : z;
    float4 p2 = (t >= 2) ? *(const float4*)(h0 - 2*Dm + i) : z;
    float4 o;
    o.x = to_tf32(cur.x + w0.x*p2.x + w1.x*p1.x + w2.x*cur.x + bb.x);
    o.y = to_tf32(cur.y + w0.y*p2.y + w1.y*p1.y + w2.y*cur.y + bb.y);
    o.z = to_tf32(cur.z + w0.z*p2.z + w1.z*p1.z + w2.z*cur.z + bb.z);
    o.w = to_tf32(cur.w + w0.w*p2.w + w1.w*p1.w + w2.w*cur.w + bb.w);
    *(float4*)(out + (size_t)row * Dm + i) = o;
}

// ---------------- per-head k layernorm ----------------
__global__ void __launch_bounds__(512) kln_kernel(float* __restrict__ qkv,
                                                  const float* __restrict__ g,
                                                  const float* __restrict__ b) {
    int row = blockIdx.x;
    int wid = threadIdx.x >> 5, lane = threadIdx.x & 31;
    float* k = qkv + (size_t)row * (3*Dm) + Dm + wid * DK;
    float x0 = k[lane], x1 = k[lane + 32];
    float s = x0 + x1;
    #pragma unroll
    for (int o = 16; o; o >>= 1) s += __shfl_xor_sync(0xffffffffu, s, o);
    float mean = s * (1.f / DK);
    float d0 = x0 - mean, d1 = x1 - mean;
    float q = d0*d0 + d1*d1;
    #pragma unroll
    for (int o = 16; o; o >>= 1) q += __shfl_xor_sync(0xffffffffu, q, o);
    float rstd = rsqrtf(q * (1.f / DK) + 1e-5f);
    k[lane]      = d0 * rstd * g[lane]      + b[lane];
    k[lane + 32] = d1 * rstd * g[lane + 32] + b[lane + 32];
}

// ---------------- static physics ----------------
__global__ void physics_kernel(const float* __restrict__ W_LTM,
                               const float* __restrict__ V_T0,
                               const float* __restrict__ V_gs,
                               const float* __restrict__ beta_tau,
                               const float* __restrict__ beta_gm,
                               const float* __restrict__ C_ch,
                               const float* __restrict__ gma,
                               const float* __restrict__ alpha,
                               const float* __restrict__ icth,
                               float* __restrict__ ret,
                               float* __restrict__ gate) {
    int idx = blockIdx.x * blockDim.x + threadIdx.x;
    if (idx >= Ll*Hh*DK*DK) return;
    int lh = idx / (DK*DK);
    int l  = lh / Hh;
    float veff = (V_gs[lh] - V_T0[lh]) + W_LTM[idx];
    float sp   = (veff > 20.f) ? veff : log1pf(expf(veff));
    float g_ch = beta_tau[lh] * sp;
    float r    = expf(-g_ch / C_ch[lh]);
    float G    = beta_gm[lh] * sp * (1.f / (1.f + expf(-veff)));
    float sgn  = tanhf(alpha[l] * (g_ch - icth[l]));
    ret[idx]  = r;
    gate[idx] = gma[lh] * sgn * G;
}

// ---------------- sequential recurrence (v-split: 128 blocks) ----------------
// block bh2: bh = bh2>>1, v-half = bh2&1 (32 v-rows). 256 thr = 32 rows x 8.
__global__ void __launch_bounds__(256, 1) scan_kernel(const float* __restrict__ qkv,
                                                      const float* __restrict__ ret,
                                                      const float* __restrict__ gate,
                                                      const float* __restrict__ W,
                                                      float* __restrict__ y) {
    int bh = blockIdx.x >> 1;
    int vh = blockIdx.x & 1;
    int b = bh / Hh, h = bh % Hh;
    int tid = threadIdx.x;
    int v = vh * 32 + (tid >> 3), part = tid & 7, koff = part * 8;

    float r[8], g[8], w[8], f[8];
    {
        int base = (h*DK + v)*DK + koff;
        #pragma unroll
        for (int j = 0; j < 8; j++) {
            r[j] = ret[base + j];
            g[j] = gate[base + j];
            w[j] = W[base + j];
            f[j] = 0.f;
        }
    }

    __shared__ float sbuf[2][192];   // [q(64) | k(64) | v(64)]
    bool loader = tid < 192;
    int which = tid >> 6, lane = tid & 63;
    size_t rowbase = (size_t)b * Tlen * (3*Dm) + h * DK;
    const float* src = qkv + rowbase + which * Dm + lane;
    float pre = loader ? src[0] : 0.f;
    float* yout = y + (size_t)b * Tlen * Dm + h * DK + v;

    for (int t = 0; t < Tlen; t++) {
        int p = t & 1;
        if (loader) sbuf[p][tid] = pre;
        __syncthreads();
        if (loader && (t + 1 < Tlen))
            pre = src[(size_t)(t + 1) * (3*Dm)];
        float vt = sbuf[p][128 + v];
        const float4* k4 = (const float4*)&sbuf[p][64 + koff];
        const float4* q4 = (const float4*)&sbuf[p][koff];
        float yacc = 0.f;
        #pragma unroll
        for (int j4 = 0; j4 < 2; j4++) {
            float4 kk = k4[j4];
            float4 qq = q4[j4];
            int j = j4 * 4;
            f[j+0] = r[j+0]*f[j+0] + (g[j+0]*vt)*kk.x;
            f[j+1] = r[j+1]*f[j+1] + (g[j+1]*vt)*kk.y;
            f[j+2] = r[j+2]*f[j+2] + (g[j+2]*vt)*kk.z;
            f[j+3] = r[j+3]*f[j+3] + (g[j+3]*vt)*kk.w;
            yacc = fmaf(w[j+0] + f[j+0], qq.x, yacc);
            yacc = fmaf(w[j+1] + f[j+1], qq.y, yacc);
            yacc = fmaf(w[j+2] + f[j+2], qq.z, yacc);
            yacc = fmaf(w[j+3] + f[j+3], qq.w, yacc);
        }
        yacc += __shfl_xor_sync(0xffffffffu, yacc, 1);
        yacc += __shfl_xor_sync(0xffffffffu, yacc, 2);
        yacc += __shfl_xor_sync(0xffffffffu, yacc, 4);
        if (part == 0) yout[(size_t)t * Dm] = to_tf32(yacc);
    }
}

// ======== tf32 tensor-core GEMM v2: cp.async 4-stage pipeline ========
// C = A * B^T (+Res). A:(M,K), B:(N,K) row-major, both already tf32-rounded.
// Block 128x128, BK=16, 8 warps each 64x32, mma.sync m16n8k8 tf32.
#define BKt   16
#define ASTR  20                         // padded smem stride (floats)
#define NSTG  4
#define STG_FLTS (128*ASTR)              // 2560 floats = 10240 B per tile
#define SOFF_B   (NSTG*STG_FLTS)         // B tiles after A tiles
#define G_SMEM_FLTS (2*NSTG*STG_FLTS)    // 20480 floats = 81920 B

__device__ __forceinline__ void cpasync16(uint32_t dst_smem, const void* src) {
    asm volatile("cp.async.cg.shared.global [%0], [%1], 16;"
                 :: "r"(dst_smem), "l"(src) : "memory");
}
__device__ __forceinline__ uint32_t smem_u32(const void* p) {
    uint32_t a;
    asm("{ .reg .u64 t; cvta.to.shared.u64 t, %1; cvt.u32.u64 %0, t; }"
        : "=r"(a) : "l"(p));
    return a;
}

__device__ __forceinline__ void mma_tf32(float c[4],
                                         uint32_t a0, uint32_t a1, uint32_t a2, uint32_t a3,
                                         uint32_t b0, uint32_t b1) {
    asm volatile(
        "mma.sync.aligned.m16n8k8.row.col.f32.tf32.tf32.f32 "
        "{%0,%1,%2,%3}, {%4,%5,%6,%7}, {%8,%9}, {%0,%1,%2,%3};\n"
        : "+f"(c[0]), "+f"(c[1]), "+f"(c[2]), "+f"(c[3])
        : "r"(a0), "r"(a1), "r"(a2), "r"(a3), "r"(b0), "r"(b1));
}

// issue one 128x16 A-tile + B-tile pair into stage buffer s via cp.async
__device__ __forceinline__ void issue_tile(uint32_t sbase,
                                           const float* __restrict__ Agp,
                                           const float* __restrict__ Bgp,
                                           int K, int s, int kt,
                                           int r0, int c40, int r1, int c41) {
    int k0 = kt * BKt;
    uint32_t ao = sbase + (uint32_t)(s * STG_FLTS) * 4u;
    uint32_t bo = sbase + (uint32_t)(SOFF_B + s * STG_FLTS) * 4u;
    cpasync16(ao + (uint32_t)(r0*ASTR + c40)*4u, Agp + (size_t)r0*K + k0 + c40);
    cpasync16(ao + (uint32_t)(r1*ASTR + c41)*4u, Agp + (size_t)r1*K + k0 + c41);
    cpasync16(bo + (uint32_t)(r0*ASTR + c40)*4u, Bgp + (size_t)r0*K + k0 + c40);
    cpasync16(bo + (uint32_t)(r1*ASTR + c41)*4u, Bgp + (size_t)r1*K + k0 + c41);
}

__global__ void __launch_bounds__(256, 2) mma_nt(int M, int N, int K,
                                                 const float* __restrict__ A,
                                                 const float* __restrict__ B,
                                                 const float* __restrict__ Res,
                                                 float* __restrict__ C) {
    extern __shared__ float smem[];
    uint32_t sbase = smem_u32(smem);
    int tid = threadIdx.x;
    int wid = tid >> 5, lane = tid & 31;
    int wm = (wid >> 2) * 64;
    int wn = (wid & 3) * 32;
    int m0 = blockIdx.y * 128, n0 = blockIdx.x * 128;
    int lg = lane >> 2;              // 0..7
    int lq = lane & 3;               // 0..3

    float acc[4][4][4];
    #pragma unroll
    for (int i = 0; i < 4; i++)
        #pragma unroll
        for (int j = 0; j < 4; j++)
            #pragma unroll
            for (int q = 0; q < 4; q++) acc[i][j][q] = 0.f;

    const float* Agp = A + (size_t)m0 * K;
    const float* Bgp = B + (size_t)n0 * K;
    // loader mapping: 512 16B-chunks per 128x16 tile; 2 per thread
    int r0 = tid >> 2, c40 = (tid & 3) << 2;
    int r1 = (tid + 256) >> 2, c41 = c40;

    int nTiles = K / BKt;

    // prologue: stages 0..2
    issue_tile(sbase, Agp, Bgp, K, 0, 0, r0, c40, r1, c41);
    asm volatile("cp.async.commit_group;");
    issue_tile(sbase, Agp, Bgp, K, 1, 1, r0, c40, r1, c41);
    asm volatile("cp.async.commit_group;");
    issue_tile(sbase, Agp, Bgp, K, 2, 2, r0, c40, r1, c41);
    asm volatile("cp.async.commit_group;");

    for (int kt = 0; kt < nTiles; kt++) {
        int s = kt & (NSTG - 1);
        asm volatile("cp.async.wait_group 2;");
        __syncthreads();
        // refill the free buffer; empty commit keeps wait accounting uniform
        if (kt + 3 < nTiles)
            issue_tile(sbase, Agp, Bgp, K, (kt + 3) & (NSTG - 1), kt + 3,
                       r0, c40, r1, c41);
        asm volatile("cp.async.commit_group;");

        const uint32_t* Au = (const uint32_t*)(smem + s * STG_FLTS);
        const uint32_t* Bu = (const uint32_t*)(smem + SOFF_B + s * STG_FLTS);
        #pragma unroll
        for (int q = 0; q < 2; q++) {
            int kb = q * 8;
            uint32_t af[4][4], bf[4][2];
            #pragma unroll
            for (int i = 0; i < 4; i++) {
                int R = wm + i*16 + lg;
                af[i][0] = Au[R*ASTR + kb + lq];
                af[i][1] = Au[(R+8)*ASTR + kb + lq];
                af[i][2] = Au[R*ASTR + kb + lq + 4];
                af[i][3] = Au[(R+8)*ASTR + kb + lq + 4];
            }
            #pragma unroll
            for (int j = 0; j < 4; j++) {
                int Nr = wn + j*8 + lg;
                bf[j][0] = Bu[Nr*ASTR + kb + lq];
                bf[j][1] = Bu[Nr*ASTR + kb + lq + 4];
            }
            #pragma unroll
            for (int i = 0; i < 4; i++)
                #pragma unroll
                for (int j = 0; j < 4; j++)
                    mma_tf32(acc[i][j], af[i][0], af[i][1], af[i][2], af[i][3],
                             bf[j][0], bf[j][1]);
        }
        __syncthreads();
    }

    // epilogue
    #pragma unroll
    for (int i = 0; i < 4; i++) {
        int row = m0 + wm + i*16 + lg;
        #pragma unroll
        for (int j = 0; j < 4; j++) {
            int col = n0 + wn + j*8 + 2*lq;
            size_t o0 = (size_t)row * N + col;
            size_t o1 = (size_t)(row + 8) * N + col;
            float2 v0 = make_float2(acc[i][j][0], acc[i][j][1]);
            float2 v1 = make_float2(acc[i][j][2], acc[i][j][3]);
            if (Res) {
                float2 q0 = *(const float2*)(Res + o0);
                float2 q1 = *(const float2*)(Res + o1);
                v0.x += q0.x; v0.y += q0.y;
                v1.x += q1.x; v1.y += q1.y;
            }
            *(float2*)(C + o0) = v0;
            *(float2*)(C + o1) = v1;
        }
    }
}

// ---------------- launch ----------------
extern "C" void kernel_launch(void* const* d_in, const int* in_sizes, int n_in,
                              void* d_out, int out_size) {
    const int*   ids      = (const int*)  d_in[0];
    const float* embedW   = (const float*)d_in[2];
    const float* conv_w   = (const float*)d_in[3];
    const float* conv_b   = (const float*)d_in[4];
    const float* Wqkv     = (const float*)d_in[5];
    const float* Wo       = (const float*)d_in[6];
    const float* W_LTM    = (const float*)d_in[7];
    const float* V_T0     = (const float*)d_in[8];
    const float* V_gs     = (const float*)d_in[9];
    const float* beta_tau = (const float*)d_in[10];
    const float* beta_gm  = (const float*)d_in[11];
    const float* C_ch     = (const float*)d_in[12];
    const float* gma      = (const float*)d_in[13];
    const float* alpha    = (const float*)d_in[14];
    const float* icth     = (const float*)d_in[15];
    const float* ln1_g    = (const float*)d_in[16];
    const float* ln1_b    = (const float*)d_in[17];
    const float* lnk_g    = (const float*)d_in[18];
    const float* lnk_b    = (const float*)d_in[19];
    const float* lnf_g    = (const float*)d_in[20];
    const float* lnf_b    = (const float*)d_in[21];
    const float* headW    = (const float*)d_in[22];
    float* out = (float*)d_out;

    float *x, *h, *h2, *qkv, *y, *ret, *gate, *wq, *wo, *wh;
    cudaGetSymbolAddress((void**)&x,    g_x);
    cudaGetSymbolAddress((void**)&h,    g_h);
    cudaGetSymbolAddress((void**)&h2,   g_h2);
    cudaGetSymbolAddress((void**)&qkv,  g_qkv);
    cudaGetSymbolAddress((void**)&y,    g_y);
    cudaGetSymbolAddress((void**)&ret,  g_ret);
    cudaGetSymbolAddress((void**)&gate, g_gate);
    cudaGetSymbolAddress((void**)&wq,   g_wq);
    cudaGetSymbolAddress((void**)&wo,   g_wo);
    cudaGetSymbolAddress((void**)&wh,   g_wh);

    cudaFuncSetAttribute(mma_nt, cudaFuncAttributeMaxDynamicSharedMemorySize,
                         G_SMEM_FLTS * 4);

    // pre-round weights to tf32 (scratch)
    round_kernel<<<(Ll*3*Dm*Dm)/1024, 256>>>(Wqkv, wq);
    round_kernel<<<(Ll*Dm*Dm)/1024,   256>>>(Wo,   wo);
    round_kernel<<<(Vv*Dm)/1024,      256>>>(headW, wh);

    embed_kernel<<<NROW, 256>>>(ids, embedW, x);
    {
        int n = Ll*Hh*DK*DK;
        physics_kernel<<<(n + 255)/256, 256>>>(W_LTM, V_T0, V_gs, beta_tau, beta_gm,
                                               C_ch, gma, alpha, icth, ret, gate);
    }

    for (int l = 0; l < Ll; l++) {
        ln_kernel<<<NROW, 256>>>(x, ln1_g + l*Dm, ln1_b + l*Dm, h, 0);
        conv_kernel<<<NROW, 256>>>(h, conv_w + l*3*Dm, conv_b + l*Dm, h2);

        dim3 gq((3*Dm)/128, NROW/128);
        mma_nt<<<gq, 256, G_SMEM_FLTS*4>>>(NROW, 3*Dm, Dm, h2,
                                           wq + (size_t)l*3*Dm*Dm, nullptr, qkv);

        kln_kernel<<<NROW, 512>>>(qkv, lnk_g + l*DK, lnk_b + l*DK);

        scan_kernel<<<Bb*Hh*2, 256>>>(qkv,
                                      ret  + (size_t)l*Hh*DK*DK,
                                      gate + (size_t)l*Hh*DK*DK,
                                      W_LTM + (size_t)l*Hh*DK*DK,
                                      y);

        dim3 go(Dm/128, NROW/128);
        mma_nt<<<go, 256, G_SMEM_FLTS*4>>>(NROW, Dm, Dm, y,
                                           wo + (size_t)l*Dm*Dm, x, x);
    }

    ln_kernel<<<NROW, 256>>>(x, lnf_g, lnf_b, h, 1);
    dim3 gh(Vv/128, NROW/128);
    mma_nt<<<gh, 256, G_SMEM_FLTS*4>>>(NROW, Vv, Dm, h, wh, nullptr, out);
}

// round 6
// speedup vs baseline: 2.9996x; 1.2423x over previous
#include <cuda_runtime.h>
#include <cuda_fp16.h>
#include <math.h>
#include <stdint.h>

// ---------------- problem constants ----------------
#define Dm    1024
#define Tlen  2048
#define Bb    4
#define Hh    16
#define DK    64
#define Ll    2
#define Vv    8192
#define NROW  (Bb*Tlen)          // 8192 token rows

// ---------------- scratch (device globals; no allocation allowed) ----------
__device__ float  g_x  [NROW*Dm];        // residual stream (fp32)
__device__ float  g_h  [NROW*Dm];        // ln output (fp32, conv input)
__device__ __half g_h2h[NROW*Dm];        // conv output (half, A of qkv GEMM)
__device__ float  g_qkv[NROW*3*Dm];      // fp32
__device__ __half g_yh [NROW*Dm];        // scan output (half, A of Wo GEMM)
__device__ __half g_hh [NROW*Dm];        // final ln output (half, A of head GEMM)
__device__ float  g_ret [Ll*Hh*DK*DK];
__device__ float  g_gate[Ll*Hh*DK*DK];
// half weights
__device__ __half g_wqh[Ll*3*Dm*Dm];
__device__ __half g_woh[Ll*Dm*Dm];
__device__ __half g_whh[Vv*Dm];

// ---------------- fp32 -> fp16 weight conversion ----------------
__global__ void __launch_bounds__(256) tohalf_kernel(const float* __restrict__ s,
                                                     __half* __restrict__ d) {
    int i = (blockIdx.x * blockDim.x + threadIdx.x) * 4;
    float4 v = *(const float4*)(s + i);
    __half2 lo = __floats2half2_rn(v.x, v.y);
    __half2 hi = __floats2half2_rn(v.z, v.w);
    *(__half2*)(d + i)     = lo;
    *(__half2*)(d + i + 2) = hi;
}

// ---------------- embedding gather ----------------
__global__ void embed_kernel(const int* __restrict__ ids,
                             const float* __restrict__ W,
                             float* __restrict__ x) {
    int row = blockIdx.x;
    int id  = ids[row];
    const float4* src = (const float4*)(W + (size_t)id * Dm);
    float4* dst = (float4*)(x + (size_t)row * Dm);
    for (int i = threadIdx.x; i < Dm/4; i += blockDim.x) dst[i] = src[i];
}

// ---------------- block reduce helper (blockDim == 256) ----------------
__device__ __forceinline__ float blockReduceSum(float v, float* sh) {
    #pragma unroll
    for (int o = 16; o; o >>= 1) v += __shfl_xor_sync(0xffffffffu, v, o);
    if ((threadIdx.x & 31) == 0) sh[threadIdx.x >> 5] = v;
    __syncthreads();
    float tot = 0.f;
    #pragma unroll
    for (int i = 0; i < 8; i++) tot += sh[i];
    __syncthreads();
    return tot;
}

// ---------------- layernorm (fp32 out) ----------------
__global__ void __launch_bounds__(256) ln_kernel(const float* __restrict__ x,
                                                 const float* __restrict__ g,
                                                 const float* __restrict__ b,
                                                 float* __restrict__ out) {
    __shared__ float sh[8];
    int row = blockIdx.x;
    const float* xr = x + (size_t)row * Dm;
    int i0 = threadIdx.x * 4;
    float4 xv = *(const float4*)(xr + i0);
    float s = xv.x + xv.y + xv.z + xv.w;
    float mean = blockReduceSum(s, sh) * (1.f / Dm);
    float d0 = xv.x - mean, d1 = xv.y - mean, d2 = xv.z - mean, d3 = xv.w - mean;
    float sq = d0*d0 + d1*d1 + d2*d2 + d3*d3;
    float var = blockReduceSum(sq, sh) * (1.f / Dm);
    float rstd = rsqrtf(var + 1e-5f);
    float4 gv = *(const float4*)(g + i0);
    float4 bv = *(const float4*)(b + i0);
    float4 ov;
    ov.x = d0 * rstd * gv.x + bv.x;
    ov.y = d1 * rstd * gv.y + bv.y;
    ov.z = d2 * rstd * gv.z + bv.z;
    ov.w = d3 * rstd * gv.w + bv.w;
    *(float4*)(out + (size_t)row * Dm + i0) = ov;
}

// ---------------- layernorm (half out, for head GEMM A) ----------------
__global__ void __launch_bounds__(256) lnh_kernel(const float* __restrict__ x,
                                                  const float* __restrict__ g,
                                                  const float* __restrict__ b,
                                                  __half* __restrict__ out) {
    __shared__ float sh[8];
    int row = blockIdx.x;
    const float* xr = x + (size_t)row * Dm;
    int i0 = threadIdx.x * 4;
    float4 xv = *(const float4*)(xr + i0);
    float s = xv.x + xv.y + xv.z + xv.w;
    float mean = blockReduceSum(s, sh) * (1.f / Dm);
    float d0 = xv.x - mean, d1 = xv.y - mean, d2 = xv.z - mean, d3 = xv.w - mean;
    float sq = d0*d0 + d1*d1 + d2*d2 + d3*d3;
    float var = blockReduceSum(sq, sh) * (1.f / Dm);
    float rstd = rsqrtf(var + 1e-5f);
    float4 gv = *(const float4*)(g + i0);
    float4 bv = *(const float4*)(b + i0);
    __half2 lo = __floats2half2_rn(d0 * rstd * gv.x + bv.x, d1 * rstd * gv.y + bv.y);
    __half2 hi = __floats2half2_rn(d2 * rstd * gv.z + bv.z, d3 * rstd * gv.w + bv.w);
    *(__half2*)(out + (size_t)row * Dm + i0)     = lo;
    *(__half2*)(out + (size_t)row * Dm + i0 + 2) = hi;
}

// ---------------- causal depthwise conv (half out) ----------------
__global__ void __launch_bounds__(256) conv_kernel(const float* __restrict__ h,
                                                   const float* __restrict__ cw,
                                                   const float* __restrict__ cb,
                                                   __half* __restrict__ out) {
    int row = blockIdx.x;
    int t = row % Tlen;
    const float* h0 = h + (size_t)row * Dm;
    int i = threadIdx.x * 4;
    float4 cur = *(const float4*)(h0 + i);
    float4 w0 = *(const float4*)(cw + 0*Dm + i);
    float4 w1 = *(const float4*)(cw + 1*Dm + i);
    float4 w2 = *(const float4*)(cw + 2*Dm + i);
    float4 bb = *(const float4*)(cb + i);
    float4 z = make_float4(0.f, 0.f, 0.f, 0.f);
    float4 p1 = (t >= 1) ? *(const float4*)(h0 - Dm + i) : z;
    float4 p2 = (t >= 2) ? *(const float4*)(h0 - 2*Dm + i) : z;
    float ox = cur.x + w0.x*p2.x + w1.x*p1.x + w2.x*cur.x + bb.x;
    float oy = cur.y + w0.y*p2.y + w1.y*p1.y + w2.y*cur.y + bb.y;
    float oz = cur.z + w0.z*p2.z + w1.z*p1.z + w2.z*cur.z + bb.z;
    float ow = cur.w + w0.w*p2.w + w1.w*p1.w + w2.w*cur.w + bb.w;
    *(__half2*)(out + (size_t)row * Dm + i)     = __floats2half2_rn(ox, oy);
    *(__half2*)(out + (size_t)row * Dm + i + 2) = __floats2half2_rn(oz, ow);
}

// ---------------- per-head k layernorm ----------------
__global__ void __launch_bounds__(512) kln_kernel(float* __restrict__ qkv,
                                                  const float* __restrict__ g,
                                                  const float* __restrict__ b) {
    int row = blockIdx.x;
    int wid = threadIdx.x >> 5, lane = threadIdx.x & 31;
    float* k = qkv + (size_t)row * (3*Dm) + Dm + wid * DK;
    float x0 = k[lane], x1 = k[lane + 32];
    float s = x0 + x1;
    #pragma unroll
    for (int o = 16; o; o >>= 1) s += __shfl_xor_sync(0xffffffffu, s, o);
    float mean = s * (1.f / DK);
    float d0 = x0 - mean, d1 = x1 - mean;
    float q = d0*d0 + d1*d1;
    #pragma unroll
    for (int o = 16; o; o >>= 1) q += __shfl_xor_sync(0xffffffffu, q, o);
    float rstd = rsqrtf(q * (1.f / DK) + 1e-5f);
    k[lane]      = d0 * rstd * g[lane]      + b[lane];
    k[lane + 32] = d1 * rstd * g[lane + 32] + b[lane + 32];
}

// ---------------- static physics ----------------
__global__ void physics_kernel(const float* __restrict__ W_LTM,
                               const float* __restrict__ V_T0,
                               const float* __restrict__ V_gs,
                               const float* __restrict__ beta_tau,
                               const float* __restrict__ beta_gm,
                               const float* __restrict__ C_ch,
                               const float* __restrict__ gma,
                               const float* __restrict__ alpha,
                               const float* __restrict__ icth,
                               float* __restrict__ ret,
                               float* __restrict__ gate) {
    int idx = blockIdx.x * blockDim.x + threadIdx.x;
    if (idx >= Ll*Hh*DK*DK) return;
    int lh = idx / (DK*DK);
    int l  = lh / Hh;
    float veff = (V_gs[lh] - V_T0[lh]) + W_LTM[idx];
    float sp   = (veff > 20.f) ? veff : log1pf(expf(veff));
    float g_ch = beta_tau[lh] * sp;
    float r    = expf(-g_ch / C_ch[lh]);
    float G    = beta_gm[lh] * sp * (1.f / (1.f + expf(-veff)));
    float sgn  = tanhf(alpha[l] * (g_ch - icth[l]));
    ret[idx]  = r;
    gate[idx] = gma[lh] * sgn * G;
}

// ---------------- sequential recurrence (v-split, half output) -------------
__global__ void __launch_bounds__(256, 1) scan_kernel(const float* __restrict__ qkv,
                                                      const float* __restrict__ ret,
                                                      const float* __restrict__ gate,
                                                      const float* __restrict__ W,
                                                      __half* __restrict__ y) {
    int bh = blockIdx.x >> 1;
    int vh = blockIdx.x & 1;
    int b = bh / Hh, h = bh % Hh;
    int tid = threadIdx.x;
    int v = vh * 32 + (tid >> 3), part = tid & 7, koff = part * 8;

    float r[8], g[8], w[8], f[8];
    {
        int base = (h*DK + v)*DK + koff;
        #pragma unroll
        for (int j = 0; j < 8; j++) {
            r[j] = ret[base + j];
            g[j] = gate[base + j];
            w[j] = W[base + j];
            f[j] = 0.f;
        }
    }

    __shared__ float sbuf[2][192];   // [q(64) | k(64) | v(64)]
    bool loader = tid < 192;
    int which = tid >> 6, lane = tid & 63;
    size_t rowbase = (size_t)b * Tlen * (3*Dm) + h * DK;
    const float* src = qkv + rowbase + which * Dm + lane;
    float pre = loader ? src[0] : 0.f;
    __half* yout = y + (size_t)b * Tlen * Dm + h * DK + v;

    for (int t = 0; t < Tlen; t++) {
        int p = t & 1;
        if (loader) sbuf[p][tid] = pre;
        __syncthreads();
        if (loader && (t + 1 < Tlen))
            pre = src[(size_t)(t + 1) * (3*Dm)];
        float vt = sbuf[p][128 + v];
        const float4* k4 = (const float4*)&sbuf[p][64 + koff];
        const float4* q4 = (const float4*)&sbuf[p][koff];
        float yacc = 0.f;
        #pragma unroll
        for (int j4 = 0; j4 < 2; j4++) {
            float4 kk = k4[j4];
            float4 qq = q4[j4];
            int j = j4 * 4;
            f[j+0] = r[j+0]*f[j+0] + (g[j+0]*vt)*kk.x;
            f[j+1] = r[j+1]*f[j+1] + (g[j+1]*vt)*kk.y;
            f[j+2] = r[j+2]*f[j+2] + (g[j+2]*vt)*kk.z;
            f[j+3] = r[j+3]*f[j+3] + (g[j+3]*vt)*kk.w;
            yacc = fmaf(w[j+0] + f[j+0], qq.x, yacc);
            yacc = fmaf(w[j+1] + f[j+1], qq.y, yacc);
            yacc = fmaf(w[j+2] + f[j+2], qq.z, yacc);
            yacc = fmaf(w[j+3] + f[j+3], qq.w, yacc);
        }
        yacc += __shfl_xor_sync(0xffffffffu, yacc, 1);
        yacc += __shfl_xor_sync(0xffffffffu, yacc, 2);
        yacc += __shfl_xor_sync(0xffffffffu, yacc, 4);
        if (part == 0) yout[(size_t)t * Dm] = __float2half_rn(yacc);
    }
}

// ======== fp16 tensor-core GEMM: cp.async 4-stage, m16n8k16 ========
// C = A * B^T (+Res). A:(M,K), B:(N,K) row-major __half. fp32 accumulate.
// Block 128x128, BK=16, 8 warps each 64x32.
#define BKt   16
#define HSTR  24                          // halves per smem row (12 words: conflict-free)
#define NSTG  4
#define HSTG  (128*HSTR)                  // halves per tile buffer (6144 B)
#define SOFF_B (NSTG*HSTG)
#define G_SMEM_HALVES (2*NSTG*HSTG)       // 49152 B

__device__ __forceinline__ void cpasync16(uint32_t dst_smem, const void* src) {
    asm volatile("cp.async.cg.shared.global [%0], [%1], 16;"
                 :: "r"(dst_smem), "l"(src) : "memory");
}
__device__ __forceinline__ uint32_t smem_u32(const void* p) {
    uint32_t a;
    asm("{ .reg .u64 t; cvta.to.shared.u64 t, %1; cvt.u32.u64 %0, t; }"
        : "=r"(a) : "l"(p));
    return a;
}

__device__ __forceinline__ void mma_f16(float c[4],
                                        uint32_t a0, uint32_t a1, uint32_t a2, uint32_t a3,
                                        uint32_t b0, uint32_t b1) {
    asm volatile(
        "mma.sync.aligned.m16n8k16.row.col.f32.f16.f16.f32 "
        "{%0,%1,%2,%3}, {%4,%5,%6,%7}, {%8,%9}, {%0,%1,%2,%3};\n"
        : "+f"(c[0]), "+f"(c[1]), "+f"(c[2]), "+f"(c[3])
        : "r"(a0), "r"(a1), "r"(a2), "r"(a3), "r"(b0), "r"(b1));
}

// issue one 128x16-half A-tile + B-tile into stage s. Per matrix: 256 chunks
// of 16B (128 rows x 2); each of 256 threads does exactly one chunk.
__device__ __forceinline__ void issue_tile_h(uint32_t sbase,
                                             const __half* __restrict__ Agp,
                                             const __half* __restrict__ Bgp,
                                             int K, int s, int kt,
                                             int rr, int ch) {
    int k0 = kt * BKt;
    uint32_t ao = sbase + (uint32_t)(s * HSTG) * 2u
                + (uint32_t)(rr * HSTR) * 2u + (uint32_t)ch * 16u;
    uint32_t bo = ao + (uint32_t)SOFF_B * 2u;
    cpasync16(ao, Agp + (size_t)rr * K + k0 + ch * 8);
    cpasync16(bo, Bgp + (size_t)rr * K + k0 + ch * 8);
}

__global__ void __launch_bounds__(256, 2) mma_nt_h(int M, int N, int K,
                                                   const __half* __restrict__ A,
                                                   const __half* __restrict__ B,
                                                   const float* __restrict__ Res,
                                                   float* __restrict__ C) {
    extern __shared__ __half smemh[];
    uint32_t sbase = smem_u32(smemh);
    int tid = threadIdx.x;
    int wid = tid >> 5, lane = tid & 31;
    int wm = (wid >> 2) * 64;
    int wn = (wid & 3) * 32;
    int m0 = blockIdx.y * 128, n0 = blockIdx.x * 128;
    int lg = lane >> 2;              // 0..7
    int lq = lane & 3;               // 0..3

    float acc[4][4][4];
    #pragma unroll
    for (int i = 0; i < 4; i++)
        #pragma unroll
        for (int j = 0; j < 4; j++)
            #pragma unroll
            for (int q = 0; q < 4; q++) acc[i][j][q] = 0.f;

    const __half* Agp = A + (size_t)m0 * K;
    const __half* Bgp = B + (size_t)n0 * K;
    int rr = tid >> 1, ch = tid & 1;

    int nTiles = K / BKt;

    issue_tile_h(sbase, Agp, Bgp, K, 0, 0, rr, ch);
    asm volatile("cp.async.commit_group;");
    issue_tile_h(sbase, Agp, Bgp, K, 1, 1, rr, ch);
    asm volatile("cp.async.commit_group;");
    issue_tile_h(sbase, Agp, Bgp, K, 2, 2, rr, ch);
    asm volatile("cp.async.commit_group;");

    for (int kt = 0; kt < nTiles; kt++) {
        int s = kt & (NSTG - 1);
        asm volatile("cp.async.wait_group 2;");
        __syncthreads();
        // refill freed buffer; barrier above guarantees no warp still reads it
        if (kt + 3 < nTiles)
            issue_tile_h(sbase, Agp, Bgp, K, (kt + 3) & (NSTG - 1), kt + 3, rr, ch);
        asm volatile("cp.async.commit_group;");

        const uint32_t* Au = (const uint32_t*)(smemh + s * HSTG);
        const uint32_t* Bu = (const uint32_t*)(smemh + SOFF_B + s * HSTG);
        uint32_t af[4][4], bf[4][2];
        #pragma unroll
        for (int i = 0; i < 4; i++) {
            int R = wm + i*16 + lg;
            af[i][0] = Au[R*12 + lq];
            af[i][1] = Au[(R+8)*12 + lq];
            af[i][2] = Au[R*12 + lq + 4];
            af[i][3] = Au[(R+8)*12 + lq + 4];
        }
        #pragma unroll
        for (int j = 0; j < 4; j++) {
            int Nr = wn + j*8 + lg;
            bf[j][0] = Bu[Nr*12 + lq];
            bf[j][1] = Bu[Nr*12 + lq + 4];
        }
        #pragma unroll
        for (int i = 0; i < 4; i++)
            #pragma unroll
            for (int j = 0; j < 4; j++)
                mma_f16(acc[i][j], af[i][0], af[i][1], af[i][2], af[i][3],
                        bf[j][0], bf[j][1]);
    }

    // epilogue
    #pragma unroll
    for (int i = 0; i < 4; i++) {
        int row = m0 + wm + i*16 + lg;
        #pragma unroll
        for (int j = 0; j < 4; j++) {
            int col = n0 + wn + j*8 + 2*lq;
            size_t o0 = (size_t)row * N + col;
            size_t o1 = (size_t)(row + 8) * N + col;
            float2 v0 = make_float2(acc[i][j][0], acc[i][j][1]);
            float2 v1 = make_float2(acc[i][j][2], acc[i][j][3]);
            if (Res) {
                float2 q0 = *(const float2*)(Res + o0);
                float2 q1 = *(const float2*)(Res + o1);
                v0.x += q0.x; v0.y += q0.y;
                v1.x += q1.x; v1.y += q1.y;
            }
            *(float2*)(C + o0) = v0;
            *(float2*)(C + o1) = v1;
        }
    }
}

// ---------------- launch ----------------
extern "C" void kernel_launch(void* const* d_in, const int* in_sizes, int n_in,
                              void* d_out, int out_size) {
    const int*   ids      = (const int*)  d_in[0];
    const float* embedW   = (const float*)d_in[2];
    const float* conv_w   = (const float*)d_in[3];
    const float* conv_b   = (const float*)d_in[4];
    const float* Wqkv     = (const float*)d_in[5];
    const float* Wo       = (const float*)d_in[6];
    const float* W_LTM    = (const float*)d_in[7];
    const float* V_T0     = (const float*)d_in[8];
    const float* V_gs     = (const float*)d_in[9];
    const float* beta_tau = (const float*)d_in[10];
    const float* beta_gm  = (const float*)d_in[11];
    const float* C_ch     = (const float*)d_in[12];
    const float* gma      = (const float*)d_in[13];
    const float* alpha    = (const float*)d_in[14];
    const float* icth     = (const float*)d_in[15];
    const float* ln1_g    = (const float*)d_in[16];
    const float* ln1_b    = (const float*)d_in[17];
    const float* lnk_g    = (const float*)d_in[18];
    const float* lnk_b    = (const float*)d_in[19];
    const float* lnf_g    = (const float*)d_in[20];
    const float* lnf_b    = (const float*)d_in[21];
    const float* headW    = (const float*)d_in[22];
    float* out = (float*)d_out;

    float *x, *h, *qkv, *ret, *gate;
    __half *h2h, *yh, *hh, *wqh, *woh, *whh;
    cudaGetSymbolAddress((void**)&x,    g_x);
    cudaGetSymbolAddress((void**)&h,    g_h);
    cudaGetSymbolAddress((void**)&h2h,  g_h2h);
    cudaGetSymbolAddress((void**)&qkv,  g_qkv);
    cudaGetSymbolAddress((void**)&yh,   g_yh);
    cudaGetSymbolAddress((void**)&hh,   g_hh);
    cudaGetSymbolAddress((void**)&ret,  g_ret);
    cudaGetSymbolAddress((void**)&gate, g_gate);
    cudaGetSymbolAddress((void**)&wqh,  g_wqh);
    cudaGetSymbolAddress((void**)&woh,  g_woh);
    cudaGetSymbolAddress((void**)&whh,  g_whh);

    cudaFuncSetAttribute(mma_nt_h, cudaFuncAttributeMaxDynamicSharedMemorySize,
                         G_SMEM_HALVES * 2);

    // weight conversions (once per launch; cheap)
    tohalf_kernel<<<(Ll*3*Dm*Dm)/1024, 256>>>(Wqkv,  wqh);
    tohalf_kernel<<<(Ll*Dm*Dm)/1024,   256>>>(Wo,    woh);
    tohalf_kernel<<<(Vv*Dm)/1024,      256>>>(headW, whh);

    embed_kernel<<<NROW, 256>>>(ids, embedW, x);
    {
        int n = Ll*Hh*DK*DK;
        physics_kernel<<<(n + 255)/256, 256>>>(W_LTM, V_T0, V_gs, beta_tau, beta_gm,
                                               C_ch, gma, alpha, icth, ret, gate);
    }

    for (int l = 0; l < Ll; l++) {
        ln_kernel<<<NROW, 256>>>(x, ln1_g + l*Dm, ln1_b + l*Dm, h);
        conv_kernel<<<NROW, 256>>>(h, conv_w + l*3*Dm, conv_b + l*Dm, h2h);

        dim3 gq((3*Dm)/128, NROW/128);
        mma_nt_h<<<gq, 256, G_SMEM_HALVES*2>>>(NROW, 3*Dm, Dm, h2h,
                                               wqh + (size_t)l*3*Dm*Dm, nullptr, qkv);

        kln_kernel<<<NROW, 512>>>(qkv, lnk_g + l*DK, lnk_b + l*DK);

        scan_kernel<<<Bb*Hh*2, 256>>>(qkv,
                                      ret  + (size_t)l*Hh*DK*DK,
                                      gate + (size_t)l*Hh*DK*DK,
                                      W_LTM + (size_t)l*Hh*DK*DK,
                                      yh);

        dim3 go(Dm/128, NROW/128);
        mma_nt_h<<<go, 256, G_SMEM_HALVES*2>>>(NROW, Dm, Dm, yh,
                                               woh + (size_t)l*Dm*Dm, x, x);
    }

    ln_kernel<<<NROW, 256>>>(x, lnf_g, lnf_b, h);
    lnh_kernel<<<NROW, 256>>>(x, lnf_g, lnf_b, hh);
    dim3 gh(Vv/128, NROW/128);
    mma_nt_h<<<gh, 256, G_SMEM_HALVES*2>>>(NROW, Vv, Dm, hh, whh, nullptr, out);
}

// round 7
// speedup vs baseline: 3.2819x; 1.0941x over previous
#include <cuda_runtime.h>
#include <cuda_fp16.h>
#include <math.h>
#include <stdint.h>

// ---------------- problem constants ----------------
#define Dm    1024
#define Tlen  2048
#define Bb    4
#define Hh    16
#define DK    64
#define Ll    2
#define Vv    8192
#define NROW  (Bb*Tlen)          // 8192 token rows

// ---------------- scratch (device globals; no allocation allowed) ----------
__device__ float  g_x  [NROW*Dm];        // residual stream (fp32)
__device__ float  g_h  [NROW*Dm];        // ln output (fp32, conv input)
__device__ __half g_h2h[NROW*Dm];        // conv output (half, A of qkv GEMM)
__device__ float  g_qkv[NROW*3*Dm];      // fp32
__device__ __half g_yh [NROW*Dm];        // scan output (half, A of Wo GEMM)
__device__ __half g_hh [NROW*Dm];        // final ln output (half, A of head GEMM)
__device__ float  g_ret [Ll*Hh*DK*DK];
__device__ float  g_gate[Ll*Hh*DK*DK];
// half weights
__device__ __half g_wqh[Ll*3*Dm*Dm];
__device__ __half g_woh[Ll*Dm*Dm];
__device__ __half g_whh[Vv*Dm];

// ---------------- fp32 -> fp16 weight conversion ----------------
__global__ void __launch_bounds__(256) tohalf_kernel(const float* __restrict__ s,
                                                     __half* __restrict__ d) {
    int i = (blockIdx.x * blockDim.x + threadIdx.x) * 4;
    float4 v = *(const float4*)(s + i);
    *(__half2*)(d + i)     = __floats2half2_rn(v.x, v.y);
    *(__half2*)(d + i + 2) = __floats2half2_rn(v.z, v.w);
}

// ---------------- embedding gather ----------------
__global__ void embed_kernel(const int* __restrict__ ids,
                             const float* __restrict__ W,
                             float* __restrict__ x) {
    int row = blockIdx.x;
    int id  = ids[row];
    const float4* src = (const float4*)(W + (size_t)id * Dm);
    float4* dst = (float4*)(x + (size_t)row * Dm);
    for (int i = threadIdx.x; i < Dm/4; i += blockDim.x) dst[i] = src[i];
}

// ---------------- block reduce helper (blockDim == 256) ----------------
__device__ __forceinline__ float blockReduceSum(float v, float* sh) {
    #pragma unroll
    for (int o = 16; o; o >>= 1) v += __shfl_xor_sync(0xffffffffu, v, o);
    if ((threadIdx.x & 31) == 0) sh[threadIdx.x >> 5] = v;
    __syncthreads();
    float tot = 0.f;
    #pragma unroll
    for (int i = 0; i < 8; i++) tot += sh[i];
    __syncthreads();
    return tot;
}

// ---------------- layernorm (fp32 out) ----------------
__global__ void __launch_bounds__(256) ln_kernel(const float* __restrict__ x,
                                                 const float* __restrict__ g,
                                                 const float* __restrict__ b,
                                                 float* __restrict__ out) {
    __shared__ float sh[8];
    int row = blockIdx.x;
    const float* xr = x + (size_t)row * Dm;
    int i0 = threadIdx.x * 4;
    float4 xv = *(const float4*)(xr + i0);
    float s = xv.x + xv.y + xv.z + xv.w;
    float mean = blockReduceSum(s, sh) * (1.f / Dm);
    float d0 = xv.x - mean, d1 = xv.y - mean, d2 = xv.z - mean, d3 = xv.w - mean;
    float sq = d0*d0 + d1*d1 + d2*d2 + d3*d3;
    float var = blockReduceSum(sq, sh) * (1.f / Dm);
    float rstd = rsqrtf(var + 1e-5f);
    float4 gv = *(const float4*)(g + i0);
    float4 bv = *(const float4*)(b + i0);
    float4 ov;
    ov.x = d0 * rstd * gv.x + bv.x;
    ov.y = d1 * rstd * gv.y + bv.y;
    ov.z = d2 * rstd * gv.z + bv.z;
    ov.w = d3 * rstd * gv.w + bv.w;
    *(float4*)(out + (size_t)row * Dm + i0) = ov;
}

// ---------------- layernorm (half out, for head GEMM A) ----------------
__global__ void __launch_bounds__(256) lnh_kernel(const float* __restrict__ x,
                                                  const float* __restrict__ g,
                                                  const float* __restrict__ b,
                                                  __half* __restrict__ out) {
    __shared__ float sh[8];
    int row = blockIdx.x;
    const float* xr = x + (size_t)row * Dm;
    int i0 = threadIdx.x * 4;
    float4 xv = *(const float4*)(xr + i0);
    float s = xv.x + xv.y + xv.z + xv.w;
    float mean = blockReduceSum(s, sh) * (1.f / Dm);
    float d0 = xv.x - mean, d1 = xv.y - mean, d2 = xv.z - mean, d3 = xv.w - mean;
    float sq = d0*d0 + d1*d1 + d2*d2 + d3*d3;
    float var = blockReduceSum(sq, sh) * (1.f / Dm);
    float rstd = rsqrtf(var + 1e-5f);
    float4 gv = *(const float4*)(g + i0);
    float4 bv = *(const float4*)(b + i0);
    *(__half2*)(out + (size_t)row * Dm + i0) =
        __floats2half2_rn(d0 * rstd * gv.x + bv.x, d1 * rstd * gv.y + bv.y);
    *(__half2*)(out + (size_t)row * Dm + i0 + 2) =
        __floats2half2_rn(d2 * rstd * gv.z + bv.z, d3 * rstd * gv.w + bv.w);
}

// ---------------- causal depthwise conv (half out) ----------------
__global__ void __launch_bounds__(256) conv_kernel(const float* __restrict__ h,
                                                   const float* __restrict__ cw,
                                                   const float* __restrict__ cb,
                                                   __half* __restrict__ out) {
    int row = blockIdx.x;
    int t = row % Tlen;
    const float* h0 = h + (size_t)row * Dm;
    int i = threadIdx.x * 4;
    float4 cur = *(const float4*)(h0 + i);
    float4 w0 = *(const float4*)(cw + 0*Dm + i);
    float4 w1 = *(const float4*)(cw + 1*Dm + i);
    float4 w2 = *(const float4*)(cw + 2*Dm + i);
    float4 bb = *(const float4*)(cb + i);
    float4 z = make_float4(0.f, 0.f, 0.f, 0.f);
    float4 p1 = (t >= 1) ? *(const float4*)(h0 - Dm + i) : z;
    float4 p2 = (t >= 2) ? *(const float4*)(h0 - 2*Dm + i) : z;
    float ox = cur.x + w0.x*p2.x + w1.x*p1.x + w2.x*cur.x + bb.x;
    float oy = cur.y + w0.y*p2.y + w1.y*p1.y + w2.y*cur.y + bb.y;
    float oz = cur.z + w0.z*p2.z + w1.z*p1.z + w2.z*cur.z + bb.z;
    float ow = cur.w + w0.w*p2.w + w1.w*p1.w + w2.w*cur.w + bb.w;
    *(__half2*)(out + (size_t)row * Dm + i)     = __floats2half2_rn(ox, oy);
    *(__half2*)(out + (size_t)row * Dm + i + 2) = __floats2half2_rn(oz, ow);
}

// ---------------- per-head k layernorm ----------------
__global__ void __launch_bounds__(512) kln_kernel(float* __restrict__ qkv,
                                                  const float* __restrict__ g,
                                                  const float* __restrict__ b) {
    int row = blockIdx.x;
    int wid = threadIdx.x >> 5, lane = threadIdx.x & 31;
    float* k = qkv + (size_t)row * (3*Dm) + Dm + wid * DK;
    float x0 = k[lane], x1 = k[lane + 32];
    float s = x0 + x1;
    #pragma unroll
    for (int o = 16; o; o >>= 1) s += __shfl_xor_sync(0xffffffffu, s, o);
    float mean = s * (1.f / DK);
    float d0 = x0 - mean, d1 = x1 - mean;
    float q = d0*d0 + d1*d1;
    #pragma unroll
    for (int o = 16; o; o >>= 1) q += __shfl_xor_sync(0xffffffffu, q, o);
    float rstd = rsqrtf(q * (1.f / DK) + 1e-5f);
    k[lane]      = d0 * rstd * g[lane]      + b[lane];
    k[lane + 32] = d1 * rstd * g[lane + 32] + b[lane + 32];
}

// ---------------- static physics ----------------
__global__ void physics_kernel(const float* __restrict__ W_LTM,
                               const float* __restrict__ V_T0,
                               const float* __restrict__ V_gs,
                               const float* __restrict__ beta_tau,
                               const float* __restrict__ beta_gm,
                               const float* __restrict__ C_ch,
                               const float* __restrict__ gma,
                               const float* __restrict__ alpha,
                               const float* __restrict__ icth,
                               float* __restrict__ ret,
                               float* __restrict__ gate) {
    int idx = blockIdx.x * blockDim.x + threadIdx.x;
    if (idx >= Ll*Hh*DK*DK) return;
    int lh = idx / (DK*DK);
    int l  = lh / Hh;
    float veff = (V_gs[lh] - V_T0[lh]) + W_LTM[idx];
    float sp   = (veff > 20.f) ? veff : log1pf(expf(veff));
    float g_ch = beta_tau[lh] * sp;
    float r    = expf(-g_ch / C_ch[lh]);
    float G    = beta_gm[lh] * sp * (1.f / (1.f + expf(-veff)));
    float sgn  = tanhf(alpha[l] * (g_ch - icth[l]));
    ret[idx]  = r;
    gate[idx] = gma[lh] * sgn * G;
}

// ---------------- sequential recurrence (v-split, half output) -------------
__global__ void __launch_bounds__(256, 1) scan_kernel(const float* __restrict__ qkv,
                                                      const float* __restrict__ ret,
                                                      const float* __restrict__ gate,
                                                      const float* __restrict__ W,
                                                      __half* __restrict__ y) {
    int bh = blockIdx.x >> 1;
    int vh = blockIdx.x & 1;
    int b = bh / Hh, h = bh % Hh;
    int tid = threadIdx.x;
    int v = vh * 32 + (tid >> 3), part = tid & 7, koff = part * 8;

    float r[8], g[8], w[8], f[8];
    {
        int base = (h*DK + v)*DK + koff;
        #pragma unroll
        for (int j = 0; j < 8; j++) {
            r[j] = ret[base + j];
            g[j] = gate[base + j];
            w[j] = W[base + j];
            f[j] = 0.f;
        }
    }

    __shared__ float sbuf[2][192];   // [q(64) | k(64) | v(64)]
    bool loader = tid < 192;
    int which = tid >> 6, lane = tid & 63;
    size_t rowbase = (size_t)b * Tlen * (3*Dm) + h * DK;
    const float* src = qkv + rowbase + which * Dm + lane;
    float pre = loader ? src[0] : 0.f;
    __half* yout = y + (size_t)b * Tlen * Dm + h * DK + v;

    for (int t = 0; t < Tlen; t++) {
        int p = t & 1;
        if (loader) sbuf[p][tid] = pre;
        __syncthreads();
        if (loader && (t + 1 < Tlen))
            pre = src[(size_t)(t + 1) * (3*Dm)];
        float vt = sbuf[p][128 + v];
        const float4* k4 = (const float4*)&sbuf[p][64 + koff];
        const float4* q4 = (const float4*)&sbuf[p][koff];
        float yacc = 0.f;
        #pragma unroll
        for (int j4 = 0; j4 < 2; j4++) {
            float4 kk = k4[j4];
            float4 qq = q4[j4];
            int j = j4 * 4;
            f[j+0] = r[j+0]*f[j+0] + (g[j+0]*vt)*kk.x;
            f[j+1] = r[j+1]*f[j+1] + (g[j+1]*vt)*kk.y;
            f[j+2] = r[j+2]*f[j+2] + (g[j+2]*vt)*kk.z;
            f[j+3] = r[j+3]*f[j+3] + (g[j+3]*vt)*kk.w;
            yacc = fmaf(w[j+0] + f[j+0], qq.x, yacc);
            yacc = fmaf(w[j+1] + f[j+1], qq.y, yacc);
            yacc = fmaf(w[j+2] + f[j+2], qq.z, yacc);
            yacc = fmaf(w[j+3] + f[j+3], qq.w, yacc);
        }
        yacc += __shfl_xor_sync(0xffffffffu, yacc, 1);
        yacc += __shfl_xor_sync(0xffffffffu, yacc, 2);
        yacc += __shfl_xor_sync(0xffffffffu, yacc, 4);
        if (part == 0) yout[(size_t)t * Dm] = __float2half_rn(yacc);
    }
}

// ======== fp16 GEMM v3: ldmatrix + BK=32 + cp.async 4-stage ========
// C = A * B^T (+Res). A:(M,K), B:(N,K) row-major __half. fp32 accumulate.
// SMEM tile layout: 128 m-rows x 32 halves as 64 macro-rows x 128B
// (macro-row mr = m>>1; m's 64B at half (m&1)); 16B chunks XOR-swizzled by mr&7.
#define BKt   32
#define NSTG  4
#define TILE_B  8192                      // bytes per A (or B) stage tile
#define G_SMEM_BYTES (2*NSTG*TILE_B)      // 65536

__device__ __forceinline__ void cpasync16(uint32_t dst_smem, const void* src) {
    asm volatile("cp.async.cg.shared.global [%0], [%1], 16;"
                 :: "r"(dst_smem), "l"(src) : "memory");
}
__device__ __forceinline__ uint32_t smem_u32(const void* p) {
    uint32_t a;
    asm("{ .reg .u64 t; cvta.to.shared.u64 t, %1; cvt.u32.u64 %0, t; }"
        : "=r"(a) : "l"(p));
    return a;
}
__device__ __forceinline__ void ldm_x4(uint32_t& r0, uint32_t& r1,
                                       uint32_t& r2, uint32_t& r3, uint32_t addr) {
    asm volatile("ldmatrix.sync.aligned.m8n8.x4.shared.b16 {%0,%1,%2,%3}, [%4];"
                 : "=r"(r0), "=r"(r1), "=r"(r2), "=r"(r3) : "r"(addr));
}
__device__ __forceinline__ void mma_f16(float c[4],
                                        uint32_t a0, uint32_t a1, uint32_t a2, uint32_t a3,
                                        uint32_t b0, uint32_t b1) {
    asm volatile(
        "mma.sync.aligned.m16n8k16.row.col.f32.f16.f16.f32 "
        "{%0,%1,%2,%3}, {%4,%5,%6,%7}, {%8,%9}, {%0,%1,%2,%3};\n"
        : "+f"(c[0]), "+f"(c[1]), "+f"(c[2]), "+f"(c[3])
        : "r"(a0), "r"(a1), "r"(a2), "r"(a3), "r"(b0), "r"(b1));
}

// issue one 128x32-half tile into stage buffer (base = stage smem addr).
// 512 chunks of 16B; thread handles chunks tid and tid+256.
__device__ __forceinline__ void issue_tile32(uint32_t base,
                                             const __half* __restrict__ Gp,
                                             int K, int k0, int tid) {
    #pragma unroll
    for (int half_i = 0; half_i < 2; half_i++) {
        int c = tid + half_i * 256;
        int mr = c >> 3, kk = c & 7;
        int m = mr * 2 + (kk >> 2);
        int h0 = (kk & 3) * 8;
        uint32_t dst = base + (uint32_t)(mr * 128 + ((kk ^ (mr & 7)) << 4));
        cpasync16(dst, Gp + (size_t)m * K + k0 + h0);
    }
}

__global__ void __launch_bounds__(256, 2) mma_nt_h(int M, int N, int K,
                                                   const __half* __restrict__ A,
                                                   const __half* __restrict__ B,
                                                   const float* __restrict__ Res,
                                                   float* __restrict__ C) {
    extern __shared__ __half smemh[];
    uint32_t sbase = smem_u32(smemh);
    int tid = threadIdx.x;
    int wid = tid >> 5, lane = tid & 31;
    int wm = (wid >> 2) * 64;        // 0 or 64
    int wn = (wid & 3) * 32;         // 0,32,64,96
    int m0 = blockIdx.y * 128, n0 = blockIdx.x * 128;
    int lg = lane >> 2;              // 0..7 (epilogue row group)
    int lq = lane & 3;               // 0..3

    float acc[4][4][4];
    #pragma unroll
    for (int i = 0; i < 4; i++)
        #pragma unroll
        for (int j = 0; j < 4; j++)
            #pragma unroll
            for (int q = 0; q < 4; q++) acc[i][j][q] = 0.f;

    const __half* Agp = A + (size_t)m0 * K;
    const __half* Bgp = B + (size_t)n0 * K;

    // ldmatrix lane geometry
    int lm = lane & 15;              // row within 16
    int lc = lane >> 4;              // 0/1: k-chunk select within a kb half
    int mrA0 = (wm + lm) >> 1;       // macro-row base for A (i adds 8)
    int mrB0 = (wn + lm) >> 1;       // macro-row base for B (jj adds 8)
    int halfbit = lm & 1;
    // swizzled chunk index (same &7 group for all i / jj since they add 8)
    int kpA[2], kpB[2];
    #pragma unroll
    for (int kb = 0; kb < 2; kb++) {
        kpA[kb] = ((halfbit * 4 + kb * 2 + lc) ^ (mrA0 & 7)) << 4;
        kpB[kb] = ((halfbit * 4 + kb * 2 + lc) ^ (mrB0 & 7)) << 4;
    }
    uint32_t aRow = (uint32_t)(mrA0 * 128);
    uint32_t bRow = (uint32_t)(mrB0 * 128);

    int nTiles = K / BKt;

    issue_tile32(sbase + 0*TILE_B, Agp, K, 0*BKt, tid);
    issue_tile32(sbase + (uint32_t)(NSTG + 0)*TILE_B, Bgp, K, 0*BKt, tid);
    asm volatile("cp.async.commit_group;");
    issue_tile32(sbase + 1*TILE_B, Agp, K, 1*BKt, tid);
    issue_tile32(sbase + (uint32_t)(NSTG + 1)*TILE_B, Bgp, K, 1*BKt, tid);
    asm volatile("cp.async.commit_group;");
    issue_tile32(sbase + 2*TILE_B, Agp, K, 2*BKt, tid);
    issue_tile32(sbase + (uint32_t)(NSTG + 2)*TILE_B, Bgp, K, 2*BKt, tid);
    asm volatile("cp.async.commit_group;");

    for (int kt = 0; kt < nTiles; kt++) {
        int s = kt & (NSTG - 1);
        asm volatile("cp.async.wait_group 2;");
        __syncthreads();
        if (kt + 3 < nTiles) {
            int ns = (kt + 3) & (NSTG - 1);
            issue_tile32(sbase + (uint32_t)ns*TILE_B, Agp, K, (kt+3)*BKt, tid);
            issue_tile32(sbase + (uint32_t)(NSTG + ns)*TILE_B, Bgp, K, (kt+3)*BKt, tid);
        }
        asm volatile("cp.async.commit_group;");

        uint32_t aBase = sbase + (uint32_t)s * TILE_B + aRow;
        uint32_t bBase = sbase + (uint32_t)(NSTG + s) * TILE_B + bRow;

        #pragma unroll
        for (int kb = 0; kb < 2; kb++) {
            uint32_t af[4][4];
            #pragma unroll
            for (int i = 0; i < 4; i++)
                ldm_x4(af[i][0], af[i][1], af[i][2], af[i][3],
                       aBase + (uint32_t)(i * 1024) + kpA[kb]);
            uint32_t bf[4][2];
            #pragma unroll
            for (int jj = 0; jj < 2; jj++) {
                uint32_t r0, r1, r2, r3;
                ldm_x4(r0, r1, r2, r3, bBase + (uint32_t)(jj * 1024) + kpB[kb]);
                bf[jj*2][0] = r0; bf[jj*2+1][0] = r1;
                bf[jj*2][1] = r2; bf[jj*2+1][1] = r3;
            }
            #pragma unroll
            for (int i = 0; i < 4; i++)
                #pragma unroll
                for (int j = 0; j < 4; j++)
                    mma_f16(acc[i][j], af[i][0], af[i][1], af[i][2], af[i][3],
                            bf[j][0], bf[j][1]);
        }
        __syncthreads();
    }

    // epilogue
    #pragma unroll
    for (int i = 0; i < 4; i++) {
        int row = m0 + wm + i*16 + lg;
        #pragma unroll
        for (int j = 0; j < 4; j++) {
            int col = n0 + wn + j*8 + 2*lq;
            size_t o0 = (size_t)row * N + col;
            size_t o1 = (size_t)(row + 8) * N + col;
            float2 v0 = make_float2(acc[i][j][0], acc[i][j][1]);
            float2 v1 = make_float2(acc[i][j][2], acc[i][j][3]);
            if (Res) {
                float2 q0 = *(const float2*)(Res + o0);
                float2 q1 = *(const float2*)(Res + o1);
                v0.x += q0.x; v0.y += q0.y;
                v1.x += q1.x; v1.y += q1.y;
            }
            *(float2*)(C + o0) = v0;
            *(float2*)(C + o1) = v1;
        }
    }
}

// ---------------- launch ----------------
extern "C" void kernel_launch(void* const* d_in, const int* in_sizes, int n_in,
                              void* d_out, int out_size) {
    const int*   ids      = (const int*)  d_in[0];
    const float* embedW   = (const float*)d_in[2];
    const float* conv_w   = (const float*)d_in[3];
    const float* conv_b   = (const float*)d_in[4];
    const float* Wqkv     = (const float*)d_in[5];
    const float* Wo       = (const float*)d_in[6];
    const float* W_LTM    = (const float*)d_in[7];
    const float* V_T0     = (const float*)d_in[8];
    const float* V_gs     = (const float*)d_in[9];
    const float* beta_tau = (const float*)d_in[10];
    const float* beta_gm  = (const float*)d_in[11];
    const float* C_ch     = (const float*)d_in[12];
    const float* gma      = (const float*)d_in[13];
    const float* alpha    = (const float*)d_in[14];
    const float* icth     = (const float*)d_in[15];
    const float* ln1_g    = (const float*)d_in[16];
    const float* ln1_b    = (const float*)d_in[17];
    const float* lnk_g    = (const float*)d_in[18];
    const float* lnk_b    = (const float*)d_in[19];
    const float* lnf_g    = (const float*)d_in[20];
    const float* lnf_b    = (const float*)d_in[21];
    const float* headW    = (const float*)d_in[22];
    float* out = (float*)d_out;

    float *x, *h, *qkv, *ret, *gate;
    __half *h2h, *yh, *hh, *wqh, *woh, *whh;
    cudaGetSymbolAddress((void**)&x,    g_x);
    cudaGetSymbolAddress((void**)&h,    g_h);
    cudaGetSymbolAddress((void**)&h2h,  g_h2h);
    cudaGetSymbolAddress((void**)&qkv,  g_qkv);
    cudaGetSymbolAddress((void**)&yh,   g_yh);
    cudaGetSymbolAddress((void**)&hh,   g_hh);
    cudaGetSymbolAddress((void**)&ret,  g_ret);
    cudaGetSymbolAddress((void**)&gate, g_gate);
    cudaGetSymbolAddress((void**)&wqh,  g_wqh);
    cudaGetSymbolAddress((void**)&woh,  g_woh);
    cudaGetSymbolAddress((void**)&whh,  g_whh);

    cudaFuncSetAttribute(mma_nt_h, cudaFuncAttributeMaxDynamicSharedMemorySize,
                         G_SMEM_BYTES);

    tohalf_kernel<<<(Ll*3*Dm*Dm)/1024, 256>>>(Wqkv,  wqh);
    tohalf_kernel<<<(Ll*Dm*Dm)/1024,   256>>>(Wo,    woh);
    tohalf_kernel<<<(Vv*Dm)/1024,      256>>>(headW, whh);

    embed_kernel<<<NROW, 256>>>(ids, embedW, x);
    {
        int n = Ll*Hh*DK*DK;
        physics_kernel<<<(n + 255)/256, 256>>>(W_LTM, V_T0, V_gs, beta_tau, beta_gm,
                                               C_ch, gma, alpha, icth, ret, gate);
    }

    for (int l = 0; l < Ll; l++) {
        ln_kernel<<<NROW, 256>>>(x, ln1_g + l*Dm, ln1_b + l*Dm, h);
        conv_kernel<<<NROW, 256>>>(h, conv_w + l*3*Dm, conv_b + l*Dm, h2h);

        dim3 gq((3*Dm)/128, NROW/128);
        mma_nt_h<<<gq, 256, G_SMEM_BYTES>>>(NROW, 3*Dm, Dm, h2h,
                                            wqh + (size_t)l*3*Dm*Dm, nullptr, qkv);

        kln_kernel<<<NROW, 512>>>(qkv, lnk_g + l*DK, lnk_b + l*DK);

        scan_kernel<<<Bb*Hh*2, 256>>>(qkv,
                                      ret  + (size_t)l*Hh*DK*DK,
                                      gate + (size_t)l*Hh*DK*DK,
                                      W_LTM + (size_t)l*Hh*DK*DK,
                                      yh);

        dim3 go(Dm/128, NROW/128);
        mma_nt_h<<<go, 256, G_SMEM_BYTES>>>(NROW, Dm, Dm, yh,
                                            woh + (size_t)l*Dm*Dm, x, x);
    }

    lnh_kernel<<<NROW, 256>>>(x, lnf_g, lnf_b, hh);
    dim3 gh(Vv/128, NROW/128);
    mma_nt_h<<<gh, 256, G_SMEM_BYTES>>>(NROW, Vv, Dm, hh, whh, nullptr, out);
}

// round 8
// speedup vs baseline: 5.7491x; 1.7518x over previous
#include <cuda_runtime.h>
#include <cuda_fp16.h>
#include <math.h>
#include <stdint.h>

// ---------------- problem constants ----------------
#define Dm    1024
#define Tlen  2048
#define Bb    4
#define Hh    16
#define DK    64
#define Ll    2
#define Vv    8192
#define NROW  (Bb*Tlen)          // 8192 token rows

// ---------------- scratch (device globals; no allocation allowed) ----------
__device__ float  g_x  [NROW*Dm];        // residual stream (fp32)
__device__ float  g_h  [NROW*Dm];        // ln output (fp32, conv input)
__device__ __half g_h2h[NROW*Dm];        // conv output (half, A of qkv GEMM)
__device__ float  g_qkv[NROW*3*Dm];      // fp32
__device__ __half g_yh [NROW*Dm];        // scan output (half, A of Wo GEMM)
__device__ __half g_hh [NROW*Dm];        // final ln output (half, A of head GEMM)
__device__ float  g_ret [Ll*Hh*DK*DK];
__device__ float  g_gate[Ll*Hh*DK*DK];
// half weights
__device__ __half g_wqh[Ll*3*Dm*Dm];
__device__ __half g_woh[Ll*Dm*Dm];
__device__ __half g_whh[Vv*Dm];

// ---------------- fp32 -> fp16 weight conversion ----------------
__global__ void __launch_bounds__(256) tohalf_kernel(const float* __restrict__ s,
                                                     __half* __restrict__ d) {
    int i = (blockIdx.x * blockDim.x + threadIdx.x) * 4;
    float4 v = *(const float4*)(s + i);
    *(__half2*)(d + i)     = __floats2half2_rn(v.x, v.y);
    *(__half2*)(d + i + 2) = __floats2half2_rn(v.z, v.w);
}

// ---------------- embedding gather ----------------
__global__ void embed_kernel(const int* __restrict__ ids,
                             const float* __restrict__ W,
                             float* __restrict__ x) {
    int row = blockIdx.x;
    int id  = ids[row];
    const float4* src = (const float4*)(W + (size_t)id * Dm);
    float4* dst = (float4*)(x + (size_t)row * Dm);
    for (int i = threadIdx.x; i < Dm/4; i += blockDim.x) dst[i] = src[i];
}

// ---------------- block reduce helper (blockDim == 256) ----------------
__device__ __forceinline__ float blockReduceSum(float v, float* sh) {
    #pragma unroll
    for (int o = 16; o; o >>= 1) v += __shfl_xor_sync(0xffffffffu, v, o);
    if ((threadIdx.x & 31) == 0) sh[threadIdx.x >> 5] = v;
    __syncthreads();
    float tot = 0.f;
    #pragma unroll
    for (int i = 0; i < 8; i++) tot += sh[i];
    __syncthreads();
    return tot;
}

// ---------------- layernorm (fp32 out) ----------------
__global__ void __launch_bounds__(256) ln_kernel(const float* __restrict__ x,
                                                 const float* __restrict__ g,
                                                 const float* __restrict__ b,
                                                 float* __restrict__ out) {
    __shared__ float sh[8];
    int row = blockIdx.x;
    const float* xr = x + (size_t)row * Dm;
    int i0 = threadIdx.x * 4;
    float4 xv = *(const float4*)(xr + i0);
    float s = xv.x + xv.y + xv.z + xv.w;
    float mean = blockReduceSum(s, sh) * (1.f / Dm);
    float d0 = xv.x - mean, d1 = xv.y - mean, d2 = xv.z - mean, d3 = xv.w - mean;
    float sq = d0*d0 + d1*d1 + d2*d2 + d3*d3;
    float var = blockReduceSum(sq, sh) * (1.f / Dm);
    float rstd = rsqrtf(var + 1e-5f);
    float4 gv = *(const float4*)(g + i0);
    float4 bv = *(const float4*)(b + i0);
    float4 ov;
    ov.x = d0 * rstd * gv.x + bv.x;
    ov.y = d1 * rstd * gv.y + bv.y;
    ov.z = d2 * rstd * gv.z + bv.z;
    ov.w = d3 * rstd * gv.w + bv.w;
    *(float4*)(out + (size_t)row * Dm + i0) = ov;
}

// ---------------- layernorm (half out, for head GEMM A) ----------------
__global__ void __launch_bounds__(256) lnh_kernel(const float* __restrict__ x,
                                                  const float* __restrict__ g,
                                                  const float* __restrict__ b,
                                                  __half* __restrict__ out) {
    __shared__ float sh[8];
    int row = blockIdx.x;
    const float* xr = x + (size_t)row * Dm;
    int i0 = threadIdx.x * 4;
    float4 xv = *(const float4*)(xr + i0);
    float s = xv.x + xv.y + xv.z + xv.w;
    float mean = blockReduceSum(s, sh) * (1.f / Dm);
    float d0 = xv.x - mean, d1 = xv.y - mean, d2 = xv.z - mean, d3 = xv.w - mean;
    float sq = d0*d0 + d1*d1 + d2*d2 + d3*d3;
    float var = blockReduceSum(sq, sh) * (1.f / Dm);
    float rstd = rsqrtf(var + 1e-5f);
    float4 gv = *(const float4*)(g + i0);
    float4 bv = *(const float4*)(b + i0);
    *(__half2*)(out + (size_t)row * Dm + i0) =
        __floats2half2_rn(d0 * rstd * gv.x + bv.x, d1 * rstd * gv.y + bv.y);
    *(__half2*)(out + (size_t)row * Dm + i0 + 2) =
        __floats2half2_rn(d2 * rstd * gv.z + bv.z, d3 * rstd * gv.w + bv.w);
}

// ---------------- causal depthwise conv (half out) ----------------
__global__ void __launch_bounds__(256) conv_kernel(const float* __restrict__ h,
                                                   const float* __restrict__ cw,
                                                   const float* __restrict__ cb,
                                                   __half* __restrict__ out) {
    int row = blockIdx.x;
    int t = row % Tlen;
    const float* h0 = h + (size_t)row * Dm;
    int i = threadIdx.x * 4;
    float4 cur = *(const float4*)(h0 + i);
    float4 w0 = *(const float4*)(cw + 0*Dm + i);
    float4 w1 = *(const float4*)(cw + 1*Dm + i);
    float4 w2 = *(const float4*)(cw + 2*Dm + i);
    float4 bb = *(const float4*)(cb + i);
    float4 z = make_float4(0.f, 0.f, 0.f, 0.f);
    float4 p1 = (t >= 1) ? *(const float4*)(h0 - Dm + i) : z;
    float4 p2 = (t >= 2) ? *(const float4*)(h0 - 2*Dm + i) : z;
    float ox = cur.x + w0.x*p2.x + w1.x*p1.x + w2.x*cur.x + bb.x;
    float oy = cur.y + w0.y*p2.y + w1.y*p1.y + w2.y*cur.y + bb.y;
    float oz = cur.z + w0.z*p2.z + w1.z*p1.z + w2.z*cur.z + bb.z;
    float ow = cur.w + w0.w*p2.w + w1.w*p1.w + w2.w*cur.w + bb.w;
    *(__half2*)(out + (size_t)row * Dm + i)     = __floats2half2_rn(ox, oy);
    *(__half2*)(out + (size_t)row * Dm + i + 2) = __floats2half2_rn(oz, ow);
}

// ---------------- per-head k layernorm ----------------
__global__ void __launch_bounds__(512) kln_kernel(float* __restrict__ qkv,
                                                  const float* __restrict__ g,
                                                  const float* __restrict__ b) {
    int row = blockIdx.x;
    int wid = threadIdx.x >> 5, lane = threadIdx.x & 31;
    float* k = qkv + (size_t)row * (3*Dm) + Dm + wid * DK;
    float x0 = k[lane], x1 = k[lane + 32];
    float s = x0 + x1;
    #pragma unroll
    for (int o = 16; o; o >>= 1) s += __shfl_xor_sync(0xffffffffu, s, o);
    float mean = s * (1.f / DK);
    float d0 = x0 - mean, d1 = x1 - mean;
    float q = d0*d0 + d1*d1;
    #pragma unroll
    for (int o = 16; o; o >>= 1) q += __shfl_xor_sync(0xffffffffu, q, o);
    float rstd = rsqrtf(q * (1.f / DK) + 1e-5f);
    k[lane]      = d0 * rstd * g[lane]      + b[lane];
    k[lane + 32] = d1 * rstd * g[lane + 32] + b[lane + 32];
}

// ---------------- static physics ----------------
__global__ void physics_kernel(const float* __restrict__ W_LTM,
                               const float* __restrict__ V_T0,
                               const float* __restrict__ V_gs,
                               const float* __restrict__ beta_tau,
                               const float* __restrict__ beta_gm,
                               const float* __restrict__ C_ch,
                               const float* __restrict__ gma,
                               const float* __restrict__ alpha,
                               const float* __restrict__ icth,
                               float* __restrict__ ret,
                               float* __restrict__ gate) {
    int idx = blockIdx.x * blockDim.x + threadIdx.x;
    if (idx >= Ll*Hh*DK*DK) return;
    int lh = idx / (DK*DK);
    int l  = lh / Hh;
    float veff = (V_gs[lh] - V_T0[lh]) + W_LTM[idx];
    float sp   = (veff > 20.f) ? veff : log1pf(expf(veff));
    float g_ch = beta_tau[lh] * sp;
    float r    = expf(-g_ch / C_ch[lh]);
    float G    = beta_gm[lh] * sp * (1.f / (1.f + expf(-veff)));
    float sgn  = tanhf(alpha[l] * (g_ch - icth[l]));
    ret[idx]  = r;
    gate[idx] = gma[lh] * sgn * G;
}

// ---------------- sequential recurrence: 4-step blocked, deep prefetch -----
// 128 blocks (bh x v-half). One barrier per 4 timesteps; loaders keep a
// 4-entry register prefetch window, so ~4 compute-steps of latency is hidden.
__global__ void __launch_bounds__(256, 1) scan_kernel(const float* __restrict__ qkv,
                                                      const float* __restrict__ ret,
                                                      const float* __restrict__ gate,
                                                      const float* __restrict__ W,
                                                      __half* __restrict__ y) {
    int bh = blockIdx.x >> 1;
    int vh = blockIdx.x & 1;
    int b = bh / Hh, h = bh % Hh;
    int tid = threadIdx.x;
    int v = vh * 32 + (tid >> 3), part = tid & 7, koff = part * 8;

    float r[8], g[8], w[8], f[8];
    {
        int base = (h*DK + v)*DK + koff;
        #pragma unroll
        for (int j = 0; j < 8; j++) {
            r[j] = ret[base + j];
            g[j] = gate[base + j];
            w[j] = W[base + j];
            f[j] = 0.f;
        }
    }

    __shared__ float sbuf[2][4][192];   // [buf][step][q|k|v]
    bool loader = tid < 192;
    int which = tid >> 6, lane = tid & 63;
    size_t rowbase = (size_t)b * Tlen * (3*Dm) + h * DK;
    const float* src = qkv + rowbase + which * Dm + lane;
    float pre[4];
    if (loader) {
        #pragma unroll
        for (int j = 0; j < 4; j++) pre[j] = src[(size_t)j * (3*Dm)];
    }
    __half* yout = y + (size_t)b * Tlen * Dm + h * DK + v;

    const int NB = Tlen / 4;
    for (int tb = 0; tb < NB; tb++) {
        int p = tb & 1;
        if (loader) {
            #pragma unroll
            for (int j = 0; j < 4; j++) sbuf[p][j][tid] = pre[j];
        }
        __syncthreads();
        if (loader && tb + 1 < NB) {
            size_t tn = (size_t)(tb * 4 + 4);
            #pragma unroll
            for (int j = 0; j < 4; j++)
                pre[j] = src[(tn + j) * (3*Dm)];
        }
        #pragma unroll
        for (int st = 0; st < 4; st++) {
            float vt = sbuf[p][st][128 + v];
            const float4* k4 = (const float4*)&sbuf[p][st][64 + koff];
            const float4* q4 = (const float4*)&sbuf[p][st][koff];
            float yacc = 0.f;
            #pragma unroll
            for (int j4 = 0; j4 < 2; j4++) {
                float4 kk = k4[j4];
                float4 qq = q4[j4];
                int j = j4 * 4;
                f[j+0] = r[j+0]*f[j+0] + (g[j+0]*vt)*kk.x;
                f[j+1] = r[j+1]*f[j+1] + (g[j+1]*vt)*kk.y;
                f[j+2] = r[j+2]*f[j+2] + (g[j+2]*vt)*kk.z;
                f[j+3] = r[j+3]*f[j+3] + (g[j+3]*vt)*kk.w;
                yacc = fmaf(w[j+0] + f[j+0], qq.x, yacc);
                yacc = fmaf(w[j+1] + f[j+1], qq.y, yacc);
                yacc = fmaf(w[j+2] + f[j+2], qq.z, yacc);
                yacc = fmaf(w[j+3] + f[j+3], qq.w, yacc);
            }
            yacc += __shfl_xor_sync(0xffffffffu, yacc, 1);
            yacc += __shfl_xor_sync(0xffffffffu, yacc, 2);
            yacc += __shfl_xor_sync(0xffffffffu, yacc, 4);
            if (part == 0) yout[(size_t)(tb * 4 + st) * Dm] = __float2half_rn(yacc);
        }
    }
}

// ======== fp16 GEMM v4: 64x64 warp tiles, ldmatrix, BK=32, cp.async ========
// C = A * B^T (+Res). A:(M,K), B:(N,K) row-major __half. fp32 accumulate.
// CTA tile 128x128, 4 warps (2x2 grid of 64x64), 128 threads, 2 CTA/SM.
// SMEM tile layout unchanged: 64 macro-rows x 128B, 16B chunks XOR-swizzled.
#define BKt   32
#define NSTG  4
#define TILE_B  8192                      // bytes per A (or B) stage tile
#define G_SMEM_BYTES (2*NSTG*TILE_B)      // 65536

__device__ __forceinline__ void cpasync16(uint32_t dst_smem, const void* src) {
    asm volatile("cp.async.cg.shared.global [%0], [%1], 16;"
                 :: "r"(dst_smem), "l"(src) : "memory");
}
__device__ __forceinline__ uint32_t smem_u32(const void* p) {
    uint32_t a;
    asm("{ .reg .u64 t; cvta.to.shared.u64 t, %1; cvt.u32.u64 %0, t; }"
        : "=r"(a) : "l"(p));
    return a;
}
__device__ __forceinline__ void ldm_x4(uint32_t& r0, uint32_t& r1,
                                       uint32_t& r2, uint32_t& r3, uint32_t addr) {
    asm volatile("ldmatrix.sync.aligned.m8n8.x4.shared.b16 {%0,%1,%2,%3}, [%4];"
                 : "=r"(r0), "=r"(r1), "=r"(r2), "=r"(r3) : "r"(addr));
}
__device__ __forceinline__ void mma_f16(float c[4],
                                        uint32_t a0, uint32_t a1, uint32_t a2, uint32_t a3,
                                        uint32_t b0, uint32_t b1) {
    asm volatile(
        "mma.sync.aligned.m16n8k16.row.col.f32.f16.f16.f32 "
        "{%0,%1,%2,%3}, {%4,%5,%6,%7}, {%8,%9}, {%0,%1,%2,%3};\n"
        : "+f"(c[0]), "+f"(c[1]), "+f"(c[2]), "+f"(c[3])
        : "r"(a0), "r"(a1), "r"(a2), "r"(a3), "r"(b0), "r"(b1));
}

// issue one 128x32-half tile into a stage buffer (128 threads: 4 chunks each)
__device__ __forceinline__ void issue_tile32(uint32_t base,
                                             const __half* __restrict__ Gp,
                                             int K, int k0, int tid) {
    #pragma unroll
    for (int hi = 0; hi < 4; hi++) {
        int c = tid + hi * 128;
        int mr = c >> 3, kk = c & 7;
        int m = mr * 2 + (kk >> 2);
        int h0 = (kk & 3) * 8;
        uint32_t dst = base + (uint32_t)(mr * 128 + ((kk ^ (mr & 7)) << 4));
        cpasync16(dst, Gp + (size_t)m * K + k0 + h0);
    }
}

__global__ void __launch_bounds__(128, 2) mma_nt_h(int M, int N, int K,
                                                   const __half* __restrict__ A,
                                                   const __half* __restrict__ B,
                                                   const float* __restrict__ Res,
                                                   float* __restrict__ C) {
    extern __shared__ __half smemh[];
    uint32_t sbase = smem_u32(smemh);
    int tid = threadIdx.x;
    int wid = tid >> 5, lane = tid & 31;
    int wm = (wid & 1) * 64;
    int wn = (wid >> 1) * 64;
    int m0 = blockIdx.y * 128, n0 = blockIdx.x * 128;
    int lg = lane >> 2;              // 0..7 (epilogue row group)
    int lq = lane & 3;               // 0..3

    float acc[4][8][4];
    #pragma unroll
    for (int i = 0; i < 4; i++)
        #pragma unroll
        for (int j = 0; j < 8; j++)
            #pragma unroll
            for (int q = 0; q < 4; q++) acc[i][j][q] = 0.f;

    const __half* Agp = A + (size_t)m0 * K;
    const __half* Bgp = B + (size_t)n0 * K;

    // ldmatrix lane geometry
    int lm = lane & 15;
    int lc = lane >> 4;
    int mrA0 = (wm + lm) >> 1;
    int mrB0 = (wn + lm) >> 1;
    int halfbit = lm & 1;
    int kpA[2], kpB[2];
    #pragma unroll
    for (int kb = 0; kb < 2; kb++) {
        kpA[kb] = ((halfbit * 4 + kb * 2 + lc) ^ (mrA0 & 7)) << 4;
        kpB[kb] = ((halfbit * 4 + kb * 2 + lc) ^ (mrB0 & 7)) << 4;
    }
    uint32_t aRow = (uint32_t)(mrA0 * 128);
    uint32_t bRow = (uint32_t)(mrB0 * 128);

    int nTiles = K / BKt;

    issue_tile32(sbase + 0*TILE_B, Agp, K, 0*BKt, tid);
    issue_tile32(sbase + (uint32_t)(NSTG + 0)*TILE_B, Bgp, K, 0*BKt, tid);
    asm volatile("cp.async.commit_group;");
    issue_tile32(sbase + 1*TILE_B, Agp, K, 1*BKt, tid);
    issue_tile32(sbase + (uint32_t)(NSTG + 1)*TILE_B, Bgp, K, 1*BKt, tid);
    asm volatile("cp.async.commit_group;");
    issue_tile32(sbase + 2*TILE_B, Agp, K, 2*BKt, tid);
    issue_tile32(sbase + (uint32_t)(NSTG + 2)*TILE_B, Bgp, K, 2*BKt, tid);
    asm volatile("cp.async.commit_group;");

    for (int kt = 0; kt < nTiles; kt++) {
        int s = kt & (NSTG - 1);
        asm volatile("cp.async.wait_group 2;");
        __syncthreads();   // also orders: iter kt-1 reads precede refill below
        if (kt + 3 < nTiles) {
            int ns = (kt + 3) & (NSTG - 1);
            issue_tile32(sbase + (uint32_t)ns*TILE_B, Agp, K, (kt+3)*BKt, tid);
            issue_tile32(sbase + (uint32_t)(NSTG + ns)*TILE_B, Bgp, K, (kt+3)*BKt, tid);
        }
        asm volatile("cp.async.commit_group;");

        uint32_t aBase = sbase + (uint32_t)s * TILE_B + aRow;
        uint32_t bBase = sbase + (uint32_t)(NSTG + s) * TILE_B + bRow;

        #pragma unroll
        for (int kb = 0; kb < 2; kb++) {
            uint32_t af[4][4];
            #pragma unroll
            for (int i = 0; i < 4; i++)
                ldm_x4(af[i][0], af[i][1], af[i][2], af[i][3],
                       aBase + (uint32_t)(i * 1024) + kpA[kb]);
            uint32_t bf[8][2];
            #pragma unroll
            for (int jj = 0; jj < 4; jj++) {
                uint32_t r0, r1, r2, r3;
                ldm_x4(r0, r1, r2, r3, bBase + (uint32_t)(jj * 1024) + kpB[kb]);
                bf[jj*2][0] = r0; bf[jj*2+1][0] = r1;
                bf[jj*2][1] = r2; bf[jj*2+1][1] = r3;
            }
            #pragma unroll
            for (int i = 0; i < 4; i++)
                #pragma unroll
                for (int j = 0; j < 8; j++)
                    mma_f16(acc[i][j], af[i][0], af[i][1], af[i][2], af[i][3],
                            bf[j][0], bf[j][1]);
        }
    }

    // epilogue
    #pragma unroll
    for (int i = 0; i < 4; i++) {
        int row = m0 + wm + i*16 + lg;
        #pragma unroll
        for (int j = 0; j < 8; j++) {
            int col = n0 + wn + j*8 + 2*lq;
            size_t o0 = (size_t)row * N + col;
            size_t o1 = (size_t)(row + 8) * N + col;
            float2 v0 = make_float2(acc[i][j][0], acc[i][j][1]);
            float2 v1 = make_float2(acc[i][j][2], acc[i][j][3]);
            if (Res) {
                float2 q0 = *(const float2*)(Res + o0);
                float2 q1 = *(const float2*)(Res + o1);
                v0.x += q0.x; v0.y += q0.y;
                v1.x += q1.x; v1.y += q1.y;
            }
            *(float2*)(C + o0) = v0;
            *(float2*)(C + o1) = v1;
        }
    }
}

// ---------------- launch ----------------
extern "C" void kernel_launch(void* const* d_in, const int* in_sizes, int n_in,
                              void* d_out, int out_size) {
    const int*   ids      = (const int*)  d_in[0];
    const float* embedW   = (const float*)d_in[2];
    const float* conv_w   = (const float*)d_in[3];
    const float* conv_b   = (const float*)d_in[4];
    const float* Wqkv     = (const float*)d_in[5];
    const float* Wo       = (const float*)d_in[6];
    const float* W_LTM    = (const float*)d_in[7];
    const float* V_T0     = (const float*)d_in[8];
    const float* V_gs     = (const float*)d_in[9];
    const float* beta_tau = (const float*)d_in[10];
    const float* beta_gm  = (const float*)d_in[11];
    const float* C_ch     = (const float*)d_in[12];
    const float* gma      = (const float*)d_in[13];
    const float* alpha    = (const float*)d_in[14];
    const float* icth     = (const float*)d_in[15];
    const float* ln1_g    = (const float*)d_in[16];
    const float* ln1_b    = (const float*)d_in[17];
    const float* lnk_g    = (const float*)d_in[18];
    const float* lnk_b    = (const float*)d_in[19];
    const float* lnf_g    = (const float*)d_in[20];
    const float* lnf_b    = (const float*)d_in[21];
    const float* headW    = (const float*)d_in[22];
    float* out = (float*)d_out;

    float *x, *h, *qkv, *ret, *gate;
    __half *h2h, *yh, *hh, *wqh, *woh, *whh;
    cudaGetSymbolAddress((void**)&x,    g_x);
    cudaGetSymbolAddress((void**)&h,    g_h);
    cudaGetSymbolAddress((void**)&h2h,  g_h2h);
    cudaGetSymbolAddress((void**)&qkv,  g_qkv);
    cudaGetSymbolAddress((void**)&yh,   g_yh);
    cudaGetSymbolAddress((void**)&hh,   g_hh);
    cudaGetSymbolAddress((void**)&ret,  g_ret);
    cudaGetSymbolAddress((void**)&gate, g_gate);
    cudaGetSymbolAddress((void**)&wqh,  g_wqh);
    cudaGetSymbolAddress((void**)&woh,  g_woh);
    cudaGetSymbolAddress((void**)&whh,  g_whh);

    cudaFuncSetAttribute(mma_nt_h, cudaFuncAttributeMaxDynamicSharedMemorySize,
                         G_SMEM_BYTES);

    tohalf_kernel<<<(Ll*3*Dm*Dm)/1024, 256>>>(Wqkv,  wqh);
    tohalf_kernel<<<(Ll*Dm*Dm)/1024,   256>>>(Wo,    woh);
    tohalf_kernel<<<(Vv*Dm)/1024,      256>>>(headW, whh);

    embed_kernel<<<NROW, 256>>>(ids, embedW, x);
    {
        int n = Ll*Hh*DK*DK;
        physics_kernel<<<(n + 255)/256, 256>>>(W_LTM, V_T0, V_gs, beta_tau, beta_gm,
                                               C_ch, gma, alpha, icth, ret, gate);
    }

    for (int l = 0; l < Ll; l++) {
        ln_kernel<<<NROW, 256>>>(x, ln1_g + l*Dm, ln1_b + l*Dm, h);
        conv_kernel<<<NROW, 256>>>(h, conv_w + l*3*Dm, conv_b + l*Dm, h2h);

        dim3 gq((3*Dm)/128, NROW/128);
        mma_nt_h<<<gq, 128, G_SMEM_BYTES>>>(NROW, 3*Dm, Dm, h2h,
                                            wqh + (size_t)l*3*Dm*Dm, nullptr, qkv);

        kln_kernel<<<NROW, 512>>>(qkv, lnk_g + l*DK, lnk_b + l*DK);

        scan_kernel<<<Bb*Hh*2, 256>>>(qkv,
                                      ret  + (size_t)l*Hh*DK*DK,
                                      gate + (size_t)l*Hh*DK*DK,
                                      W_LTM + (size_t)l*Hh*DK*DK,
                                      yh);

        dim3 go(Dm/128, NROW/128);
        mma_nt_h<<<go, 128, G_SMEM_BYTES>>>(NROW, Dm, Dm, yh,
                                            woh + (size_t)l*Dm*Dm, x, x);
    }

    lnh_kernel<<<NROW, 256>>>(x, lnf_g, lnf_b, hh);
    dim3 gh(Vv/128, NROW/128);
    mma_nt_h<<<gh, 128, G_SMEM_BYTES>>>(NROW, Vv, Dm, hh, whh, nullptr, out);
}

// round 9
// speedup vs baseline: 6.1573x; 1.0710x over previous
#include <cuda_runtime.h>
#include <cuda_fp16.h>
#include <math.h>
#include <stdint.h>

// ---------------- problem constants ----------------
#define Dm    1024
#define Tlen  2048
#define Bb    4
#define Hh    16
#define DK    64
#define Ll    2
#define Vv    8192
#define NROW  (Bb*Tlen)          // 8192 token rows

// ---------------- scratch (device globals; no allocation allowed) ----------
__device__ float  g_x  [NROW*Dm];        // residual stream (fp32)
__device__ float  g_h  [NROW*Dm];        // ln output (fp32, conv input)
__device__ __half g_h2h[NROW*Dm];        // conv output (half, A of qkv GEMM)
__device__ float  g_qkv[NROW*3*Dm];      // fp32
__device__ __half g_yh [NROW*Dm];        // scan output (half, A of Wo GEMM)
__device__ __half g_hh [NROW*Dm];        // final ln output (half, A of head GEMM)
__device__ float  g_ret [Ll*Hh*DK*DK];
__device__ float  g_gate[Ll*Hh*DK*DK];
// half weights
__device__ __half g_wqh[Ll*3*Dm*Dm];
__device__ __half g_woh[Ll*Dm*Dm];
__device__ __half g_whh[Vv*Dm];

// ---------------- fp32 -> fp16 weight conversion ----------------
__global__ void __launch_bounds__(256) tohalf_kernel(const float* __restrict__ s,
                                                     __half* __restrict__ d) {
    int i = (blockIdx.x * blockDim.x + threadIdx.x) * 4;
    float4 v = *(const float4*)(s + i);
    *(__half2*)(d + i)     = __floats2half2_rn(v.x, v.y);
    *(__half2*)(d + i + 2) = __floats2half2_rn(v.z, v.w);
}

// ---------------- embedding gather ----------------
__global__ void embed_kernel(const int* __restrict__ ids,
                             const float* __restrict__ W,
                             float* __restrict__ x) {
    int row = blockIdx.x;
    int id  = ids[row];
    const float4* src = (const float4*)(W + (size_t)id * Dm);
    float4* dst = (float4*)(x + (size_t)row * Dm);
    for (int i = threadIdx.x; i < Dm/4; i += blockDim.x) dst[i] = src[i];
}

// ---------------- block reduce helper (blockDim == 256) ----------------
__device__ __forceinline__ float blockReduceSum(float v, float* sh) {
    #pragma unroll
    for (int o = 16; o; o >>= 1) v += __shfl_xor_sync(0xffffffffu, v, o);
    if ((threadIdx.x & 31) == 0) sh[threadIdx.x >> 5] = v;
    __syncthreads();
    float tot = 0.f;
    #pragma unroll
    for (int i = 0; i < 8; i++) tot += sh[i];
    __syncthreads();
    return tot;
}

// ---------------- layernorm (fp32 out) ----------------
__global__ void __launch_bounds__(256) ln_kernel(const float* __restrict__ x,
                                                 const float* __restrict__ g,
                                                 const float* __restrict__ b,
                                                 float* __restrict__ out) {
    __shared__ float sh[8];
    int row = blockIdx.x;
    const float* xr = x + (size_t)row * Dm;
    int i0 = threadIdx.x * 4;
    float4 xv = *(const float4*)(xr + i0);
    float s = xv.x + xv.y + xv.z + xv.w;
    float mean = blockReduceSum(s, sh) * (1.f / Dm);
    float d0 = xv.x - mean, d1 = xv.y - mean, d2 = xv.z - mean, d3 = xv.w - mean;
    float sq = d0*d0 + d1*d1 + d2*d2 + d3*d3;
    float var = blockReduceSum(sq, sh) * (1.f / Dm);
    float rstd = rsqrtf(var + 1e-5f);
    float4 gv = *(const float4*)(g + i0);
    float4 bv = *(const float4*)(b + i0);
    float4 ov;
    ov.x = d0 * rstd * gv.x + bv.x;
    ov.y = d1 * rstd * gv.y + bv.y;
    ov.z = d2 * rstd * gv.z + bv.z;
    ov.w = d3 * rstd * gv.w + bv.w;
    *(float4*)(out + (size_t)row * Dm + i0) = ov;
}

// ---------------- layernorm (half out, for head GEMM A) ----------------
__global__ void __launch_bounds__(256) lnh_kernel(const float* __restrict__ x,
                                                  const float* __restrict__ g,
                                                  const float* __restrict__ b,
                                                  __half* __restrict__ out) {
    __shared__ float sh[8];
    int row = blockIdx.x;
    const float* xr = x + (size_t)row * Dm;
    int i0 = threadIdx.x * 4;
    float4 xv = *(const float4*)(xr + i0);
    float s = xv.x + xv.y + xv.z + xv.w;
    float mean = blockReduceSum(s, sh) * (1.f / Dm);
    float d0 = xv.x - mean, d1 = xv.y - mean, d2 = xv.z - mean, d3 = xv.w - mean;
    float sq = d0*d0 + d1*d1 + d2*d2 + d3*d3;
    float var = blockReduceSum(sq, sh) * (1.f / Dm);
    float rstd = rsqrtf(var + 1e-5f);
    float4 gv = *(const float4*)(g + i0);
    float4 bv = *(const float4*)(b + i0);
    *(__half2*)(out + (size_t)row * Dm + i0) =
        __floats2half2_rn(d0 * rstd * gv.x + bv.x, d1 * rstd * gv.y + bv.y);
    *(__half2*)(out + (size_t)row * Dm + i0 + 2) =
        __floats2half2_rn(d2 * rstd * gv.z + bv.z, d3 * rstd * gv.w + bv.w);
}

// ---------------- causal depthwise conv (half out) ----------------
__global__ void __launch_bounds__(256) conv_kernel(const float* __restrict__ h,
                                                   const float* __restrict__ cw,
                                                   const float* __restrict__ cb,
                                                   __half* __restrict__ out) {
    int row = blockIdx.x;
    int t = row % Tlen;
    const float* h0 = h + (size_t)row * Dm;
    int i = threadIdx.x * 4;
    float4 cur = *(const float4*)(h0 + i);
    float4 w0 = *(const float4*)(cw + 0*Dm + i);
    float4 w1 = *(const float4*)(cw + 1*Dm + i);
    float4 w2 = *(const float4*)(cw + 2*Dm + i);
    float4 bb = *(const float4*)(cb + i);
    float4 z = make_float4(0.f, 0.f, 0.f, 0.f);
    float4 p1 = (t >= 1) ? *(const float4*)(h0 - Dm + i) : z;
    float4 p2 = (t >= 2) ? *(const float4*)(h0 - 2*Dm + i) : z;
    float ox = cur.x + w0.x*p2.x + w1.x*p1.x + w2.x*cur.x + bb.x;
    float oy = cur.y + w0.y*p2.y + w1.y*p1.y + w2.y*cur.y + bb.y;
    float oz = cur.z + w0.z*p2.z + w1.z*p1.z + w2.z*cur.z + bb.z;
    float ow = cur.w + w0.w*p2.w + w1.w*p1.w + w2.w*cur.w + bb.w;
    *(__half2*)(out + (size_t)row * Dm + i)     = __floats2half2_rn(ox, oy);
    *(__half2*)(out + (size_t)row * Dm + i + 2) = __floats2half2_rn(oz, ow);
}

// ---------------- per-head k layernorm ----------------
__global__ void __launch_bounds__(512) kln_kernel(float* __restrict__ qkv,
                                                  const float* __restrict__ g,
                                                  const float* __restrict__ b) {
    int row = blockIdx.x;
    int wid = threadIdx.x >> 5, lane = threadIdx.x & 31;
    float* k = qkv + (size_t)row * (3*Dm) + Dm + wid * DK;
    float x0 = k[lane], x1 = k[lane + 32];
    float s = x0 + x1;
    #pragma unroll
    for (int o = 16; o; o >>= 1) s += __shfl_xor_sync(0xffffffffu, s, o);
    float mean = s * (1.f / DK);
    float d0 = x0 - mean, d1 = x1 - mean;
    float q = d0*d0 + d1*d1;
    #pragma unroll
    for (int o = 16; o; o >>= 1) q += __shfl_xor_sync(0xffffffffu, q, o);
    float rstd = rsqrtf(q * (1.f / DK) + 1e-5f);
    k[lane]      = d0 * rstd * g[lane]      + b[lane];
    k[lane + 32] = d1 * rstd * g[lane + 32] + b[lane + 32];
}

// ---------------- static physics ----------------
__global__ void physics_kernel(const float* __restrict__ W_LTM,
                               const float* __restrict__ V_T0,
                               const float* __restrict__ V_gs,
                               const float* __restrict__ beta_tau,
                               const float* __restrict__ beta_gm,
                               const float* __restrict__ C_ch,
                               const float* __restrict__ gma,
                               const float* __restrict__ alpha,
                               const float* __restrict__ icth,
                               float* __restrict__ ret,
                               float* __restrict__ gate) {
    int idx = blockIdx.x * blockDim.x + threadIdx.x;
    if (idx >= Ll*Hh*DK*DK) return;
    int lh = idx / (DK*DK);
    int l  = lh / Hh;
    float veff = (V_gs[lh] - V_T0[lh]) + W_LTM[idx];
    float sp   = (veff > 20.f) ? veff : log1pf(expf(veff));
    float g_ch = beta_tau[lh] * sp;
    float r    = expf(-g_ch / C_ch[lh]);
    float G    = beta_gm[lh] * sp * (1.f / (1.f + expf(-veff)));
    float sgn  = tanhf(alpha[l] * (g_ch - icth[l]));
    ret[idx]  = r;
    gate[idx] = gma[lh] * sgn * G;
}

// ---------------- sequential recurrence: 8-step blocked, v/4 split ---------
// 256 blocks (bh x v-quarter). 256 thr = 16 v-rows x 16 k-parts (4 elems each).
// One barrier per 8 timesteps; 8-deep register prefetch window.
__global__ void __launch_bounds__(256, 1) scan_kernel(const float* __restrict__ qkv,
                                                      const float* __restrict__ ret,
                                                      const float* __restrict__ gate,
                                                      const float* __restrict__ W,
                                                      __half* __restrict__ y) {
    int bh = blockIdx.x >> 2;
    int vq = blockIdx.x & 3;
    int b = bh / Hh, h = bh % Hh;
    int tid = threadIdx.x;
    int v = vq * 16 + (tid >> 4), part = tid & 15, koff = part * 4;

    float r[4], g[4], w[4], f[4];
    {
        int base = (h*DK + v)*DK + koff;
        #pragma unroll
        for (int j = 0; j < 4; j++) {
            r[j] = ret[base + j];
            g[j] = gate[base + j];
            w[j] = W[base + j];
            f[j] = 0.f;
        }
    }

    __shared__ float sbuf[2][8][192];   // [buf][step][q|k|v]
    bool loader = tid < 192;
    int which = tid >> 6, lane = tid & 63;
    size_t rowbase = (size_t)b * Tlen * (3*Dm) + h * DK;
    const float* src = qkv + rowbase + which * Dm + lane;
    float pre[8];
    if (loader) {
        #pragma unroll
        for (int j = 0; j < 8; j++) pre[j] = src[(size_t)j * (3*Dm)];
    }
    __half* yout = y + (size_t)b * Tlen * Dm + h * DK + v;

    const int NB = Tlen / 8;
    for (int tb = 0; tb < NB; tb++) {
        int p = tb & 1;
        if (loader) {
            #pragma unroll
            for (int j = 0; j < 8; j++) sbuf[p][j][tid] = pre[j];
        }
        __syncthreads();
        if (loader && tb + 1 < NB) {
            size_t tn = (size_t)(tb * 8 + 8);
            #pragma unroll
            for (int j = 0; j < 8; j++)
                pre[j] = src[(tn + j) * (3*Dm)];
        }
        #pragma unroll
        for (int st = 0; st < 8; st++) {
            float vt = sbuf[p][st][128 + v];
            float4 kk = *(const float4*)&sbuf[p][st][64 + koff];
            float4 qq = *(const float4*)&sbuf[p][st][koff];
            f[0] = r[0]*f[0] + (g[0]*vt)*kk.x;
            f[1] = r[1]*f[1] + (g[1]*vt)*kk.y;
            f[2] = r[2]*f[2] + (g[2]*vt)*kk.z;
            f[3] = r[3]*f[3] + (g[3]*vt)*kk.w;
            float yacc;
            yacc = (w[0] + f[0]) * qq.x;
            yacc = fmaf(w[1] + f[1], qq.y, yacc);
            yacc = fmaf(w[2] + f[2], qq.z, yacc);
            yacc = fmaf(w[3] + f[3], qq.w, yacc);
            yacc += __shfl_xor_sync(0xffffffffu, yacc, 1);
            yacc += __shfl_xor_sync(0xffffffffu, yacc, 2);
            yacc += __shfl_xor_sync(0xffffffffu, yacc, 4);
            yacc += __shfl_xor_sync(0xffffffffu, yacc, 8);
            if (part == 0) yout[(size_t)(tb * 8 + st) * Dm] = __float2half_rn(yacc);
        }
    }
}

// ======== fp16 GEMM v5: K64 superstages, ldmatrix, 64x64 warp tiles ========
// C = A * B^T (+Res). A:(M,K), B:(N,K) row-major __half. fp32 accumulate.
// CTA 128x128, 4 warps (2x2 of 64x64), 128 threads, 2 CTA/SM.
// Superstage = K64 chunk = two K32 subtiles (each: 64 macro-rows x 128B,
// 16B chunks XOR-swizzled by mr&7). 3 superstages; one barrier per K64.
#define SUBT_B  8192                       // bytes per K32 subtile
#define SS_B    (2*SUBT_B)                 // 16 KB per matrix per superstage
#define NSS     3
#define G_SMEM_BYTES (2*NSS*SS_B)          // 98304

__device__ __forceinline__ void cpasync16(uint32_t dst_smem, const void* src) {
    asm volatile("cp.async.cg.shared.global [%0], [%1], 16;"
                 :: "r"(dst_smem), "l"(src) : "memory");
}
__device__ __forceinline__ uint32_t smem_u32(const void* p) {
    uint32_t a;
    asm("{ .reg .u64 t; cvta.to.shared.u64 t, %1; cvt.u32.u64 %0, t; }"
        : "=r"(a) : "l"(p));
    return a;
}
__device__ __forceinline__ void ldm_x4(uint32_t& r0, uint32_t& r1,
                                       uint32_t& r2, uint32_t& r3, uint32_t addr) {
    asm volatile("ldmatrix.sync.aligned.m8n8.x4.shared.b16 {%0,%1,%2,%3}, [%4];"
                 : "=r"(r0), "=r"(r1), "=r"(r2), "=r"(r3) : "r"(addr));
}
__device__ __forceinline__ void mma_f16(float c[4],
                                        uint32_t a0, uint32_t a1, uint32_t a2, uint32_t a3,
                                        uint32_t b0, uint32_t b1) {
    asm volatile(
        "mma.sync.aligned.m16n8k16.row.col.f32.f16.f16.f32 "
        "{%0,%1,%2,%3}, {%4,%5,%6,%7}, {%8,%9}, {%0,%1,%2,%3};\n"
        : "+f"(c[0]), "+f"(c[1]), "+f"(c[2]), "+f"(c[3])
        : "r"(a0), "r"(a1), "r"(a2), "r"(a3), "r"(b0), "r"(b1));
}

// one 128x32-half subtile into a buffer (128 threads: 4 chunks each)
__device__ __forceinline__ void issue_tile32(uint32_t base,
                                             const __half* __restrict__ Gp,
                                             int K, int k0, int tid) {
    #pragma unroll
    for (int hi = 0; hi < 4; hi++) {
        int c = tid + hi * 128;
        int mr = c >> 3, kk = c & 7;
        int m = mr * 2 + (kk >> 2);
        int h0 = (kk & 3) * 8;
        uint32_t dst = base + (uint32_t)(mr * 128 + ((kk ^ (mr & 7)) << 4));
        cpasync16(dst, Gp + (size_t)m * K + k0 + h0);
    }
}
// one K64 superstage (A and B) into superstage buffers
__device__ __forceinline__ void issue_ss(uint32_t sbase, int ss,
                                         const __half* __restrict__ Agp,
                                         const __half* __restrict__ Bgp,
                                         int K, int k0, int tid) {
    uint32_t aB = sbase + (uint32_t)ss * SS_B;
    uint32_t bB = sbase + (uint32_t)(NSS * SS_B) + (uint32_t)ss * SS_B;
    issue_tile32(aB,          Agp, K, k0,      tid);
    issue_tile32(aB + SUBT_B, Agp, K, k0 + 32, tid);
    issue_tile32(bB,          Bgp, K, k0,      tid);
    issue_tile32(bB + SUBT_B, Bgp, K, k0 + 32, tid);
}

__global__ void __launch_bounds__(128, 2) mma_nt_h(int M, int N, int K,
                                                   const __half* __restrict__ A,
                                                   const __half* __restrict__ B,
                                                   const float* __restrict__ Res,
                                                   float* __restrict__ C) {
    extern __shared__ __half smemh[];
    uint32_t sbase = smem_u32(smemh);
    int tid = threadIdx.x;
    int wid = tid >> 5, lane = tid & 31;
    int wm = (wid & 1) * 64;
    int wn = (wid >> 1) * 64;
    int m0 = blockIdx.y * 128, n0 = blockIdx.x * 128;
    int lg = lane >> 2;
    int lq = lane & 3;

    float acc[4][8][4];
    #pragma unroll
    for (int i = 0; i < 4; i++)
        #pragma unroll
        for (int j = 0; j < 8; j++)
            #pragma unroll
            for (int q = 0; q < 4; q++) acc[i][j][q] = 0.f;

    const __half* Agp = A + (size_t)m0 * K;
    const __half* Bgp = B + (size_t)n0 * K;

    // ldmatrix lane geometry
    int lm = lane & 15;
    int lc = lane >> 4;
    int mrA0 = (wm + lm) >> 1;
    int mrB0 = (wn + lm) >> 1;
    int halfbit = lm & 1;
    int kpA[2], kpB[2];
    #pragma unroll
    for (int kb = 0; kb < 2; kb++) {
        kpA[kb] = ((halfbit * 4 + kb * 2 + lc) ^ (mrA0 & 7)) << 4;
        kpB[kb] = ((halfbit * 4 + kb * 2 + lc) ^ (mrB0 & 7)) << 4;
    }
    uint32_t aRow = (uint32_t)(mrA0 * 128);
    uint32_t bRow = (uint32_t)(mrB0 * 128);

    int nSS = K >> 6;   // K / 64

    issue_ss(sbase, 0, Agp, Bgp, K, 0,  tid);
    asm volatile("cp.async.commit_group;");
    issue_ss(sbase, 1, Agp, Bgp, K, 64, tid);
    asm volatile("cp.async.commit_group;");

    for (int st = 0; st < nSS; st++) {
        int ss = st % NSS;
        asm volatile("cp.async.wait_group 1;");
        __syncthreads();   // all warps done reading stage refilled below
        if (st + 2 < nSS)
            issue_ss(sbase, (st + 2) % NSS, Agp, Bgp, K, (st + 2) << 6, tid);
        asm volatile("cp.async.commit_group;");

        uint32_t aSS = sbase + (uint32_t)ss * SS_B + aRow;
        uint32_t bSS = sbase + (uint32_t)(NSS * SS_B) + (uint32_t)ss * SS_B + bRow;

        #pragma unroll
        for (int sub = 0; sub < 2; sub++) {
            uint32_t aBase = aSS + (uint32_t)(sub * SUBT_B);
            uint32_t bBase = bSS + (uint32_t)(sub * SUBT_B);
            #pragma unroll
            for (int kb = 0; kb < 2; kb++) {
                uint32_t af[4][4];
                #pragma unroll
                for (int i = 0; i < 4; i++)
                    ldm_x4(af[i][0], af[i][1], af[i][2], af[i][3],
                           aBase + (uint32_t)(i * 1024) + kpA[kb]);
                uint32_t bf[8][2];
                #pragma unroll
                for (int jj = 0; jj < 4; jj++) {
                    uint32_t r0, r1, r2, r3;
                    ldm_x4(r0, r1, r2, r3, bBase + (uint32_t)(jj * 1024) + kpB[kb]);
                    bf[jj*2][0] = r0; bf[jj*2+1][0] = r1;
                    bf[jj*2][1] = r2; bf[jj*2+1][1] = r3;
                }
                #pragma unroll
                for (int i = 0; i < 4; i++)
                    #pragma unroll
                    for (int j = 0; j < 8; j++)
                        mma_f16(acc[i][j], af[i][0], af[i][1], af[i][2], af[i][3],
                                bf[j][0], bf[j][1]);
            }
        }
    }

    // epilogue
    #pragma unroll
    for (int i = 0; i < 4; i++) {
        int row = m0 + wm + i*16 + lg;
        #pragma unroll
        for (int j = 0; j < 8; j++) {
            int col = n0 + wn + j*8 + 2*lq;
            size_t o0 = (size_t)row * N + col;
            size_t o1 = (size_t)(row + 8) * N + col;
            float2 v0 = make_float2(acc[i][j][0], acc[i][j][1]);
            float2 v1 = make_float2(acc[i][j][2], acc[i][j][3]);
            if (Res) {
                float2 q0 = *(const float2*)(Res + o0);
                float2 q1 = *(const float2*)(Res + o1);
                v0.x += q0.x; v0.y += q0.y;
                v1.x += q1.x; v1.y += q1.y;
            }
            *(float2*)(C + o0) = v0;
            *(float2*)(C + o1) = v1;
        }
    }
}

// ---------------- launch ----------------
extern "C" void kernel_launch(void* const* d_in, const int* in_sizes, int n_in,
                              void* d_out, int out_size) {
    const int*   ids      = (const int*)  d_in[0];
    const float* embedW   = (const float*)d_in[2];
    const float* conv_w   = (const float*)d_in[3];
    const float* conv_b   = (const float*)d_in[4];
    const float* Wqkv     = (const float*)d_in[5];
    const float* Wo       = (const float*)d_in[6];
    const float* W_LTM    = (const float*)d_in[7];
    const float* V_T0     = (const float*)d_in[8];
    const float* V_gs     = (const float*)d_in[9];
    const float* beta_tau = (const float*)d_in[10];
    const float* beta_gm  = (const float*)d_in[11];
    const float* C_ch     = (const float*)d_in[12];
    const float* gma      = (const float*)d_in[13];
    const float* alpha    = (const float*)d_in[14];
    const float* icth     = (const float*)d_in[15];
    const float* ln1_g    = (const float*)d_in[16];
    const float* ln1_b    = (const float*)d_in[17];
    const float* lnk_g    = (const float*)d_in[18];
    const float* lnk_b    = (const float*)d_in[19];
    const float* lnf_g    = (const float*)d_in[20];
    const float* lnf_b    = (const float*)d_in[21];
    const float* headW    = (const float*)d_in[22];
    float* out = (float*)d_out;

    float *x, *h, *qkv, *ret, *gate;
    __half *h2h, *yh, *hh, *wqh, *woh, *whh;
    cudaGetSymbolAddress((void**)&x,    g_x);
    cudaGetSymbolAddress((void**)&h,    g_h);
    cudaGetSymbolAddress((void**)&h2h,  g_h2h);
    cudaGetSymbolAddress((void**)&qkv,  g_qkv);
    cudaGetSymbolAddress((void**)&yh,   g_yh);
    cudaGetSymbolAddress((void**)&hh,   g_hh);
    cudaGetSymbolAddress((void**)&ret,  g_ret);
    cudaGetSymbolAddress((void**)&gate, g_gate);
    cudaGetSymbolAddress((void**)&wqh,  g_wqh);
    cudaGetSymbolAddress((void**)&woh,  g_woh);
    cudaGetSymbolAddress((void**)&whh,  g_whh);

    cudaFuncSetAttribute(mma_nt_h, cudaFuncAttributeMaxDynamicSharedMemorySize,
                         G_SMEM_BYTES);

    tohalf_kernel<<<(Ll*3*Dm*Dm)/1024, 256>>>(Wqkv,  wqh);
    tohalf_kernel<<<(Ll*Dm*Dm)/1024,   256>>>(Wo,    woh);
    tohalf_kernel<<<(Vv*Dm)/1024,      256>>>(headW, whh);

    embed_kernel<<<NROW, 256>>>(ids, embedW, x);
    {
        int n = Ll*Hh*DK*DK;
        physics_kernel<<<(n + 255)/256, 256>>>(W_LTM, V_T0, V_gs, beta_tau, beta_gm,
                                               C_ch, gma, alpha, icth, ret, gate);
    }

    for (int l = 0; l < Ll; l++) {
        ln_kernel<<<NROW, 256>>>(x, ln1_g + l*Dm, ln1_b + l*Dm, h);
        conv_kernel<<<NROW, 256>>>(h, conv_w + l*3*Dm, conv_b + l*Dm, h2h);

        dim3 gq((3*Dm)/128, NROW/128);
        mma_nt_h<<<gq, 128, G_SMEM_BYTES>>>(NROW, 3*Dm, Dm, h2h,
                                            wqh + (size_t)l*3*Dm*Dm, nullptr, qkv);

        kln_kernel<<<NROW, 512>>>(qkv, lnk_g + l*DK, lnk_b + l*DK);

        scan_kernel<<<Bb*Hh*4, 256>>>(qkv,
                                      ret  + (size_t)l*Hh*DK*DK,
                                      gate + (size_t)l*Hh*DK*DK,
                                      W_LTM + (size_t)l*Hh*DK*DK,
                                      yh);

        dim3 go(Dm/128, NROW/128);
        mma_nt_h<<<go, 128, G_SMEM_BYTES>>>(NROW, Dm, Dm, yh,
                                            woh + (size_t)l*Dm*Dm, x, x);
    }

    lnh_kernel<<<NROW, 256>>>(x, lnf_g, lnf_b, hh);
    dim3 gh(Vv/128, NROW/128);
    mma_nt_h<<<gh, 128, G_SMEM_BYTES>>>(NROW, Vv, Dm, hh, whh, nullptr, out);
}

// round 10
// speedup vs baseline: 6.3062x; 1.0242x over previous
#include <cuda_runtime.h>
#include <cuda_fp16.h>
#include <math.h>
#include <stdint.h>

// ---------------- problem constants ----------------
#define Dm    1024
#define Tlen  2048
#define Bb    4
#define Hh    16
#define DK    64
#define Ll    2
#define Vv    8192
#define NROW  (Bb*Tlen)          // 8192 token rows

// ---------------- scratch (device globals; no allocation allowed) ----------
__device__ float  g_x  [NROW*Dm];        // residual stream (fp32)
__device__ float  g_h  [NROW*Dm];        // ln output (fp32, conv input)
__device__ __half g_h2h[NROW*Dm];        // conv output (half, A of qkv GEMM)
__device__ float  g_qkv[NROW*3*Dm];      // fp32
__device__ __half g_yh [NROW*Dm];        // scan output (half, A of Wo GEMM)
__device__ __half g_hh [NROW*Dm];        // final ln output (half, A of head GEMM)
__device__ float  g_ret [Ll*Hh*DK*DK];
__device__ float  g_gate[Ll*Hh*DK*DK];
// half weights
__device__ __half g_wqh[Ll*3*Dm*Dm];
__device__ __half g_woh[Ll*Dm*Dm];
__device__ __half g_whh[Vv*Dm];

// ---------------- fp32 -> fp16 weight conversion ----------------
__global__ void __launch_bounds__(256) tohalf_kernel(const float* __restrict__ s,
                                                     __half* __restrict__ d) {
    int i = (blockIdx.x * blockDim.x + threadIdx.x) * 4;
    float4 v = *(const float4*)(s + i);
    *(__half2*)(d + i)     = __floats2half2_rn(v.x, v.y);
    *(__half2*)(d + i + 2) = __floats2half2_rn(v.z, v.w);
}

// ---------------- block reduce helper (blockDim == 256) ----------------
__device__ __forceinline__ float blockReduceSum(float v, float* sh) {
    #pragma unroll
    for (int o = 16; o; o >>= 1) v += __shfl_xor_sync(0xffffffffu, v, o);
    if ((threadIdx.x & 31) == 0) sh[threadIdx.x >> 5] = v;
    __syncthreads();
    float tot = 0.f;
    #pragma unroll
    for (int i = 0; i < 8; i++) tot += sh[i];
    __syncthreads();
    return tot;
}

// ---------------- fused embedding gather + layer-0 LN ----------------
// writes residual x AND ln1(layer0) output h in one pass
__global__ void __launch_bounds__(256) embed_ln_kernel(const int* __restrict__ ids,
                                                       const float* __restrict__ W,
                                                       const float* __restrict__ g,
                                                       const float* __restrict__ b,
                                                       float* __restrict__ x,
                                                       float* __restrict__ h) {
    __shared__ float sh[8];
    int row = blockIdx.x;
    int id  = ids[row];
    const float* xr = W + (size_t)id * Dm;
    int i0 = threadIdx.x * 4;
    float4 xv = *(const float4*)(xr + i0);
    *(float4*)(x + (size_t)row * Dm + i0) = xv;     // residual stream
    float s = xv.x + xv.y + xv.z + xv.w;
    float mean = blockReduceSum(s, sh) * (1.f / Dm);
    float d0 = xv.x - mean, d1 = xv.y - mean, d2 = xv.z - mean, d3 = xv.w - mean;
    float sq = d0*d0 + d1*d1 + d2*d2 + d3*d3;
    float var = blockReduceSum(sq, sh) * (1.f / Dm);
    float rstd = rsqrtf(var + 1e-5f);
    float4 gv = *(const float4*)(g + i0);
    float4 bv = *(const float4*)(b + i0);
    float4 ov;
    ov.x = d0 * rstd * gv.x + bv.x;
    ov.y = d1 * rstd * gv.y + bv.y;
    ov.z = d2 * rstd * gv.z + bv.z;
    ov.w = d3 * rstd * gv.w + bv.w;
    *(float4*)(h + (size_t)row * Dm + i0) = ov;
}

// ---------------- layernorm (fp32 out) ----------------
__global__ void __launch_bounds__(256) ln_kernel(const float* __restrict__ x,
                                                 const float* __restrict__ g,
                                                 const float* __restrict__ b,
                                                 float* __restrict__ out) {
    __shared__ float sh[8];
    int row = blockIdx.x;
    const float* xr = x + (size_t)row * Dm;
    int i0 = threadIdx.x * 4;
    float4 xv = *(const float4*)(xr + i0);
    float s = xv.x + xv.y + xv.z + xv.w;
    float mean = blockReduceSum(s, sh) * (1.f / Dm);
    float d0 = xv.x - mean, d1 = xv.y - mean, d2 = xv.z - mean, d3 = xv.w - mean;
    float sq = d0*d0 + d1*d1 + d2*d2 + d3*d3;
    float var = blockReduceSum(sq, sh) * (1.f / Dm);
    float rstd = rsqrtf(var + 1e-5f);
    float4 gv = *(const float4*)(g + i0);
    float4 bv = *(const float4*)(b + i0);
    float4 ov;
    ov.x = d0 * rstd * gv.x + bv.x;
    ov.y = d1 * rstd * gv.y + bv.y;
    ov.z = d2 * rstd * gv.z + bv.z;
    ov.w = d3 * rstd * gv.w + bv.w;
    *(float4*)(out + (size_t)row * Dm + i0) = ov;
}

// ---------------- layernorm (half out, for head GEMM A) ----------------
__global__ void __launch_bounds__(256) lnh_kernel(const float* __restrict__ x,
                                                  const float* __restrict__ g,
                                                  const float* __restrict__ b,
                                                  __half* __restrict__ out) {
    __shared__ float sh[8];
    int row = blockIdx.x;
    const float* xr = x + (size_t)row * Dm;
    int i0 = threadIdx.x * 4;
    float4 xv = *(const float4*)(xr + i0);
    float s = xv.x + xv.y + xv.z + xv.w;
    float mean = blockReduceSum(s, sh) * (1.f / Dm);
    float d0 = xv.x - mean, d1 = xv.y - mean, d2 = xv.z - mean, d3 = xv.w - mean;
    float sq = d0*d0 + d1*d1 + d2*d2 + d3*d3;
    float var = blockReduceSum(sq, sh) * (1.f / Dm);
    float rstd = rsqrtf(var + 1e-5f);
    float4 gv = *(const float4*)(g + i0);
    float4 bv = *(const float4*)(b + i0);
    *(__half2*)(out + (size_t)row * Dm + i0) =
        __floats2half2_rn(d0 * rstd * gv.x + bv.x, d1 * rstd * gv.y + bv.y);
    *(__half2*)(out + (size_t)row * Dm + i0 + 2) =
        __floats2half2_rn(d2 * rstd * gv.z + bv.z, d3 * rstd * gv.w + bv.w);
}

// ---------------- causal depthwise conv (half out) ----------------
__global__ void __launch_bounds__(256) conv_kernel(const float* __restrict__ h,
                                                   const float* __restrict__ cw,
                                                   const float* __restrict__ cb,
                                                   __half* __restrict__ out) {
    int row = blockIdx.x;
    int t = row % Tlen;
    const float* h0 = h + (size_t)row * Dm;
    int i = threadIdx.x * 4;
    float4 cur = *(const float4*)(h0 + i);
    float4 w0 = *(const float4*)(cw + 0*Dm + i);
    float4 w1 = *(const float4*)(cw + 1*Dm + i);
    float4 w2 = *(const float4*)(cw + 2*Dm + i);
    float4 bb = *(const float4*)(cb + i);
    float4 z = make_float4(0.f, 0.f, 0.f, 0.f);
    float4 p1 = (t >= 1) ? *(const float4*)(h0 - Dm + i) : z;
    float4 p2 = (t >= 2) ? *(const float4*)(h0 - 2*Dm + i) : z;
    float ox = cur.x + w0.x*p2.x + w1.x*p1.x + w2.x*cur.x + bb.x;
    float oy = cur.y + w0.y*p2.y + w1.y*p1.y + w2.y*cur.y + bb.y;
    float oz = cur.z + w0.z*p2.z + w1.z*p1.z + w2.z*cur.z + bb.z;
    float ow = cur.w + w0.w*p2.w + w1.w*p1.w + w2.w*cur.w + bb.w;
    *(__half2*)(out + (size_t)row * Dm + i)     = __floats2half2_rn(ox, oy);
    *(__half2*)(out + (size_t)row * Dm + i + 2) = __floats2half2_rn(oz, ow);
}

// ---------------- per-head k layernorm ----------------
__global__ void __launch_bounds__(512) kln_kernel(float* __restrict__ qkv,
                                                  const float* __restrict__ g,
                                                  const float* __restrict__ b) {
    int row = blockIdx.x;
    int wid = threadIdx.x >> 5, lane = threadIdx.x & 31;
    float* k = qkv + (size_t)row * (3*Dm) + Dm + wid * DK;
    float x0 = k[lane], x1 = k[lane + 32];
    float s = x0 + x1;
    #pragma unroll
    for (int o = 16; o; o >>= 1) s += __shfl_xor_sync(0xffffffffu, s, o);
    float mean = s * (1.f / DK);
    float d0 = x0 - mean, d1 = x1 - mean;
    float q = d0*d0 + d1*d1;
    #pragma unroll
    for (int o = 16; o; o >>= 1) q += __shfl_xor_sync(0xffffffffu, q, o);
    float rstd = rsqrtf(q * (1.f / DK) + 1e-5f);
    k[lane]      = d0 * rstd * g[lane]      + b[lane];
    k[lane + 32] = d1 * rstd * g[lane + 32] + b[lane + 32];
}

// ---------------- static physics ----------------
__global__ void physics_kernel(const float* __restrict__ W_LTM,
                               const float* __restrict__ V_T0,
                               const float* __restrict__ V_gs,
                               const float* __restrict__ beta_tau,
                               const float* __restrict__ beta_gm,
                               const float* __restrict__ C_ch,
                               const float* __restrict__ gma,
                               const float* __restrict__ alpha,
                               const float* __restrict__ icth,
                               float* __restrict__ ret,
                               float* __restrict__ gate) {
    int idx = blockIdx.x * blockDim.x + threadIdx.x;
    if (idx >= Ll*Hh*DK*DK) return;
    int lh = idx / (DK*DK);
    int l  = lh / Hh;
    float veff = (V_gs[lh] - V_T0[lh]) + W_LTM[idx];
    float sp   = (veff > 20.f) ? veff : log1pf(expf(veff));
    float g_ch = beta_tau[lh] * sp;
    float r    = expf(-g_ch / C_ch[lh]);
    float G    = beta_gm[lh] * sp * (1.f / (1.f + expf(-veff)));
    float sgn  = tanhf(alpha[l] * (g_ch - icth[l]));
    ret[idx]  = r;
    gate[idx] = gma[lh] * sgn * G;
}

// ---------------- sequential recurrence: 16-step blocked, v/4 split --------
// 256 blocks (bh x v-quarter). 256 thr = 16 v-rows x 16 k-parts (4 elems each).
// One barrier per 16 timesteps; 16-deep register prefetch window.
__global__ void __launch_bounds__(256, 1) scan_kernel(const float* __restrict__ qkv,
                                                      const float* __restrict__ ret,
                                                      const float* __restrict__ gate,
                                                      const float* __restrict__ W,
                                                      __half* __restrict__ y) {
    int bh = blockIdx.x >> 2;
    int vq = blockIdx.x & 3;
    int b = bh / Hh, h = bh % Hh;
    int tid = threadIdx.x;
    int v = vq * 16 + (tid >> 4), part = tid & 15, koff = part * 4;

    float r[4], g[4], w[4], f[4];
    {
        int base = (h*DK + v)*DK + koff;
        #pragma unroll
        for (int j = 0; j < 4; j++) {
            r[j] = ret[base + j];
            g[j] = gate[base + j];
            w[j] = W[base + j];
            f[j] = 0.f;
        }
    }

    __shared__ float sbuf[2][16][192];   // [buf][step][q|k|v]
    bool loader = tid < 192;
    int which = tid >> 6, lane = tid & 63;
    size_t rowbase = (size_t)b * Tlen * (3*Dm) + h * DK;
    const float* src = qkv + rowbase + which * Dm + lane;
    float pre[16];
    if (loader) {
        #pragma unroll
        for (int j = 0; j < 16; j++) pre[j] = src[(size_t)j * (3*Dm)];
    }
    __half* yout = y + (size_t)b * Tlen * Dm + h * DK + v;

    const int NB = Tlen / 16;
    for (int tb = 0; tb < NB; tb++) {
        int p = tb & 1;
        if (loader) {
            #pragma unroll
            for (int j = 0; j < 16; j++) sbuf[p][j][tid] = pre[j];
        }
        __syncthreads();
        if (loader && tb + 1 < NB) {
            size_t tn = (size_t)(tb * 16 + 16);
            #pragma unroll
            for (int j = 0; j < 16; j++)
                pre[j] = src[(tn + j) * (3*Dm)];
        }
        #pragma unroll
        for (int st = 0; st < 16; st++) {
            float vt = sbuf[p][st][128 + v];
            float4 kk = *(const float4*)&sbuf[p][st][64 + koff];
            float4 qq = *(const float4*)&sbuf[p][st][koff];
            f[0] = r[0]*f[0] + (g[0]*vt)*kk.x;
            f[1] = r[1]*f[1] + (g[1]*vt)*kk.y;
            f[2] = r[2]*f[2] + (g[2]*vt)*kk.z;
            f[3] = r[3]*f[3] + (g[3]*vt)*kk.w;
            float yacc;
            yacc = (w[0] + f[0]) * qq.x;
            yacc = fmaf(w[1] + f[1], qq.y, yacc);
            yacc = fmaf(w[2] + f[2], qq.z, yacc);
            yacc = fmaf(w[3] + f[3], qq.w, yacc);
            yacc += __shfl_xor_sync(0xffffffffu, yacc, 1);
            yacc += __shfl_xor_sync(0xffffffffu, yacc, 2);
            yacc += __shfl_xor_sync(0xffffffffu, yacc, 4);
            yacc += __shfl_xor_sync(0xffffffffu, yacc, 8);
            if (part == 0) yout[(size_t)(tb * 16 + st) * Dm] = __float2half_rn(yacc);
        }
    }
}

// ======== fp16 GEMM v6: K64 superstages, refill-after-compute ========
// C = A * B^T (+Res). A:(M,K), B:(N,K) row-major __half. fp32 accumulate.
// CTA 128x128, 4 warps (2x2 of 64x64), 128 threads, 2 CTA/SM.
#define SUBT_B  8192                       // bytes per K32 subtile
#define SS_B    (2*SUBT_B)                 // 16 KB per matrix per superstage
#define NSS     3
#define G_SMEM_BYTES (2*NSS*SS_B)          // 98304

__device__ __forceinline__ void cpasync16(uint32_t dst_smem, const void* src) {
    asm volatile("cp.async.cg.shared.global [%0], [%1], 16;"
                 :: "r"(dst_smem), "l"(src) : "memory");
}
__device__ __forceinline__ uint32_t smem_u32(const void* p) {
    uint32_t a;
    asm("{ .reg .u64 t; cvta.to.shared.u64 t, %1; cvt.u32.u64 %0, t; }"
        : "=r"(a) : "l"(p));
    return a;
}
__device__ __forceinline__ void ldm_x4(uint32_t& r0, uint32_t& r1,
                                       uint32_t& r2, uint32_t& r3, uint32_t addr) {
    asm volatile("ldmatrix.sync.aligned.m8n8.x4.shared.b16 {%0,%1,%2,%3}, [%4];"
                 : "=r"(r0), "=r"(r1), "=r"(r2), "=r"(r3) : "r"(addr));
}
__device__ __forceinline__ void mma_f16(float c[4],
                                        uint32_t a0, uint32_t a1, uint32_t a2, uint32_t a3,
                                        uint32_t b0, uint32_t b1) {
    asm volatile(
        "mma.sync.aligned.m16n8k16.row.col.f32.f16.f16.f32 "
        "{%0,%1,%2,%3}, {%4,%5,%6,%7}, {%8,%9}, {%0,%1,%2,%3};\n"
        : "+f"(c[0]), "+f"(c[1]), "+f"(c[2]), "+f"(c[3])
        : "r"(a0), "r"(a1), "r"(a2), "r"(a3), "r"(b0), "r"(b1));
}

// one 128x32-half subtile into a buffer (128 threads: 4 chunks each)
__device__ __forceinline__ void issue_tile32(uint32_t base,
                                             const __half* __restrict__ Gp,
                                             int K, int k0, int tid) {
    #pragma unroll
    for (int hi = 0; hi < 4; hi++) {
        int c = tid + hi * 128;
        int mr = c >> 3, kk = c & 7;
        int m = mr * 2 + (kk >> 2);
        int h0 = (kk & 3) * 8;
        uint32_t dst = base + (uint32_t)(mr * 128 + ((kk ^ (mr & 7)) << 4));
        cpasync16(dst, Gp + (size_t)m * K + k0 + h0);
    }
}
// one K64 superstage (A and B) into superstage buffers
__device__ __forceinline__ void issue_ss(uint32_t sbase, int ss,
                                         const __half* __restrict__ Agp,
                                         const __half* __restrict__ Bgp,
                                         int K, int k0, int tid) {
    uint32_t aB = sbase + (uint32_t)ss * SS_B;
    uint32_t bB = sbase + (uint32_t)(NSS * SS_B) + (uint32_t)ss * SS_B;
    issue_tile32(aB,          Agp, K, k0,      tid);
    issue_tile32(aB + SUBT_B, Agp, K, k0 + 32, tid);
    issue_tile32(bB,          Bgp, K, k0,      tid);
    issue_tile32(bB + SUBT_B, Bgp, K, k0 + 32, tid);
}

__global__ void __launch_bounds__(128, 2) mma_nt_h(int M, int N, int K,
                                                   const __half* __restrict__ A,
                                                   const __half* __restrict__ B,
                                                   const float* __restrict__ Res,
                                                   float* __restrict__ C) {
    extern __shared__ __half smemh[];
    uint32_t sbase = smem_u32(smemh);
    int tid = threadIdx.x;
    int wid = tid >> 5, lane = tid & 31;
    int wm = (wid & 1) * 64;
    int wn = (wid >> 1) * 64;
    int m0 = blockIdx.y * 128, n0 = blockIdx.x * 128;
    int lg = lane >> 2;
    int lq = lane & 3;

    float acc[4][8][4];
    #pragma unroll
    for (int i = 0; i < 4; i++)
        #pragma unroll
        for (int j = 0; j < 8; j++)
            #pragma unroll
            for (int q = 0; q < 4; q++) acc[i][j][q] = 0.f;

    const __half* Agp = A + (size_t)m0 * K;
    const __half* Bgp = B + (size_t)n0 * K;

    // ldmatrix lane geometry
    int lm = lane & 15;
    int lc = lane >> 4;
    int mrA0 = (wm + lm) >> 1;
    int mrB0 = (wn + lm) >> 1;
    int halfbit = lm & 1;
    int kpA[2], kpB[2];
    #pragma unroll
    for (int kb = 0; kb < 2; kb++) {
        kpA[kb] = ((halfbit * 4 + kb * 2 + lc) ^ (mrA0 & 7)) << 4;
        kpB[kb] = ((halfbit * 4 + kb * 2 + lc) ^ (mrB0 & 7)) << 4;
    }
    uint32_t aRow = (uint32_t)(mrA0 * 128);
    uint32_t bRow = (uint32_t)(mrB0 * 128);

    int nSS = K >> 6;   // K / 64

    issue_ss(sbase, 0, Agp, Bgp, K, 0,  tid);
    asm volatile("cp.async.commit_group;");
    issue_ss(sbase, 1, Agp, Bgp, K, 64, tid);
    asm volatile("cp.async.commit_group;");

    for (int st = 0; st < nSS; st++) {
        int ss = st % NSS;
        asm volatile("cp.async.wait_group 1;");
        __syncthreads();   // all warps done with stage (st-1) => buffer (st+2)%3 free

        uint32_t aSS = sbase + (uint32_t)ss * SS_B + aRow;
        uint32_t bSS = sbase + (uint32_t)(NSS * SS_B) + (uint32_t)ss * SS_B + bRow;

        #pragma unroll
        for (int sub = 0; sub < 2; sub++) {
            uint32_t aBase = aSS + (uint32_t)(sub * SUBT_B);
            uint32_t bBase = bSS + (uint32_t)(sub * SUBT_B);
            #pragma unroll
            for (int kb = 0; kb < 2; kb++) {
                uint32_t af[4][4];
                #pragma unroll
                for (int i = 0; i < 4; i++)
                    ldm_x4(af[i][0], af[i][1], af[i][2], af[i][3],
                           aBase + (uint32_t)(i * 1024) + kpA[kb]);
                uint32_t bf[8][2];
                #pragma unroll
                for (int jj = 0; jj < 4; jj++) {
                    uint32_t r0, r1, r2, r3;
                    ldm_x4(r0, r1, r2, r3, bBase + (uint32_t)(jj * 1024) + kpB[kb]);
                    bf[jj*2][0] = r0; bf[jj*2+1][0] = r1;
                    bf[jj*2][1] = r2; bf[jj*2+1][1] = r3;
                }
                #pragma unroll
                for (int i = 0; i < 4; i++)
                    #pragma unroll
                    for (int j = 0; j < 8; j++)
                        mma_f16(acc[i][j], af[i][0], af[i][1], af[i][2], af[i][3],
                                bf[j][0], bf[j][1]);
            }
        }

        // refill AFTER compute: MMAs start right after the barrier, LSU burst
        // moves off the critical path. Lead is still a full superstage.
        if (st + 2 < nSS)
            issue_ss(sbase, (st + 2) % NSS, Agp, Bgp, K, (st + 2) << 6, tid);
        asm volatile("cp.async.commit_group;");
    }

    // epilogue
    #pragma unroll
    for (int i = 0; i < 4; i++) {
        int row = m0 + wm + i*16 + lg;
        #pragma unroll
        for (int j = 0; j < 8; j++) {
            int col = n0 + wn + j*8 + 2*lq;
            size_t o0 = (size_t)row * N + col;
            size_t o1 = (size_t)(row + 8) * N + col;
            float2 v0 = make_float2(acc[i][j][0], acc[i][j][1]);
            float2 v1 = make_float2(acc[i][j][2], acc[i][j][3]);
            if (Res) {
                float2 q0 = *(const float2*)(Res + o0);
                float2 q1 = *(const float2*)(Res + o1);
                v0.x += q0.x; v0.y += q0.y;
                v1.x += q1.x; v1.y += q1.y;
            }
            *(float2*)(C + o0) = v0;
            *(float2*)(C + o1) = v1;
        }
    }
}

// ---------------- launch ----------------
extern "C" void kernel_launch(void* const* d_in, const int* in_sizes, int n_in,
                              void* d_out, int out_size) {
    const int*   ids      = (const int*)  d_in[0];
    const float* embedW   = (const float*)d_in[2];
    const float* conv_w   = (const float*)d_in[3];
    const float* conv_b   = (const float*)d_in[4];
    const float* Wqkv     = (const float*)d_in[5];
    const float* Wo       = (const float*)d_in[6];
    const float* W_LTM    = (const float*)d_in[7];
    const float* V_T0     = (const float*)d_in[8];
    const float* V_gs     = (const float*)d_in[9];
    const float* beta_tau = (const float*)d_in[10];
    const float* beta_gm  = (const float*)d_in[11];
    const float* C_ch     = (const float*)d_in[12];
    const float* gma      = (const float*)d_in[13];
    const float* alpha    = (const float*)d_in[14];
    const float* icth     = (const float*)d_in[15];
    const float* ln1_g    = (const float*)d_in[16];
    const float* ln1_b    = (const float*)d_in[17];
    const float* lnk_g    = (const float*)d_in[18];
    const float* lnk_b    = (const float*)d_in[19];
    const float* lnf_g    = (const float*)d_in[20];
    const float* lnf_b    = (const float*)d_in[21];
    const float* headW    = (const float*)d_in[22];
    float* out = (float*)d_out;

    float *x, *h, *qkv, *ret, *gate;
    __half *h2h, *yh, *hh, *wqh, *woh, *whh;
    cudaGetSymbolAddress((void**)&x,    g_x);
    cudaGetSymbolAddress((void**)&h,    g_h);
    cudaGetSymbolAddress((void**)&h2h,  g_h2h);
    cudaGetSymbolAddress((void**)&qkv,  g_qkv);
    cudaGetSymbolAddress((void**)&yh,   g_yh);
    cudaGetSymbolAddress((void**)&hh,   g_hh);
    cudaGetSymbolAddress((void**)&ret,  g_ret);
    cudaGetSymbolAddress((void**)&gate, g_gate);
    cudaGetSymbolAddress((void**)&wqh,  g_wqh);
    cudaGetSymbolAddress((void**)&woh,  g_woh);
    cudaGetSymbolAddress((void**)&whh,  g_whh);

    cudaFuncSetAttribute(mma_nt_h, cudaFuncAttributeMaxDynamicSharedMemorySize,
                         G_SMEM_BYTES);

    tohalf_kernel<<<(Ll*3*Dm*Dm)/1024, 256>>>(Wqkv,  wqh);
    tohalf_kernel<<<(Ll*Dm*Dm)/1024,   256>>>(Wo,    woh);
    tohalf_kernel<<<(Vv*Dm)/1024,      256>>>(headW, whh);

    // fused: embedding gather + layer-0 LN
    embed_ln_kernel<<<NROW, 256>>>(ids, embedW, ln1_g, ln1_b, x, h);
    {
        int n = Ll*Hh*DK*DK;
        physics_kernel<<<(n + 255)/256, 256>>>(W_LTM, V_T0, V_gs, beta_tau, beta_gm,
                                               C_ch, gma, alpha, icth, ret, gate);
    }

    for (int l = 0; l < Ll; l++) {
        if (l > 0)
            ln_kernel<<<NROW, 256>>>(x, ln1_g + l*Dm, ln1_b + l*Dm, h);
        conv_kernel<<<NROW, 256>>>(h, conv_w + l*3*Dm, conv_b + l*Dm, h2h);

        dim3 gq((3*Dm)/128, NROW/128);
        mma_nt_h<<<gq, 128, G_SMEM_BYTES>>>(NROW, 3*Dm, Dm, h2h,
                                            wqh + (size_t)l*3*Dm*Dm, nullptr, qkv);

        kln_kernel<<<NROW, 512>>>(qkv, lnk_g + l*DK, lnk_b + l*DK);

        scan_kernel<<<Bb*Hh*4, 256>>>(qkv,
                                      ret  + (size_t)l*Hh*DK*DK,
                                      gate + (size_t)l*Hh*DK*DK,
                                      W_LTM + (size_t)l*Hh*DK*DK,
                                      yh);

        dim3 go(Dm/128, NROW/128);
        mma_nt_h<<<go, 128, G_SMEM_BYTES>>>(NROW, Dm, Dm, yh,
                                            woh + (size_t)l*Dm*Dm, x, x);
    }

    lnh_kernel<<<NROW, 256>>>(x, lnf_g, lnf_b, hh);
    dim3 gh(Vv/128, NROW/128);
    mma_nt_h<<<gh, 128, G_SMEM_BYTES>>>(NROW, Vv, Dm, hh, whh, nullptr, out);
}

// round 11
// speedup vs baseline: 6.3151x; 1.0014x over previous
#include <cuda_runtime.h>
#include <cuda_fp16.h>
#include <math.h>
#include <stdint.h>

// ---------------- problem constants ----------------
#define Dm    1024
#define Tlen  2048
#define Bb    4
#define Hh    16
#define DK    64
#define Ll    2
#define Vv    8192
#define NROW  (Bb*Tlen)          // 8192 token rows

// ---------------- scratch (device globals; no allocation allowed) ----------
__device__ float  g_x  [NROW*Dm];        // residual stream (fp32)
__device__ float  g_h  [NROW*Dm];        // ln output (fp32, conv input)
__device__ __half g_h2h[NROW*Dm];        // conv output (half, A of qkv GEMM)
__device__ float  g_qkv[NROW*3*Dm];      // fp32 (k section LN'd in GEMM epilogue)
__device__ __half g_yh [NROW*Dm];        // scan output (half, A of Wo GEMM)
__device__ __half g_hh [NROW*Dm];        // final ln output (half, A of head GEMM)
__device__ float  g_ret [Ll*Hh*DK*DK];
__device__ float  g_gate[Ll*Hh*DK*DK];
// half weights
__device__ __half g_wqh[Ll*3*Dm*Dm];
__device__ __half g_woh[Ll*Dm*Dm];
__device__ __half g_whh[Vv*Dm];

// ---------------- fp32 -> fp16 weight conversion ----------------
__global__ void __launch_bounds__(256) tohalf_kernel(const float* __restrict__ s,
                                                     __half* __restrict__ d) {
    int i = (blockIdx.x * blockDim.x + threadIdx.x) * 4;
    float4 v = *(const float4*)(s + i);
    *(__half2*)(d + i)     = __floats2half2_rn(v.x, v.y);
    *(__half2*)(d + i + 2) = __floats2half2_rn(v.z, v.w);
}

// ---------------- block reduce helper (blockDim == 256) ----------------
__device__ __forceinline__ float blockReduceSum(float v, float* sh) {
    #pragma unroll
    for (int o = 16; o; o >>= 1) v += __shfl_xor_sync(0xffffffffu, v, o);
    if ((threadIdx.x & 31) == 0) sh[threadIdx.x >> 5] = v;
    __syncthreads();
    float tot = 0.f;
    #pragma unroll
    for (int i = 0; i < 8; i++) tot += sh[i];
    __syncthreads();
    return tot;
}

// ---------------- fused embedding gather + layer-0 LN ----------------
__global__ void __launch_bounds__(256) embed_ln_kernel(const int* __restrict__ ids,
                                                       const float* __restrict__ W,
                                                       const float* __restrict__ g,
                                                       const float* __restrict__ b,
                                                       float* __restrict__ x,
                                                       float* __restrict__ h) {
    __shared__ float sh[8];
    int row = blockIdx.x;
    int id  = ids[row];
    const float* xr = W + (size_t)id * Dm;
    int i0 = threadIdx.x * 4;
    float4 xv = *(const float4*)(xr + i0);
    *(float4*)(x + (size_t)row * Dm + i0) = xv;
    float s = xv.x + xv.y + xv.z + xv.w;
    float mean = blockReduceSum(s, sh) * (1.f / Dm);
    float d0 = xv.x - mean, d1 = xv.y - mean, d2 = xv.z - mean, d3 = xv.w - mean;
    float sq = d0*d0 + d1*d1 + d2*d2 + d3*d3;
    float var = blockReduceSum(sq, sh) * (1.f / Dm);
    float rstd = rsqrtf(var + 1e-5f);
    float4 gv = *(const float4*)(g + i0);
    float4 bv = *(const float4*)(b + i0);
    float4 ov;
    ov.x = d0 * rstd * gv.x + bv.x;
    ov.y = d1 * rstd * gv.y + bv.y;
    ov.z = d2 * rstd * gv.z + bv.z;
    ov.w = d3 * rstd * gv.w + bv.w;
    *(float4*)(h + (size_t)row * Dm + i0) = ov;
}

// ---------------- layernorm (fp32 out) ----------------
__global__ void __launch_bounds__(256) ln_kernel(const float* __restrict__ x,
                                                 const float* __restrict__ g,
                                                 const float* __restrict__ b,
                                                 float* __restrict__ out) {
    __shared__ float sh[8];
    int row = blockIdx.x;
    const float* xr = x + (size_t)row * Dm;
    int i0 = threadIdx.x * 4;
    float4 xv = *(const float4*)(xr + i0);
    float s = xv.x + xv.y + xv.z + xv.w;
    float mean = blockReduceSum(s, sh) * (1.f / Dm);
    float d0 = xv.x - mean, d1 = xv.y - mean, d2 = xv.z - mean, d3 = xv.w - mean;
    float sq = d0*d0 + d1*d1 + d2*d2 + d3*d3;
    float var = blockReduceSum(sq, sh) * (1.f / Dm);
    float rstd = rsqrtf(var + 1e-5f);
    float4 gv = *(const float4*)(g + i0);
    float4 bv = *(const float4*)(b + i0);
    float4 ov;
    ov.x = d0 * rstd * gv.x + bv.x;
    ov.y = d1 * rstd * gv.y + bv.y;
    ov.z = d2 * rstd * gv.z + bv.z;
    ov.w = d3 * rstd * gv.w + bv.w;
    *(float4*)(out + (size_t)row * Dm + i0) = ov;
}

// ---------------- layernorm (half out, for head GEMM A) ----------------
__global__ void __launch_bounds__(256) lnh_kernel(const float* __restrict__ x,
                                                  const float* __restrict__ g,
                                                  const float* __restrict__ b,
                                                  __half* __restrict__ out) {
    __shared__ float sh[8];
    int row = blockIdx.x;
    const float* xr = x + (size_t)row * Dm;
    int i0 = threadIdx.x * 4;
    float4 xv = *(const float4*)(xr + i0);
    float s = xv.x + xv.y + xv.z + xv.w;
    float mean = blockReduceSum(s, sh) * (1.f / Dm);
    float d0 = xv.x - mean, d1 = xv.y - mean, d2 = xv.z - mean, d3 = xv.w - mean;
    float sq = d0*d0 + d1*d1 + d2*d2 + d3*d3;
    float var = blockReduceSum(sq, sh) * (1.f / Dm);
    float rstd = rsqrtf(var + 1e-5f);
    float4 gv = *(const float4*)(g + i0);
    float4 bv = *(const float4*)(b + i0);
    *(__half2*)(out + (size_t)row * Dm + i0) =
        __floats2half2_rn(d0 * rstd * gv.x + bv.x, d1 * rstd * gv.y + bv.y);
    *(__half2*)(out + (size_t)row * Dm + i0 + 2) =
        __floats2half2_rn(d2 * rstd * gv.z + bv.z, d3 * rstd * gv.w + bv.w);
}

// ---------------- causal depthwise conv (half out) ----------------
__global__ void __launch_bounds__(256) conv_kernel(const float* __restrict__ h,
                                                   const float* __restrict__ cw,
                                                   const float* __restrict__ cb,
                                                   __half* __restrict__ out) {
    int row = blockIdx.x;
    int t = row % Tlen;
    const float* h0 = h + (size_t)row * Dm;
    int i = threadIdx.x * 4;
    float4 cur = *(const float4*)(h0 + i);
    float4 w0 = *(const float4*)(cw + 0*Dm + i);
    float4 w1 = *(const float4*)(cw + 1*Dm + i);
    float4 w2 = *(const float4*)(cw + 2*Dm + i);
    float4 bb = *(const float4*)(cb + i);
    float4 z = make_float4(0.f, 0.f, 0.f, 0.f);
    float4 p1 = (t >= 1) ? *(const float4*)(h0 - Dm + i) : z;
    float4 p2 = (t >= 2) ? *(const float4*)(h0 - 2*Dm + i) : z;
    float ox = cur.x + w0.x*p2.x + w1.x*p1.x + w2.x*cur.x + bb.x;
    float oy = cur.y + w0.y*p2.y + w1.y*p1.y + w2.y*cur.y + bb.y;
    float oz = cur.z + w0.z*p2.z + w1.z*p1.z + w2.z*cur.z + bb.z;
    float ow = cur.w + w0.w*p2.w + w1.w*p1.w + w2.w*cur.w + bb.w;
    *(__half2*)(out + (size_t)row * Dm + i)     = __floats2half2_rn(ox, oy);
    *(__half2*)(out + (size_t)row * Dm + i + 2) = __floats2half2_rn(oz, ow);
}

// ---------------- static physics ----------------
__global__ void physics_kernel(const float* __restrict__ W_LTM,
                               const float* __restrict__ V_T0,
                               const float* __restrict__ V_gs,
                               const float* __restrict__ beta_tau,
                               const float* __restrict__ beta_gm,
                               const float* __restrict__ C_ch,
                               const float* __restrict__ gma,
                               const float* __restrict__ alpha,
                               const float* __restrict__ icth,
                               float* __restrict__ ret,
                               float* __restrict__ gate) {
    int idx = blockIdx.x * blockDim.x + threadIdx.x;
    if (idx >= Ll*Hh*DK*DK) return;
    int lh = idx / (DK*DK);
    int l  = lh / Hh;
    float veff = (V_gs[lh] - V_T0[lh]) + W_LTM[idx];
    float sp   = (veff > 20.f) ? veff : log1pf(expf(veff));
    float g_ch = beta_tau[lh] * sp;
    float r    = expf(-g_ch / C_ch[lh]);
    float G    = beta_gm[lh] * sp * (1.f / (1.f + expf(-veff)));
    float sgn  = tanhf(alpha[l] * (g_ch - icth[l]));
    ret[idx]  = r;
    gate[idx] = gma[lh] * sgn * G;
}

// ---------------- sequential recurrence: 16-step blocked, v/4 split --------
__global__ void __launch_bounds__(256, 1) scan_kernel(const float* __restrict__ qkv,
                                                      const float* __restrict__ ret,
                                                      const float* __restrict__ gate,
                                                      const float* __restrict__ W,
                                                      __half* __restrict__ y) {
    int bh = blockIdx.x >> 2;
    int vq = blockIdx.x & 3;
    int b = bh / Hh, h = bh % Hh;
    int tid = threadIdx.x;
    int v = vq * 16 + (tid >> 4), part = tid & 15, koff = part * 4;

    float r[4], g[4], w[4], f[4];
    {
        int base = (h*DK + v)*DK + koff;
        #pragma unroll
        for (int j = 0; j < 4; j++) {
            r[j] = ret[base + j];
            g[j] = gate[base + j];
            w[j] = W[base + j];
            f[j] = 0.f;
        }
    }

    __shared__ float sbuf[2][16][192];
    bool loader = tid < 192;
    int which = tid >> 6, lane = tid & 63;
    size_t rowbase = (size_t)b * Tlen * (3*Dm) + h * DK;
    const float* src = qkv + rowbase + which * Dm + lane;
    float pre[16];
    if (loader) {
        #pragma unroll
        for (int j = 0; j < 16; j++) pre[j] = src[(size_t)j * (3*Dm)];
    }
    __half* yout = y + (size_t)b * Tlen * Dm + h * DK + v;

    const int NB = Tlen / 16;
    for (int tb = 0; tb < NB; tb++) {
        int p = tb & 1;
        if (loader) {
            #pragma unroll
            for (int j = 0; j < 16; j++) sbuf[p][j][tid] = pre[j];
        }
        __syncthreads();
        if (loader && tb + 1 < NB) {
            size_t tn = (size_t)(tb * 16 + 16);
            #pragma unroll
            for (int j = 0; j < 16; j++)
                pre[j] = src[(tn + j) * (3*Dm)];
        }
        #pragma unroll
        for (int st = 0; st < 16; st++) {
            float vt = sbuf[p][st][128 + v];
            float4 kk = *(const float4*)&sbuf[p][st][64 + koff];
            float4 qq = *(const float4*)&sbuf[p][st][koff];
            f[0] = r[0]*f[0] + (g[0]*vt)*kk.x;
            f[1] = r[1]*f[1] + (g[1]*vt)*kk.y;
            f[2] = r[2]*f[2] + (g[2]*vt)*kk.z;
            f[3] = r[3]*f[3] + (g[3]*vt)*kk.w;
            float yacc;
            yacc = (w[0] + f[0]) * qq.x;
            yacc = fmaf(w[1] + f[1], qq.y, yacc);
            yacc = fmaf(w[2] + f[2], qq.z, yacc);
            yacc = fmaf(w[3] + f[3], qq.w, yacc);
            yacc += __shfl_xor_sync(0xffffffffu, yacc, 1);
            yacc += __shfl_xor_sync(0xffffffffu, yacc, 2);
            yacc += __shfl_xor_sync(0xffffffffu, yacc, 4);
            yacc += __shfl_xor_sync(0xffffffffu, yacc, 8);
            if (part == 0) yout[(size_t)(tb * 16 + st) * Dm] = __float2half_rn(yacc);
        }
    }
}

// ======== fp16 GEMM v7: NSS=2, 3 CTA/SM, fused per-head k-LN epilogue ======
// C = A * B^T (+Res). A:(M,K), B:(N,K) row-major __half. fp32 accumulate.
// CTA 128x128, 4 warps (2x2 of 64x64), 128 threads, 3 CTA/SM (64 KB smem).
#define SUBT_B  8192                       // bytes per K32 subtile
#define SS_B    (2*SUBT_B)                 // 16 KB per matrix per superstage
#define NSS     2
#define G_SMEM_BYTES (2*NSS*SS_B)          // 65536

__device__ __forceinline__ void cpasync16(uint32_t dst_smem, const void* src) {
    asm volatile("cp.async.cg.shared.global [%0], [%1], 16;"
                 :: "r"(dst_smem), "l"(src) : "memory");
}
__device__ __forceinline__ uint32_t smem_u32(const void* p) {
    uint32_t a;
    asm("{ .reg .u64 t; cvta.to.shared.u64 t, %1; cvt.u32.u64 %0, t; }"
        : "=r"(a) : "l"(p));
    return a;
}
__device__ __forceinline__ void ldm_x4(uint32_t& r0, uint32_t& r1,
                                       uint32_t& r2, uint32_t& r3, uint32_t addr) {
    asm volatile("ldmatrix.sync.aligned.m8n8.x4.shared.b16 {%0,%1,%2,%3}, [%4];"
                 : "=r"(r0), "=r"(r1), "=r"(r2), "=r"(r3) : "r"(addr));
}
__device__ __forceinline__ void mma_f16(float c[4],
                                        uint32_t a0, uint32_t a1, uint32_t a2, uint32_t a3,
                                        uint32_t b0, uint32_t b1) {
    asm volatile(
        "mma.sync.aligned.m16n8k16.row.col.f32.f16.f16.f32 "
        "{%0,%1,%2,%3}, {%4,%5,%6,%7}, {%8,%9}, {%0,%1,%2,%3};\n"
        : "+f"(c[0]), "+f"(c[1]), "+f"(c[2]), "+f"(c[3])
        : "r"(a0), "r"(a1), "r"(a2), "r"(a3), "r"(b0), "r"(b1));
}

// one 128x32-half subtile into a buffer (128 threads: 4 chunks each)
__device__ __forceinline__ void issue_tile32(uint32_t base,
                                             const __half* __restrict__ Gp,
                                             int K, int k0, int tid) {
    #pragma unroll
    for (int hi = 0; hi < 4; hi++) {
        int c = tid + hi * 128;
        int mr = c >> 3, kk = c & 7;
        int m = mr * 2 + (kk >> 2);
        int h0 = (kk & 3) * 8;
        uint32_t dst = base + (uint32_t)(mr * 128 + ((kk ^ (mr & 7)) << 4));
        cpasync16(dst, Gp + (size_t)m * K + k0 + h0);
    }
}
__device__ __forceinline__ void issue_ss(uint32_t sbase, int ss,
                                         const __half* __restrict__ Agp,
                                         const __half* __restrict__ Bgp,
                                         int K, int k0, int tid) {
    uint32_t aB = sbase + (uint32_t)ss * SS_B;
    uint32_t bB = sbase + (uint32_t)(NSS * SS_B) + (uint32_t)ss * SS_B;
    issue_tile32(aB,          Agp, K, k0,      tid);
    issue_tile32(aB + SUBT_B, Agp, K, k0 + 32, tid);
    issue_tile32(bB,          Bgp, K, k0,      tid);
    issue_tile32(bB + SUBT_B, Bgp, K, k0 + 32, tid);
}

__global__ void __launch_bounds__(128, 3) mma_nt_h(int M, int N, int K,
                                                   const __half* __restrict__ A,
                                                   const __half* __restrict__ B,
                                                   const float* __restrict__ Res,
                                                   float* __restrict__ C,
                                                   const float* __restrict__ lng,
                                                   const float* __restrict__ lnb,
                                                   int lnmode) {
    extern __shared__ __half smemh[];
    uint32_t sbase = smem_u32(smemh);
    int tid = threadIdx.x;
    int wid = tid >> 5, lane = tid & 31;
    int wm = (wid & 1) * 64;
    int wn = (wid >> 1) * 64;
    int m0 = blockIdx.y * 128, n0 = blockIdx.x * 128;
    int lg = lane >> 2;
    int lq = lane & 3;

    float acc[4][8][4];
    #pragma unroll
    for (int i = 0; i < 4; i++)
        #pragma unroll
        for (int j = 0; j < 8; j++)
            #pragma unroll
            for (int q = 0; q < 4; q++) acc[i][j][q] = 0.f;

    const __half* Agp = A + (size_t)m0 * K;
    const __half* Bgp = B + (size_t)n0 * K;

    // ldmatrix lane geometry
    int lm = lane & 15;
    int lc = lane >> 4;
    int mrA0 = (wm + lm) >> 1;
    int mrB0 = (wn + lm) >> 1;
    int halfbit = lm & 1;
    int kpA[2], kpB[2];
    #pragma unroll
    for (int kb = 0; kb < 2; kb++) {
        kpA[kb] = ((halfbit * 4 + kb * 2 + lc) ^ (mrA0 & 7)) << 4;
        kpB[kb] = ((halfbit * 4 + kb * 2 + lc) ^ (mrB0 & 7)) << 4;
    }
    uint32_t aRow = (uint32_t)(mrA0 * 128);
    uint32_t bRow = (uint32_t)(mrB0 * 128);

    int nSS = K >> 6;   // K / 64

    issue_ss(sbase, 0, Agp, Bgp, K, 0,  tid);
    asm volatile("cp.async.commit_group;");
    issue_ss(sbase, 1, Agp, Bgp, K, 64, tid);
    asm volatile("cp.async.commit_group;");

    for (int st = 0; st < nSS; st++) {
        int ss = st & 1;
        asm volatile("cp.async.wait_group 1;");
        __syncthreads();

        uint32_t aSS = sbase + (uint32_t)ss * SS_B + aRow;
        uint32_t bSS = sbase + (uint32_t)(NSS * SS_B) + (uint32_t)ss * SS_B + bRow;

        #pragma unroll
        for (int sub = 0; sub < 2; sub++) {
            uint32_t aBase = aSS + (uint32_t)(sub * SUBT_B);
            uint32_t bBase = bSS + (uint32_t)(sub * SUBT_B);
            #pragma unroll
            for (int kb = 0; kb < 2; kb++) {
                uint32_t af[4][4];
                #pragma unroll
                for (int i = 0; i < 4; i++)
                    ldm_x4(af[i][0], af[i][1], af[i][2], af[i][3],
                           aBase + (uint32_t)(i * 1024) + kpA[kb]);
                // interleave B fragment loads with MMAs (4 live B regs)
                #pragma unroll
                for (int jj = 0; jj < 4; jj++) {
                    uint32_t b0, b1, b2, b3;
                    ldm_x4(b0, b1, b2, b3, bBase + (uint32_t)(jj * 1024) + kpB[kb]);
                    #pragma unroll
                    for (int i = 0; i < 4; i++) {
                        mma_f16(acc[i][jj*2],   af[i][0], af[i][1], af[i][2], af[i][3], b0, b2);
                        mma_f16(acc[i][jj*2+1], af[i][0], af[i][1], af[i][2], af[i][3], b1, b3);
                    }
                }
            }
        }
        __syncthreads();   // all warps done reading buffer ss before refill
        if (st + 2 < nSS)
            issue_ss(sbase, ss, Agp, Bgp, K, (st + 2) << 6, tid);
        asm volatile("cp.async.commit_group;");
    }

    // ---- epilogue (optionally fused per-head k-LN over this warp's 64 cols)
    bool do_ln = (lnmode != 0) && ((n0 + wn) >= Dm) && ((n0 + wn) < 2*Dm);
    #pragma unroll
    for (int i = 0; i < 4; i++) {
        int row = m0 + wm + i*16 + lg;
        float mA = 0.f, rA = 1.f, mB = 0.f, rB = 1.f;
        if (do_ln) {
            float s0 = 0.f, q0 = 0.f, s1 = 0.f, q1 = 0.f;
            #pragma unroll
            for (int j = 0; j < 8; j++) {
                s0 += acc[i][j][0] + acc[i][j][1];
                q0 += acc[i][j][0]*acc[i][j][0] + acc[i][j][1]*acc[i][j][1];
                s1 += acc[i][j][2] + acc[i][j][3];
                q1 += acc[i][j][2]*acc[i][j][2] + acc[i][j][3]*acc[i][j][3];
            }
            s0 += __shfl_xor_sync(0xffffffffu, s0, 1);
            s0 += __shfl_xor_sync(0xffffffffu, s0, 2);
            q0 += __shfl_xor_sync(0xffffffffu, q0, 1);
            q0 += __shfl_xor_sync(0xffffffffu, q0, 2);
            s1 += __shfl_xor_sync(0xffffffffu, s1, 1);
            s1 += __shfl_xor_sync(0xffffffffu, s1, 2);
            q1 += __shfl_xor_sync(0xffffffffu, q1, 1);
            q1 += __shfl_xor_sync(0xffffffffu, q1, 2);
            mA = s0 * (1.f/64);
            rA = rsqrtf(fmaxf(q0 * (1.f/64) - mA*mA, 0.f) + 1e-5f);
            mB = s1 * (1.f/64);
            rB = rsqrtf(fmaxf(q1 * (1.f/64) - mB*mB, 0.f) + 1e-5f);
        }
        #pragma unroll
        for (int j = 0; j < 8; j++) {
            int col = n0 + wn + j*8 + 2*lq;
            size_t o0 = (size_t)row * N + col;
            size_t o1 = (size_t)(row + 8) * N + col;
            float2 v0 = make_float2(acc[i][j][0], acc[i][j][1]);
            float2 v1 = make_float2(acc[i][j][2], acc[i][j][3]);
            if (do_ln) {
                int c = j*8 + 2*lq;          // within-head index 0..62
                float g0 = lng[c], b0 = lnb[c];
                float g1 = lng[c+1], b1 = lnb[c+1];
                v0.x = (v0.x - mA)*rA*g0 + b0;  v0.y = (v0.y - mA)*rA*g1 + b1;
                v1.x = (v1.x - mB)*rB*g0 + b0;  v1.y = (v1.y - mB)*rB*g1 + b1;
            }
            if (Res) {
                float2 q0 = *(const float2*)(Res + o0);
                float2 q1 = *(const float2*)(Res + o1);
                v0.x += q0.x; v0.y += q0.y;
                v1.x += q1.x; v1.y += q1.y;
            }
            *(float2*)(C + o0) = v0;
            *(float2*)(C + o1) = v1;
        }
    }
}

// ---------------- launch ----------------
extern "C" void kernel_launch(void* const* d_in, const int* in_sizes, int n_in,
                              void* d_out, int out_size) {
    const int*   ids      = (const int*)  d_in[0];
    const float* embedW   = (const float*)d_in[2];
    const float* conv_w   = (const float*)d_in[3];
    const float* conv_b   = (const float*)d_in[4];
    const float* Wqkv     = (const float*)d_in[5];
    const float* Wo       = (const float*)d_in[6];
    const float* W_LTM    = (const float*)d_in[7];
    const float* V_T0     = (const float*)d_in[8];
    const float* V_gs     = (const float*)d_in[9];
    const float* beta_tau = (const float*)d_in[10];
    const float* beta_gm  = (const float*)d_in[11];
    const float* C_ch     = (const float*)d_in[12];
    const float* gma      = (const float*)d_in[13];
    const float* alpha    = (const float*)d_in[14];
    const float* icth     = (const float*)d_in[15];
    const float* ln1_g    = (const float*)d_in[16];
    const float* ln1_b    = (const float*)d_in[17];
    const float* lnk_g    = (const float*)d_in[18];
    const float* lnk_b    = (const float*)d_in[19];
    const float* lnf_g    = (const float*)d_in[20];
    const float* lnf_b    = (const float*)d_in[21];
    const float* headW    = (const float*)d_in[22];
    float* out = (float*)d_out;

    float *x, *h, *qkv, *ret, *gate;
    __half *h2h, *yh, *hh, *wqh, *woh, *whh;
    cudaGetSymbolAddress((void**)&x,    g_x);
    cudaGetSymbolAddress((void**)&h,    g_h);
    cudaGetSymbolAddress((void**)&h2h,  g_h2h);
    cudaGetSymbolAddress((void**)&qkv,  g_qkv);
    cudaGetSymbolAddress((void**)&yh,   g_yh);
    cudaGetSymbolAddress((void**)&hh,   g_hh);
    cudaGetSymbolAddress((void**)&ret,  g_ret);
    cudaGetSymbolAddress((void**)&gate, g_gate);
    cudaGetSymbolAddress((void**)&wqh,  g_wqh);
    cudaGetSymbolAddress((void**)&woh,  g_woh);
    cudaGetSymbolAddress((void**)&whh,  g_whh);

    cudaFuncSetAttribute(mma_nt_h, cudaFuncAttributeMaxDynamicSharedMemorySize,
                         G_SMEM_BYTES);

    tohalf_kernel<<<(Ll*3*Dm*Dm)/1024, 256>>>(Wqkv,  wqh);
    tohalf_kernel<<<(Ll*Dm*Dm)/1024,   256>>>(Wo,    woh);
    tohalf_kernel<<<(Vv*Dm)/1024,      256>>>(headW, whh);

    embed_ln_kernel<<<NROW, 256>>>(ids, embedW, ln1_g, ln1_b, x, h);
    {
        int n = Ll*Hh*DK*DK;
        physics_kernel<<<(n + 255)/256, 256>>>(W_LTM, V_T0, V_gs, beta_tau, beta_gm,
                                               C_ch, gma, alpha, icth, ret, gate);
    }

    for (int l = 0; l < Ll; l++) {
        if (l > 0)
            ln_kernel<<<NROW, 256>>>(x, ln1_g + l*Dm, ln1_b + l*Dm, h);
        conv_kernel<<<NROW, 256>>>(h, conv_w + l*3*Dm, conv_b + l*Dm, h2h);

        dim3 gq((3*Dm)/128, NROW/128);
        mma_nt_h<<<gq, 128, G_SMEM_BYTES>>>(NROW, 3*Dm, Dm, h2h,
                                            wqh + (size_t)l*3*Dm*Dm, nullptr, qkv,
                                            lnk_g + l*DK, lnk_b + l*DK, 1);

        scan_kernel<<<Bb*Hh*4, 256>>>(qkv,
                                      ret  + (size_t)l*Hh*DK*DK,
                                      gate + (size_t)l*Hh*DK*DK,
                                      W_LTM + (size_t)l*Hh*DK*DK,
                                      yh);

        dim3 go(Dm/128, NROW/128);
        mma_nt_h<<<go, 128, G_SMEM_BYTES>>>(NROW, Dm, Dm, yh,
                                            woh + (size_t)l*Dm*Dm, x, x,
                                            nullptr, nullptr, 0);
    }

    lnh_kernel<<<NROW, 256>>>(x, lnf_g, lnf_b, hh);
    dim3 gh(Vv/128, NROW/128);
    mma_nt_h<<<gh, 128, G_SMEM_BYTES>>>(NROW, Vv, Dm, hh, whh, nullptr, out,
                                        nullptr, nullptr, 0);
}